// round 1
// baseline (speedup 1.0000x reference)
#include <cuda_runtime.h>
#include <math.h>

#define NQ 1024
#define MI_STRIDE 544   // padded stride for mlp_in (535 real cols)

// ---------------- scratch (device globals; no allocation) ----------------
__device__ float g_cv[NQ * 4096];        // 16 MB
__device__ float g_pos[NQ * 2];
__device__ float g_occv[NQ];
__device__ float g_expd[NQ];
__device__ float g_feats[NQ * 384];
__device__ float g_fgavg[32 * 32 * 256]; // 1 MB
__device__ float g_mlpin[NQ * MI_STRIDE];
__device__ float g_hid[NQ * 512];

__device__ __forceinline__ float gelu_tanh(float x) {
    float x3 = x * x * x;
    return 0.5f * x * (1.f + tanhf(0.7978845608028654f * (x + 0.044715f * x3)));
}

// ---------------- cv = qf[1024,256] @ fg[4096,256]^T ----------------
__global__ __launch_bounds__(256) void k_cv(const float* __restrict__ A,
                                            const float* __restrict__ B,
                                            float* __restrict__ C) {
    __shared__ float As[16][64];
    __shared__ float Bs[16][68];
    int n0 = blockIdx.x * 64, m0 = blockIdx.y * 64, t = threadIdx.x;
    int ty = t >> 4, tx = t & 15;
    float acc[4][4];
#pragma unroll
    for (int i = 0; i < 4; i++)
#pragma unroll
        for (int j = 0; j < 4; j++) acc[i][j] = 0.f;

    for (int k0 = 0; k0 < 256; k0 += 16) {
        for (int i = t; i < 1024; i += 256) {
            int mm = i >> 4, kk = i & 15;
            As[kk][mm] = A[(m0 + mm) * 256 + k0 + kk];
        }
        for (int i = t; i < 1024; i += 256) {
            int nn = i >> 4, kk = i & 15;
            Bs[kk][nn] = B[(n0 + nn) * 256 + k0 + kk];
        }
        __syncthreads();
#pragma unroll
        for (int kk = 0; kk < 16; kk++) {
            float a[4], b[4];
#pragma unroll
            for (int i = 0; i < 4; i++) a[i] = As[kk][ty * 4 + i];
#pragma unroll
            for (int j = 0; j < 4; j++) b[j] = Bs[kk][tx * 4 + j];
#pragma unroll
            for (int i = 0; i < 4; i++)
#pragma unroll
                for (int j = 0; j < 4; j++) acc[i][j] = fmaf(a[i], b[j], acc[i][j]);
        }
        __syncthreads();
    }
#pragma unroll
    for (int i = 0; i < 4; i++)
#pragma unroll
        for (int j = 0; j < 4; j++)
            C[(m0 + ty * 4 + i) * 4096 + n0 + tx * 4 + j] = acc[i][j];
}

// ---------------- fg_avg (2x2 mean pool) ----------------
__global__ void k_fgavg(const float* __restrict__ fg, float* __restrict__ out) {
    int b = blockIdx.x;           // 0..1023
    int y = b >> 5, x = b & 31, t = threadIdx.x; // 256 channels
    const float* p = fg + ((2 * y) * 64 + 2 * x) * 256;
    float v = p[t] + p[256 + t] + p[64 * 256 + t] + p[64 * 256 + 256 + t];
    out[(y * 32 + x) * 256 + t] = 0.25f * v;
}

// ---------------- per-query head: conv1/conv2/softmax/coords + conv3/mean/FCs ----------------
__global__ __launch_bounds__(256) void k_head(
    const float* __restrict__ cv_g, const float* __restrict__ hq, const float* __restrict__ qf,
    const float* __restrict__ w1, const float* __restrict__ b1,
    const float* __restrict__ w2, const float* __restrict__ b2,
    const float* __restrict__ w3, const float* __restrict__ b3,
    const float* __restrict__ w4, const float* __restrict__ b4,
    const float* __restrict__ occw, const float* __restrict__ occb) {
    extern __shared__ float sm[];
    float* s_cv   = sm;               // 64*66
    float* s_occ  = s_cv + 64 * 66;   // 10*16*64
    float* s_pmap = s_occ + 10240;    // 4096
    float* s_w3t  = s_pmap + 4096;    // 144*32  [k][oc]
    float* s_w1   = s_w3t + 4608;     // 144
    float* s_b1   = s_w1 + 144;       // 16
    float* s_w2   = s_b1 + 16;        // 144
    float* s_w4   = s_w2 + 144;       // 512
    float* s_b3   = s_w4 + 512;       // 32
    float* s_b4   = s_b3 + 32;        // 16
    float* s_ow   = s_b4 + 16;        // 32
    float* s_ob   = s_ow + 32;        // 2
    float* s_red  = s_ob + 2;         // 32
    float* s_o3   = s_red + 32;       // 32
    float* s_h4   = s_o3 + 32;        // 16

    int q = blockIdx.x, t = threadIdx.x;
    const float* cvq = cv_g + q * 4096;
    for (int i = t; i < 4096; i += 256) s_cv[(i >> 6) * 66 + (i & 63)] = cvq[i];
    for (int i = t; i < 144; i += 256) { s_w1[i] = w1[i]; s_w2[i] = w2[i]; }
    for (int i = t; i < 4608; i += 256) { int oc = i / 144, k = i - oc * 144; s_w3t[k * 32 + oc] = w3[i]; }
    for (int i = t; i < 512; i += 256) s_w4[i] = w4[i];
    if (t < 16) s_b1[t] = b1[t];
    if (t < 32) s_b3[t] = b3[t];
    if (t < 16) s_b4[t] = b4[t];
    if (t < 32) s_ow[t] = occw[t];
    if (t < 2)  s_ob[t] = occb[t];
    if (t < 32) s_o3[t] = 0.f;
    // init feats = concat(hq, qf)
    for (int i = t; i < 128; i += 256) g_feats[q * 384 + i] = hq[q * 128 + i];
    for (int i = t; i < 256; i += 256) g_feats[q * 384 + 128 + i] = qf[q * 256 + i];
    float b2v = b2[0];
    __syncthreads();

    float acc3[16];
#pragma unroll
    for (int u = 0; u < 16; u++) acc3[u] = 0.f;
    int half = t & 1;
    int pos  = t >> 1;          // 0..127
    int jl   = pos >> 5;        // 0..3
    int ii   = pos & 31;        // 0..31

    for (int r0 = 0; r0 < 64; r0 += 8) {
        // fill occ band rows r0-1..r0+8 (conv1 + relu)
        for (int v = t; v < 10240; v += 256) {
            int slot = v >> 10;
            int rem = v & 1023;
            int c = rem >> 6, x = rem & 63;
            int row = r0 - 1 + slot;
            float val = 0.f;
            if (row >= 0 && row < 64) {
                float a = s_b1[c];
#pragma unroll
                for (int dy = 0; dy < 3; dy++) {
                    int yy = row - 1 + dy;
                    if (yy < 0 || yy > 63) continue;
#pragma unroll
                    for (int dx = 0; dx < 3; dx++) {
                        int xx = x - 1 + dx;
                        if (xx < 0 || xx > 63) continue;
                        a = fmaf(s_w1[c * 9 + dy * 3 + dx], s_cv[yy * 66 + xx], a);
                    }
                }
                val = fmaxf(a, 0.f);
            }
            s_occ[v] = val;
        }
        __syncthreads();

        // conv2 on rows r0..r0+7
        for (int e = 0; e < 2; e++) {
            int px = t + e * 256;
            int rr = px >> 6, x = px & 63;
            float a = b2v;
            for (int c = 0; c < 16; c++) {
#pragma unroll
                for (int dy = 0; dy < 3; dy++) {
                    int slot = rr + dy;   // (r-1+dy)-(r0-1)
#pragma unroll
                    for (int dx = 0; dx < 3; dx++) {
                        int xx = x - 1 + dx;
                        if (xx < 0 || xx > 63) continue;
                        a = fmaf(s_w2[c * 9 + dy * 3 + dx], s_occ[(slot * 16 + c) * 64 + xx], a);
                    }
                }
            }
            s_pmap[(r0 + rr) * 64 + x] = a;
        }

        // conv3 outputs rows j = r0/2 .. r0/2+3
        {
            float val[16];
#pragma unroll
            for (int u = 0; u < 16; u++) val[u] = s_b3[half * 16 + u];
            for (int ic = 0; ic < 16; ic++) {
#pragma unroll
                for (int dy = 0; dy < 3; dy++) {
                    int slot = 2 * jl + dy + 1;
#pragma unroll
                    for (int dx = 0; dx < 3; dx++) {
                        int col = 2 * ii + dx;
                        float xv = (col < 64) ? s_occ[(slot * 16 + ic) * 64 + col] : 0.f;
                        const float* wp = &s_w3t[(ic * 9 + dy * 3 + dx) * 32 + half * 16];
#pragma unroll
                        for (int u = 0; u < 16; u++) val[u] = fmaf(xv, wp[u], val[u]);
                    }
                }
            }
#pragma unroll
            for (int u = 0; u < 16; u++) acc3[u] += fmaxf(val[u], 0.f);
        }
        __syncthreads();
    }

    // conv3 reduction
#pragma unroll
    for (int u = 0; u < 16; u++) atomicAdd(&s_o3[half * 16 + u], acc3[u]);

    // softmax over pmap*20, expected coords
    float lmax = -1e30f;
    for (int i = t; i < 4096; i += 256) lmax = fmaxf(lmax, s_pmap[i]);
#pragma unroll
    for (int o = 16; o; o >>= 1) lmax = fmaxf(lmax, __shfl_xor_sync(0xffffffffu, lmax, o));
    if ((t & 31) == 0) s_red[t >> 5] = lmax;
    __syncthreads();
    if (t == 0) {
        float m = s_red[0];
        for (int i = 1; i < 8; i++) m = fmaxf(m, s_red[i]);
        s_red[31] = m;
    }
    __syncthreads();
    float m = s_red[31];
    float se = 0.f, sy = 0.f, sx = 0.f;
    for (int i = t; i < 4096; i += 256) {
        float e = expf((s_pmap[i] - m) * 20.f);
        se += e;
        sy += e * (float)(i >> 6);
        sx += e * (float)(i & 63);
    }
    __syncthreads();
#pragma unroll
    for (int o = 16; o; o >>= 1) {
        se += __shfl_xor_sync(0xffffffffu, se, o);
        sy += __shfl_xor_sync(0xffffffffu, sy, o);
        sx += __shfl_xor_sync(0xffffffffu, sx, o);
    }
    if ((t & 31) == 0) { int w = t >> 5; s_red[w] = se; s_red[8 + w] = sy; s_red[16 + w] = sx; }
    __syncthreads();
    if (t == 0) {
        float Se = 0, Sy = 0, Sx = 0;
        for (int i = 0; i < 8; i++) { Se += s_red[i]; Sy += s_red[8 + i]; Sx += s_red[16 + i]; }
        g_pos[q * 2 + 0] = (Sx / Se) * 8.f;   // ex * (512/64)
        g_pos[q * 2 + 1] = (Sy / Se) * 8.f;   // ey * 8
    }
    __syncthreads();

    // head FCs: o3 mean -> relu(fc16) -> occ/expd
    if (t < 16) {
        float a = s_b4[t];
        for (int ic = 0; ic < 32; ic++) a = fmaf(s_o3[ic] * (1.f / 1024.f), s_w4[ic * 16 + t], a);
        s_h4[t] = fmaxf(a, 0.f);
    }
    __syncthreads();
    if (t == 0) {
        float o = s_ob[0], ex2 = s_ob[1];
        for (int k = 0; k < 16; k++) {
            o   = fmaf(s_h4[k], s_ow[k * 2 + 0], o);
            ex2 = fmaf(s_h4[k], s_ow[k * 2 + 1], ex2);
        }
        g_occv[q] = o;
        g_expd[q] = ex2;
    }
}

// ---------------- correlation + mlp_in assembly (per iteration) ----------------
__global__ __launch_bounds__(128) void k_corr(const float* __restrict__ hg,
                                              const float* __restrict__ fg) {
    __shared__ float s_q[384];
    __shared__ float s_D[64];
    int q = blockIdx.x, t = threadIdx.x;
    float px = g_pos[q * 2 + 0], py = g_pos[q * 2 + 1];
    for (int i = t; i < 384; i += 128) s_q[i] = g_feats[q * 384 + i];
    float* mi = g_mlpin + q * MI_STRIDE;
    if (t == 0) { mi[0] = 0.f; mi[1] = 0.f; mi[2] = g_occv[q]; mi[3] = g_expd[q]; }
    for (int i = t; i < 384; i += 128) mi[4 + i] = g_feats[q * 384 + i];
    __syncthreads();

    const float* Gs[3] = { hg, fg, g_fgavg };
    const int Hs[3] = { 128, 64, 32 };
    const int Cs[3] = { 128, 256, 256 };
    const int QO[3] = { 0, 128, 128 };

    int wrp = t >> 5, lane = t & 31;
    for (int l = 0; l < 3; l++) {
        const float* G = Gs[l];
        int H = Hs[l], C = Cs[l], qo = QO[l];
        float sc = (float)H / 512.f;
        float gy = py * sc, gx = px * sc;
        float y0f = floorf(gy), x0f = floorf(gx);
        float wy = gy - y0f, wx = gx - x0f;
        int y0 = (int)y0f, x0 = (int)x0f;

        for (int p = wrp; p < 64; p += 4) {
            int ry = min(max(y0 + (p >> 3) - 3, 0), H - 1);
            int rx = min(max(x0 + (p & 7) - 3, 0), H - 1);
            const float* gp = G + (ry * H + rx) * C;
            float s = 0.f;
            for (int c = lane; c < C; c += 32) s = fmaf(gp[c], s_q[qo + c], s);
#pragma unroll
            for (int o = 16; o; o >>= 1) s += __shfl_xor_sync(0xffffffffu, s, o);
            if (lane == 0) s_D[p] = s;
        }
        __syncthreads();
        if (t < 49) {
            int r = t / 7, c2 = t - r * 7;
            float d00 = s_D[r * 8 + c2],       d01 = s_D[r * 8 + c2 + 1];
            float d10 = s_D[(r + 1) * 8 + c2], d11 = s_D[(r + 1) * 8 + c2 + 1];
            float corr = (1.f - wy) * (1.f - wx) * d00 + (1.f - wy) * wx * d01
                       + wy * (1.f - wx) * d10 + wy * wx * d11;
            mi[388 + l * 49 + t] = corr;
        }
        __syncthreads();
    }
}

// ---------------- GEMM1: [1024,535]@[535,512] + bias, gelu ----------------
__global__ __launch_bounds__(256) void k_gemm1(const float* __restrict__ B,
                                               const float* __restrict__ bias) {
    __shared__ float As[16][64];
    __shared__ float Bs[16][68];
    int n0 = blockIdx.x * 64, m0 = blockIdx.y * 64, t = threadIdx.x;
    int ty = t >> 4, tx = t & 15;
    float acc[4][4];
#pragma unroll
    for (int i = 0; i < 4; i++)
#pragma unroll
        for (int j = 0; j < 4; j++) acc[i][j] = 0.f;

    for (int k0 = 0; k0 < 535; k0 += 16) {
        for (int i = t; i < 1024; i += 256) {
            int mm = i >> 4, kk = i & 15, k = k0 + kk;
            As[kk][mm] = (k < 535) ? g_mlpin[(m0 + mm) * MI_STRIDE + k] : 0.f;
        }
        for (int i = t; i < 1024; i += 256) {
            int kk = i >> 6, nn = i & 63, k = k0 + kk;
            Bs[kk][nn] = (k < 535) ? B[k * 512 + n0 + nn] : 0.f;
        }
        __syncthreads();
#pragma unroll
        for (int kk = 0; kk < 16; kk++) {
            float a[4], b[4];
#pragma unroll
            for (int i = 0; i < 4; i++) a[i] = As[kk][ty * 4 + i];
#pragma unroll
            for (int j = 0; j < 4; j++) b[j] = Bs[kk][tx * 4 + j];
#pragma unroll
            for (int i = 0; i < 4; i++)
#pragma unroll
                for (int j = 0; j < 4; j++) acc[i][j] = fmaf(a[i], b[j], acc[i][j]);
        }
        __syncthreads();
    }
#pragma unroll
    for (int i = 0; i < 4; i++)
#pragma unroll
        for (int j = 0; j < 4; j++) {
            int mg = m0 + ty * 4 + i, ng = n0 + tx * 4 + j;
            g_hid[mg * 512 + ng] = gelu_tanh(acc[i][j] + bias[ng]);
        }
}

// ---------------- GEMM2: [1024,512]@[512,388] + bias, state update ----------------
__global__ __launch_bounds__(256) void k_gemm2(const float* __restrict__ B,
                                               const float* __restrict__ bias) {
    __shared__ float As[16][64];
    __shared__ float Bs[16][68];
    int n0 = blockIdx.x * 64, m0 = blockIdx.y * 64, t = threadIdx.x;
    int ty = t >> 4, tx = t & 15;
    float acc[4][4];
#pragma unroll
    for (int i = 0; i < 4; i++)
#pragma unroll
        for (int j = 0; j < 4; j++) acc[i][j] = 0.f;

    for (int k0 = 0; k0 < 512; k0 += 16) {
        for (int i = t; i < 1024; i += 256) {
            int mm = i >> 4, kk = i & 15;
            As[kk][mm] = g_hid[(m0 + mm) * 512 + k0 + kk];
        }
        for (int i = t; i < 1024; i += 256) {
            int kk = i >> 6, nn = i & 63;
            int n = n0 + nn;
            Bs[kk][nn] = (n < 388) ? B[(k0 + kk) * 388 + n] : 0.f;
        }
        __syncthreads();
#pragma unroll
        for (int kk = 0; kk < 16; kk++) {
            float a[4], b[4];
#pragma unroll
            for (int i = 0; i < 4; i++) a[i] = As[kk][ty * 4 + i];
#pragma unroll
            for (int j = 0; j < 4; j++) b[j] = Bs[kk][tx * 4 + j];
#pragma unroll
            for (int i = 0; i < 4; i++)
#pragma unroll
                for (int j = 0; j < 4; j++) acc[i][j] = fmaf(a[i], b[j], acc[i][j]);
        }
        __syncthreads();
    }
#pragma unroll
    for (int i = 0; i < 4; i++)
#pragma unroll
        for (int j = 0; j < 4; j++) {
            int mg = m0 + ty * 4 + i, ng = n0 + tx * 4 + j;
            if (ng < 388) {
                float v = acc[i][j] + bias[ng];
                if (ng < 2)      g_pos[mg * 2 + ng] += v;
                else if (ng == 2) g_occv[mg] += v;
                else if (ng == 3) g_expd[mg] += v;
                else             g_feats[mg * 384 + ng - 4] += v;
            }
        }
}

// ---------------- pack output ----------------
__global__ void k_out(float* __restrict__ out) {
    int i = blockIdx.x * blockDim.x + threadIdx.x;
    if (i < NQ) {
        out[i * 4 + 0] = g_pos[i * 2 + 0];
        out[i * 4 + 1] = g_pos[i * 2 + 1];
        out[i * 4 + 2] = g_occv[i];
        out[i * 4 + 3] = g_expd[i];
    }
}

// ---------------- launch ----------------
extern "C" void kernel_launch(void* const* d_in, const int* in_sizes, int n_in,
                              void* d_out, int out_size) {
    const float* fg   = (const float*)d_in[0];
    const float* hg   = (const float*)d_in[1];
    const float* qf   = (const float*)d_in[2];
    const float* hq   = (const float*)d_in[3];
    const float* w1   = (const float*)d_in[4];
    const float* b1   = (const float*)d_in[5];
    const float* w2   = (const float*)d_in[6];
    const float* b2   = (const float*)d_in[7];
    const float* w3   = (const float*)d_in[8];
    const float* b3   = (const float*)d_in[9];
    const float* w4   = (const float*)d_in[10];
    const float* b4   = (const float*)d_in[11];
    const float* occw = (const float*)d_in[12];
    const float* occb = (const float*)d_in[13];
    const float* miw  = (const float*)d_in[14];
    const float* mib  = (const float*)d_in[15];
    const float* mow  = (const float*)d_in[16];
    const float* mob  = (const float*)d_in[17];
    float* out = (float*)d_out;

    const int smem_head = 24146 * 4;
    cudaFuncSetAttribute(k_head, cudaFuncAttributeMaxDynamicSharedMemorySize, smem_head);

    k_cv<<<dim3(64, 16), 256>>>(qf, fg, g_cv);
    k_fgavg<<<1024, 256>>>(fg, g_fgavg);
    k_head<<<NQ, 256, smem_head>>>(g_cv, hq, qf, w1, b1, w2, b2, w3, b3, w4, b4, occw, occb);

    for (int it = 0; it < 4; it++) {
        k_corr<<<NQ, 128>>>(hg, fg);
        k_gemm1<<<dim3(8, 16), 256>>>(miw, mib);
        k_gemm2<<<dim3(7, 16), 256>>>(mow, mob);
    }
    k_out<<<4, 256>>>(out);
}

// round 2
// speedup vs baseline: 1.6121x; 1.6121x over previous
#include <cuda_runtime.h>
#include <math.h>

#define NQ 1024
#define MI_STRIDE 544   // padded stride for mlp_in (535 real cols)

// ---------------- scratch (device globals; no allocation) ----------------
__device__ float g_cv[NQ * 4096];        // 16 MB
__device__ float g_pos[NQ * 2];
__device__ float g_occv[NQ];
__device__ float g_expd[NQ];
__device__ float g_feats[NQ * 384];
__device__ float g_fgavg[32 * 32 * 256]; // 1 MB
__device__ float g_mlpin[NQ * MI_STRIDE];
__device__ float g_hid[NQ * 512];

__device__ __forceinline__ float gelu_tanh(float x) {
    float x3 = x * x * x;
    return 0.5f * x * (1.f + tanhf(0.7978845608028654f * (x + 0.044715f * x3)));
}

// ---------------- cv = qf[1024,256] @ fg[4096,256]^T ----------------
__global__ __launch_bounds__(256) void k_cv(const float* __restrict__ A,
                                            const float* __restrict__ B,
                                            float* __restrict__ C) {
    __shared__ float As[16][64];
    __shared__ float Bs[16][68];
    int n0 = blockIdx.x * 64, m0 = blockIdx.y * 64, t = threadIdx.x;
    int ty = t >> 4, tx = t & 15;
    float acc[4][4];
#pragma unroll
    for (int i = 0; i < 4; i++)
#pragma unroll
        for (int j = 0; j < 4; j++) acc[i][j] = 0.f;

    for (int k0 = 0; k0 < 256; k0 += 16) {
#pragma unroll
        for (int i = t; i < 1024; i += 256) {
            int mm = i >> 4, kk = i & 15;
            As[kk][mm] = A[(m0 + mm) * 256 + k0 + kk];
        }
#pragma unroll
        for (int i = t; i < 1024; i += 256) {
            int nn = i >> 4, kk = i & 15;
            Bs[kk][nn] = B[(n0 + nn) * 256 + k0 + kk];
        }
        __syncthreads();
#pragma unroll
        for (int kk = 0; kk < 16; kk++) {
            float4 a4 = *(const float4*)&As[kk][ty * 4];
            float4 b4 = *(const float4*)&Bs[kk][tx * 4];
            float a[4] = {a4.x, a4.y, a4.z, a4.w};
            float b[4] = {b4.x, b4.y, b4.z, b4.w};
#pragma unroll
            for (int i = 0; i < 4; i++)
#pragma unroll
                for (int j = 0; j < 4; j++) acc[i][j] = fmaf(a[i], b[j], acc[i][j]);
        }
        __syncthreads();
    }
#pragma unroll
    for (int i = 0; i < 4; i++)
#pragma unroll
        for (int j = 0; j < 4; j++)
            C[(m0 + ty * 4 + i) * 4096 + n0 + tx * 4 + j] = acc[i][j];
}

// ---------------- fg_avg (2x2 mean pool) ----------------
__global__ void k_fgavg(const float* __restrict__ fg, float* __restrict__ out) {
    int b = blockIdx.x;           // 0..1023
    int y = b >> 5, x = b & 31, t = threadIdx.x; // 256 channels
    const float* p = fg + ((2 * y) * 64 + 2 * x) * 256;
    float v = p[t] + p[256 + t] + p[64 * 256 + t] + p[64 * 256 + 256 + t];
    out[(y * 32 + x) * 256 + t] = 0.25f * v;
}

// ---------------- per-query head ----------------
#define OCC_STRIDE 66
__global__ __launch_bounds__(256) void k_head(
    const float* __restrict__ cv_g, const float* __restrict__ hq, const float* __restrict__ qf,
    const float* __restrict__ w1, const float* __restrict__ b1,
    const float* __restrict__ w2, const float* __restrict__ b2,
    const float* __restrict__ w3, const float* __restrict__ b3,
    const float* __restrict__ w4, const float* __restrict__ b4,
    const float* __restrict__ occw, const float* __restrict__ occb) {
    extern __shared__ float sm[];
    float* s_cv   = sm;                       // 64*66 = 4224
    float* s_occ  = s_cv + 64 * 66;           // 10*16*66 = 10560
    float* s_pmap = s_occ + 10560;            // 4096
    float* s_w3t  = s_pmap + 4096;            // 144*32
    float* s_w2   = s_w3t + 4608;             // 144
    float* s_w4   = s_w2 + 144;               // 512
    float* s_b3   = s_w4 + 512;               // 32
    float* s_b4   = s_b3 + 32;                // 16
    float* s_ow   = s_b4 + 16;                // 32
    float* s_ob   = s_ow + 32;                // 2
    float* s_red  = s_ob + 2;                 // 32
    float* s_o3   = s_red + 32;               // 32
    float* s_h4   = s_o3 + 32;                // 16

    int q = blockIdx.x, t = threadIdx.x;
    const float* cvq = cv_g + q * 4096;
    for (int i = t; i < 4096; i += 256) s_cv[(i >> 6) * 66 + (i & 63)] = cvq[i];
    for (int i = t; i < 144; i += 256) s_w2[i] = w2[i];
    for (int i = t; i < 4608; i += 256) { int oc = i / 144, k = i - oc * 144; s_w3t[k * 32 + oc] = w3[i]; }
    for (int i = t; i < 512; i += 256) s_w4[i] = w4[i];
    if (t < 32) s_b3[t] = b3[t];
    if (t < 16) s_b4[t] = b4[t];
    if (t < 32) s_ow[t] = occw[t];
    if (t < 2)  s_ob[t] = occb[t];
    if (t < 32) s_o3[t] = 0.f;
    for (int i = t; i < 128; i += 256) g_feats[q * 384 + i] = hq[q * 128 + i];
    for (int i = t; i < 256; i += 256) g_feats[q * 384 + 128 + i] = qf[q * 256 + i];
    float b2v = b2[0];

    // conv1 thread mapping: c1 = t&15, x0 = (t>>4)*4 ; weights in regs
    int c1 = t & 15, xg1 = t >> 4, x0 = xg1 * 4;
    float w1r[9], b1r = b1[c1];
#pragma unroll
    for (int k = 0; k < 9; k++) w1r[k] = w1[c1 * 9 + k];

    // conv2 mapping: rr2 = t>>6 (0..3), x2 = t&63 ; outputs rows r0+rr2, r0+rr2+4
    int rr2 = t >> 6, x2 = t & 63;

    // conv3 mapping: og = t&7 (oc group of 4), pg = t>>3 : jrow = pg>>3, cg = pg&7
    int og = t & 7, pg = t >> 3;
    int jrow = pg >> 3, cg = pg & 7, oc0 = og * 4;
    float acc3[4][4];
#pragma unroll
    for (int cc = 0; cc < 4; cc++)
#pragma unroll
        for (int u = 0; u < 4; u++) acc3[cc][u] = 0.f;

    __syncthreads();

    for (int r0 = 0; r0 < 64; r0 += 8) {
        // ---- conv1 + relu : fill occ band rows r0-1..r0+8 ----
#pragma unroll
        for (int slot = 0; slot < 10; slot++) {
            int row = r0 - 1 + slot;
            float* dst = &s_occ[(slot * 16 + c1) * OCC_STRIDE + x0];
            if (row < 0 || row > 63) {
                dst[0] = 0.f; dst[1] = 0.f; dst[2] = 0.f; dst[3] = 0.f;
                continue;
            }
            float xv[3][6];
#pragma unroll
            for (int dy = 0; dy < 3; dy++) {
                int yy = row - 1 + dy;
                bool rv = (yy >= 0 && yy <= 63);
                const float* rp = &s_cv[yy * 66];
#pragma unroll
                for (int k = 0; k < 6; k++) {
                    int col = x0 - 1 + k;
                    xv[dy][k] = (rv && col >= 0 && col <= 63) ? rp[col] : 0.f;
                }
            }
#pragma unroll
            for (int j = 0; j < 4; j++) {
                float a = b1r;
#pragma unroll
                for (int dy = 0; dy < 3; dy++)
#pragma unroll
                    for (int dx = 0; dx < 3; dx++)
                        a = fmaf(w1r[dy * 3 + dx], xv[dy][j + dx], a);
                dst[j] = fmaxf(a, 0.f);
            }
        }
        __syncthreads();

        // ---- conv2 : rows r0+rr2 and r0+rr2+4 ----
        {
            float a0 = b2v, a1 = b2v;
            float mL = (x2 > 0) ? 1.f : 0.f;
            float mR = (x2 < 63) ? 1.f : 0.f;
            int xm = (x2 > 0) ? x2 - 1 : 0;
            int xp = (x2 < 63) ? x2 + 1 : 63;
#pragma unroll
            for (int c = 0; c < 16; c++) {
                float w[9];
#pragma unroll
                for (int k = 0; k < 9; k++) w[k] = s_w2[c * 9 + k];
#pragma unroll
                for (int dy = 0; dy < 3; dy++) {
                    const float* p0 = &s_occ[((rr2 + dy) * 16 + c) * OCC_STRIDE];
                    const float* p1 = &s_occ[((rr2 + 4 + dy) * 16 + c) * OCC_STRIDE];
                    float v0m = p0[xm] * mL, v0c = p0[x2], v0p = p0[xp] * mR;
                    float v1m = p1[xm] * mL, v1c = p1[x2], v1p = p1[xp] * mR;
                    a0 = fmaf(w[dy * 3 + 0], v0m, a0);
                    a0 = fmaf(w[dy * 3 + 1], v0c, a0);
                    a0 = fmaf(w[dy * 3 + 2], v0p, a0);
                    a1 = fmaf(w[dy * 3 + 0], v1m, a1);
                    a1 = fmaf(w[dy * 3 + 1], v1c, a1);
                    a1 = fmaf(w[dy * 3 + 2], v1p, a1);
                }
            }
            s_pmap[(r0 + rr2) * 64 + x2] = a0;
            s_pmap[(r0 + rr2 + 4) * 64 + x2] = a1;
        }

        // ---- conv3 : output rows j = r0/2 + jrow, cols 4*cg..4*cg+3, oc oc0..oc0+3 ----
        {
            float val[4][4];
#pragma unroll
            for (int cc = 0; cc < 4; cc++)
#pragma unroll
                for (int u = 0; u < 4; u++) val[cc][u] = s_b3[oc0 + u];
#pragma unroll
            for (int ic = 0; ic < 16; ic++) {
#pragma unroll
                for (int dy = 0; dy < 3; dy++) {
                    int slot = 2 * jrow + dy + 1;
                    const float* base = &s_occ[(slot * 16 + ic) * OCC_STRIDE + 8 * cg];
                    float xv[9];
#pragma unroll
                    for (int k = 0; k < 9; k++)
                        xv[k] = (8 * cg + k < 64) ? base[k] : 0.f;
#pragma unroll
                    for (int dx = 0; dx < 3; dx++) {
                        const float* wp = &s_w3t[(ic * 9 + dy * 3 + dx) * 32 + oc0];
                        float w0 = wp[0], w1v = wp[1], w2v = wp[2], w3v = wp[3];
#pragma unroll
                        for (int cc = 0; cc < 4; cc++) {
                            float x = xv[2 * cc + dx];
                            val[cc][0] = fmaf(x, w0, val[cc][0]);
                            val[cc][1] = fmaf(x, w1v, val[cc][1]);
                            val[cc][2] = fmaf(x, w2v, val[cc][2]);
                            val[cc][3] = fmaf(x, w3v, val[cc][3]);
                        }
                    }
                }
            }
#pragma unroll
            for (int cc = 0; cc < 4; cc++)
#pragma unroll
                for (int u = 0; u < 4; u++) acc3[cc][u] += fmaxf(val[cc][u], 0.f);
        }
        __syncthreads();
    }

    // conv3 reduction into s_o3
#pragma unroll
    for (int u = 0; u < 4; u++) {
        float s = acc3[0][u] + acc3[1][u] + acc3[2][u] + acc3[3][u];
        atomicAdd(&s_o3[oc0 + u], s);
    }

    // softmax over pmap*20, expected coords
    float lmax = -1e30f;
    for (int i = t; i < 4096; i += 256) lmax = fmaxf(lmax, s_pmap[i]);
#pragma unroll
    for (int o = 16; o; o >>= 1) lmax = fmaxf(lmax, __shfl_xor_sync(0xffffffffu, lmax, o));
    if ((t & 31) == 0) s_red[t >> 5] = lmax;
    __syncthreads();
    if (t == 0) {
        float m = s_red[0];
        for (int i = 1; i < 8; i++) m = fmaxf(m, s_red[i]);
        s_red[31] = m;
    }
    __syncthreads();
    float m = s_red[31];
    float se = 0.f, sy = 0.f, sx = 0.f;
    for (int i = t; i < 4096; i += 256) {
        float e = __expf((s_pmap[i] - m) * 20.f);
        se += e;
        sy += e * (float)(i >> 6);
        sx += e * (float)(i & 63);
    }
    __syncthreads();
#pragma unroll
    for (int o = 16; o; o >>= 1) {
        se += __shfl_xor_sync(0xffffffffu, se, o);
        sy += __shfl_xor_sync(0xffffffffu, sy, o);
        sx += __shfl_xor_sync(0xffffffffu, sx, o);
    }
    if ((t & 31) == 0) { int w = t >> 5; s_red[w] = se; s_red[8 + w] = sy; s_red[16 + w] = sx; }
    __syncthreads();
    if (t == 0) {
        float Se = 0, Sy = 0, Sx = 0;
        for (int i = 0; i < 8; i++) { Se += s_red[i]; Sy += s_red[8 + i]; Sx += s_red[16 + i]; }
        g_pos[q * 2 + 0] = (Sx / Se) * 8.f;
        g_pos[q * 2 + 1] = (Sy / Se) * 8.f;
    }
    __syncthreads();

    // head FCs
    if (t < 16) {
        float a = s_b4[t];
        for (int ic = 0; ic < 32; ic++) a = fmaf(s_o3[ic] * (1.f / 1024.f), s_w4[ic * 16 + t], a);
        s_h4[t] = fmaxf(a, 0.f);
    }
    __syncthreads();
    if (t == 0) {
        float o = s_ob[0], ex2 = s_ob[1];
        for (int k = 0; k < 16; k++) {
            o   = fmaf(s_h4[k], s_ow[k * 2 + 0], o);
            ex2 = fmaf(s_h4[k], s_ow[k * 2 + 1], ex2);
        }
        g_occv[q] = o;
        g_expd[q] = ex2;
    }
}

// ---------------- correlation + mlp_in assembly (per iteration) ----------------
__global__ __launch_bounds__(256) void k_corr(const float* __restrict__ hg,
                                              const float* __restrict__ fg) {
    __shared__ float s_q[384];
    __shared__ float s_D[64];
    int q = blockIdx.x, t = threadIdx.x;
    float px = g_pos[q * 2 + 0], py = g_pos[q * 2 + 1];
    for (int i = t; i < 384; i += 256) s_q[i] = g_feats[q * 384 + i];
    float* mi = g_mlpin + q * MI_STRIDE;
    if (t == 0) { mi[0] = 0.f; mi[1] = 0.f; mi[2] = g_occv[q]; mi[3] = g_expd[q]; }
    for (int i = t; i < 384; i += 256) mi[4 + i] = g_feats[q * 384 + i];
    __syncthreads();

    const float* Gs[3] = { hg, fg, g_fgavg };
    const int Hs[3] = { 128, 64, 32 };
    const int Cs[3] = { 128, 256, 256 };
    const int QO[3] = { 0, 128, 128 };

    int wrp = t >> 5, lane = t & 31;
    for (int l = 0; l < 3; l++) {
        const float* G = Gs[l];
        int H = Hs[l], C = Cs[l], qo = QO[l];
        float sc = (float)H / 512.f;
        float gy = py * sc, gx = px * sc;
        float y0f = floorf(gy), x0f = floorf(gx);
        float wy = gy - y0f, wx = gx - x0f;
        int y0 = (int)y0f, x0 = (int)x0f;

        for (int p = wrp; p < 64; p += 8) {
            int ry = min(max(y0 + (p >> 3) - 3, 0), H - 1);
            int rx = min(max(x0 + (p & 7) - 3, 0), H - 1);
            const float* gp = G + (ry * H + rx) * C;
            float s = 0.f;
            for (int c = lane; c < C; c += 32) s = fmaf(gp[c], s_q[qo + c], s);
#pragma unroll
            for (int o = 16; o; o >>= 1) s += __shfl_xor_sync(0xffffffffu, s, o);
            if (lane == 0) s_D[p] = s;
        }
        __syncthreads();
        if (t < 49) {
            int r = t / 7, c2 = t - r * 7;
            float d00 = s_D[r * 8 + c2],       d01 = s_D[r * 8 + c2 + 1];
            float d10 = s_D[(r + 1) * 8 + c2], d11 = s_D[(r + 1) * 8 + c2 + 1];
            float corr = (1.f - wy) * (1.f - wx) * d00 + (1.f - wy) * wx * d01
                       + wy * (1.f - wx) * d10 + wy * wx * d11;
            mi[388 + l * 49 + t] = corr;
        }
        __syncthreads();
    }
}

// ---------------- GEMM1: [1024,535]@[535,512] + bias, gelu ----------------
__global__ __launch_bounds__(256) void k_gemm1(const float* __restrict__ B,
                                               const float* __restrict__ bias) {
    __shared__ float As[16][64];
    __shared__ float Bs[16][68];
    int n0 = blockIdx.x * 64, m0 = blockIdx.y * 64, t = threadIdx.x;
    int ty = t >> 4, tx = t & 15;
    float acc[4][4];
#pragma unroll
    for (int i = 0; i < 4; i++)
#pragma unroll
        for (int j = 0; j < 4; j++) acc[i][j] = 0.f;

    for (int k0 = 0; k0 < 535; k0 += 16) {
#pragma unroll
        for (int i = t; i < 1024; i += 256) {
            int mm = i >> 4, kk = i & 15, k = k0 + kk;
            As[kk][mm] = (k < 535) ? g_mlpin[(m0 + mm) * MI_STRIDE + k] : 0.f;
        }
#pragma unroll
        for (int i = t; i < 1024; i += 256) {
            int kk = i >> 6, nn = i & 63, k = k0 + kk;
            Bs[kk][nn] = (k < 535) ? B[k * 512 + n0 + nn] : 0.f;
        }
        __syncthreads();
#pragma unroll
        for (int kk = 0; kk < 16; kk++) {
            float4 a4 = *(const float4*)&As[kk][ty * 4];
            float4 b4 = *(const float4*)&Bs[kk][tx * 4];
            float a[4] = {a4.x, a4.y, a4.z, a4.w};
            float b[4] = {b4.x, b4.y, b4.z, b4.w};
#pragma unroll
            for (int i = 0; i < 4; i++)
#pragma unroll
                for (int j = 0; j < 4; j++) acc[i][j] = fmaf(a[i], b[j], acc[i][j]);
        }
        __syncthreads();
    }
#pragma unroll
    for (int i = 0; i < 4; i++)
#pragma unroll
        for (int j = 0; j < 4; j++) {
            int mg = m0 + ty * 4 + i, ng = n0 + tx * 4 + j;
            g_hid[mg * 512 + ng] = gelu_tanh(acc[i][j] + bias[ng]);
        }
}

// ---------------- GEMM2: [1024,512]@[512,388] + bias, state update ----------------
__global__ __launch_bounds__(256) void k_gemm2(const float* __restrict__ B,
                                               const float* __restrict__ bias) {
    __shared__ float As[16][64];
    __shared__ float Bs[16][68];
    int n0 = blockIdx.x * 64, m0 = blockIdx.y * 64, t = threadIdx.x;
    int ty = t >> 4, tx = t & 15;
    float acc[4][4];
#pragma unroll
    for (int i = 0; i < 4; i++)
#pragma unroll
        for (int j = 0; j < 4; j++) acc[i][j] = 0.f;

    for (int k0 = 0; k0 < 512; k0 += 16) {
#pragma unroll
        for (int i = t; i < 1024; i += 256) {
            int mm = i >> 4, kk = i & 15;
            As[kk][mm] = g_hid[(m0 + mm) * 512 + k0 + kk];
        }
#pragma unroll
        for (int i = t; i < 1024; i += 256) {
            int kk = i >> 6, nn = i & 63;
            int n = n0 + nn;
            Bs[kk][nn] = (n < 388) ? B[(k0 + kk) * 388 + n] : 0.f;
        }
        __syncthreads();
#pragma unroll
        for (int kk = 0; kk < 16; kk++) {
            float4 a4 = *(const float4*)&As[kk][ty * 4];
            float4 b4 = *(const float4*)&Bs[kk][tx * 4];
            float a[4] = {a4.x, a4.y, a4.z, a4.w};
            float b[4] = {b4.x, b4.y, b4.z, b4.w};
#pragma unroll
            for (int i = 0; i < 4; i++)
#pragma unroll
                for (int j = 0; j < 4; j++) acc[i][j] = fmaf(a[i], b[j], acc[i][j]);
        }
        __syncthreads();
    }
#pragma unroll
    for (int i = 0; i < 4; i++)
#pragma unroll
        for (int j = 0; j < 4; j++) {
            int mg = m0 + ty * 4 + i, ng = n0 + tx * 4 + j;
            if (ng < 388) {
                float v = acc[i][j] + bias[ng];
                if (ng < 2)      g_pos[mg * 2 + ng] += v;
                else if (ng == 2) g_occv[mg] += v;
                else if (ng == 3) g_expd[mg] += v;
                else             g_feats[mg * 384 + ng - 4] += v;
            }
        }
}

// ---------------- pack output ----------------
__global__ void k_out(float* __restrict__ out) {
    int i = blockIdx.x * blockDim.x + threadIdx.x;
    if (i < NQ) {
        out[i * 4 + 0] = g_pos[i * 2 + 0];
        out[i * 4 + 1] = g_pos[i * 2 + 1];
        out[i * 4 + 2] = g_occv[i];
        out[i * 4 + 3] = g_expd[i];
    }
}

// ---------------- launch ----------------
extern "C" void kernel_launch(void* const* d_in, const int* in_sizes, int n_in,
                              void* d_out, int out_size) {
    const float* fg   = (const float*)d_in[0];
    const float* hg   = (const float*)d_in[1];
    const float* qf   = (const float*)d_in[2];
    const float* hq   = (const float*)d_in[3];
    const float* w1   = (const float*)d_in[4];
    const float* b1   = (const float*)d_in[5];
    const float* w2   = (const float*)d_in[6];
    const float* b2   = (const float*)d_in[7];
    const float* w3   = (const float*)d_in[8];
    const float* b3   = (const float*)d_in[9];
    const float* w4   = (const float*)d_in[10];
    const float* b4   = (const float*)d_in[11];
    const float* occw = (const float*)d_in[12];
    const float* occb = (const float*)d_in[13];
    const float* miw  = (const float*)d_in[14];
    const float* mib  = (const float*)d_in[15];
    const float* mow  = (const float*)d_in[16];
    const float* mob  = (const float*)d_in[17];
    float* out = (float*)d_out;

    // s_cv 4224 + s_occ 10560 + s_pmap 4096 + s_w3t 4608 + s_w2 144 + s_w4 512 + misc 162
    const int smem_head = (4224 + 10560 + 4096 + 4608 + 144 + 512 + 162) * 4;
    cudaFuncSetAttribute(k_head, cudaFuncAttributeMaxDynamicSharedMemorySize, smem_head);

    k_cv<<<dim3(64, 16), 256>>>(qf, fg, g_cv);
    k_fgavg<<<1024, 256>>>(fg, g_fgavg);
    k_head<<<NQ, 256, smem_head>>>(g_cv, hq, qf, w1, b1, w2, b2, w3, b3, w4, b4, occw, occb);

    for (int it = 0; it < 4; it++) {
        k_corr<<<NQ, 256>>>(hg, fg);
        k_gemm1<<<dim3(8, 16), 256>>>(miw, mib);
        k_gemm2<<<dim3(7, 16), 256>>>(mow, mob);
    }
    k_out<<<4, 256>>>(out);
}

// round 3
// speedup vs baseline: 1.7520x; 1.0868x over previous
#include <cuda_runtime.h>
#include <math.h>

#define NQ 1024
#define MI_STRIDE 544   // padded stride for mlp_in (535 real cols)

// ---------------- scratch (device globals; no allocation) ----------------
__device__ float g_cv[NQ * 4096];        // 16 MB
__device__ float g_pos[NQ * 2];
__device__ float g_occv[NQ];
__device__ float g_expd[NQ];
__device__ float g_feats[NQ * 384];
__device__ float g_fgavg[32 * 32 * 256]; // 1 MB
__device__ float g_mlpin[NQ * MI_STRIDE];
__device__ float g_hid[NQ * 512];

__device__ __forceinline__ float gelu_tanh(float x) {
    float x3 = x * x * x;
    return 0.5f * x * (1.f + tanhf(0.7978845608028654f * (x + 0.044715f * x3)));
}

__device__ __forceinline__ float tf32r(float x) {
    unsigned u;
    asm("cvt.rna.tf32.f32 %0, %1;" : "=r"(u) : "f"(x));
    return __uint_as_float(u);
}

__device__ __forceinline__ void mma_tf32(float& d0, float& d1, float& d2, float& d3,
                                         float a0, float a1, float a2, float a3,
                                         float b0, float b1) {
    asm("mma.sync.aligned.m16n8k8.row.col.f32.tf32.tf32.f32 "
        "{%0,%1,%2,%3},{%4,%5,%6,%7},{%8,%9},{%0,%1,%2,%3};"
        : "+f"(d0), "+f"(d1), "+f"(d2), "+f"(d3)
        : "r"(__float_as_uint(a0)), "r"(__float_as_uint(a1)),
          "r"(__float_as_uint(a2)), "r"(__float_as_uint(a3)),
          "r"(__float_as_uint(b0)), "r"(__float_as_uint(b1)));
}

// ---------------- cv = qf[1024,256] @ fg[4096,256]^T  (fp32) ----------------
__global__ __launch_bounds__(256) void k_cv(const float* __restrict__ A,
                                            const float* __restrict__ B,
                                            float* __restrict__ C) {
    __shared__ float As[16][64];
    __shared__ float Bs[16][68];
    int n0 = blockIdx.x * 64, m0 = blockIdx.y * 64, t = threadIdx.x;
    int ty = t >> 4, tx = t & 15;
    float acc[4][4];
#pragma unroll
    for (int i = 0; i < 4; i++)
#pragma unroll
        for (int j = 0; j < 4; j++) acc[i][j] = 0.f;

    for (int k0 = 0; k0 < 256; k0 += 16) {
#pragma unroll
        for (int i = t; i < 1024; i += 256) {
            int mm = i >> 4, kk = i & 15;
            As[kk][mm] = A[(m0 + mm) * 256 + k0 + kk];
        }
#pragma unroll
        for (int i = t; i < 1024; i += 256) {
            int nn = i >> 4, kk = i & 15;
            Bs[kk][nn] = B[(n0 + nn) * 256 + k0 + kk];
        }
        __syncthreads();
#pragma unroll
        for (int kk = 0; kk < 16; kk++) {
            float4 a4 = *(const float4*)&As[kk][ty * 4];
            float4 b4 = *(const float4*)&Bs[kk][tx * 4];
            float a[4] = {a4.x, a4.y, a4.z, a4.w};
            float b[4] = {b4.x, b4.y, b4.z, b4.w};
#pragma unroll
            for (int i = 0; i < 4; i++)
#pragma unroll
                for (int j = 0; j < 4; j++) acc[i][j] = fmaf(a[i], b[j], acc[i][j]);
        }
        __syncthreads();
    }
#pragma unroll
    for (int i = 0; i < 4; i++)
#pragma unroll
        for (int j = 0; j < 4; j++)
            C[(m0 + ty * 4 + i) * 4096 + n0 + tx * 4 + j] = acc[i][j];
}

// ---------------- fg_avg (2x2 mean pool) ----------------
__global__ void k_fgavg(const float* __restrict__ fg, float* __restrict__ out) {
    int b = blockIdx.x;
    int y = b >> 5, x = b & 31, t = threadIdx.x;
    const float* p = fg + ((2 * y) * 64 + 2 * x) * 256;
    float v = p[t] + p[256 + t] + p[64 * 256 + t] + p[64 * 256 + 256 + t];
    out[(y * 32 + x) * 256 + t] = 0.25f * v;
}

// ---------------- per-query head ----------------
#define OCC_STRIDE 66
__global__ __launch_bounds__(256) void k_head(
    const float* __restrict__ cv_g, const float* __restrict__ hq, const float* __restrict__ qf,
    const float* __restrict__ w1, const float* __restrict__ b1,
    const float* __restrict__ w2, const float* __restrict__ b2,
    const float* __restrict__ w3, const float* __restrict__ b3,
    const float* __restrict__ w4, const float* __restrict__ b4,
    const float* __restrict__ occw, const float* __restrict__ occb) {
    extern __shared__ float sm[];
    float* s_cv   = sm;                       // 64*66 = 4224
    float* s_occ  = s_cv + 64 * 66;           // 10*16*66 = 10560
    float* s_pmap = s_occ + 10560;            // 4096
    float* s_w3t  = s_pmap + 4096;            // 144*33 = 4752  [k][oc], tf32-rounded
    float* s_w2   = s_w3t + 4752;             // 144
    float* s_w4   = s_w2 + 144;               // 512
    float* s_b3   = s_w4 + 512;               // 32
    float* s_b4   = s_b3 + 32;                // 16
    float* s_ow   = s_b4 + 16;                // 32
    float* s_ob   = s_ow + 32;                // 2
    float* s_red  = s_ob + 2;                 // 32
    float* s_o3   = s_red + 32;               // 32
    float* s_h4   = s_o3 + 32;                // 16

    int q = blockIdx.x, t = threadIdx.x;
    const float* cvq = cv_g + q * 4096;
    for (int i = t; i < 4096; i += 256) s_cv[(i >> 6) * 66 + (i & 63)] = cvq[i];
    for (int i = t; i < 144; i += 256) s_w2[i] = w2[i];
    for (int i = t; i < 4608; i += 256) { int oc = i / 144, k = i - oc * 144; s_w3t[k * 33 + oc] = tf32r(w3[i]); }
    for (int i = t; i < 512; i += 256) s_w4[i] = w4[i];
    if (t < 32) s_b3[t] = b3[t];
    if (t < 16) s_b4[t] = b4[t];
    if (t < 32) s_ow[t] = occw[t];
    if (t < 2)  s_ob[t] = occb[t];
    if (t < 32) s_o3[t] = 0.f;
    // zero the never-written pad columns 64,65 of s_occ (conv3 reads col 64)
    if (t < 160) { s_occ[t * 66 + 64] = 0.f; s_occ[t * 66 + 65] = 0.f; }
    for (int i = t; i < 128; i += 256) g_feats[q * 384 + i] = hq[q * 128 + i];
    for (int i = t; i < 256; i += 256) g_feats[q * 384 + 128 + i] = qf[q * 256 + i];
    float b2v = b2[0];

    // conv1 mapping: c1 = t&15, x0 = (t>>4)*4 ; weights in regs
    int c1 = t & 15, x0 = (t >> 4) * 4;
    float w1r[9], b1r = b1[c1];
#pragma unroll
    for (int k = 0; k < 9; k++) w1r[k] = w1[c1 * 9 + k];

    // conv2 mapping
    int rr2 = t >> 6, x2 = t & 63;

    // conv3 mma mapping: warp w handles 16 positions: jrow=w>>1, cols (w&1)*16 + g, +8
    int wrp = t >> 5, lane = t & 31, qd = lane & 3, g = lane >> 2;
    int jrow3 = wrp >> 1;
    int col0 = (wrp & 1) * 16 + g;
    int base0 = (2 * jrow3 + 1) * (16 * OCC_STRIDE) + 2 * col0;   // +16 gives col0+8
    float macc[4][2];
#pragma unroll
    for (int nt = 0; nt < 4; nt++) { macc[nt][0] = 0.f; macc[nt][1] = 0.f; }

    __syncthreads();

    // bias regs for conv3 epilogue (n = nt*8 + qd*2 + {0,1})
    float b3n[4][2];
#pragma unroll
    for (int nt = 0; nt < 4; nt++) {
        b3n[nt][0] = s_b3[nt * 8 + qd * 2 + 0];
        b3n[nt][1] = s_b3[nt * 8 + qd * 2 + 1];
    }

    for (int r0 = 0; r0 < 64; r0 += 8) {
        // ---- conv1 + relu : fill occ band rows r0-1..r0+8 ----
#pragma unroll
        for (int slot = 0; slot < 10; slot++) {
            int row = r0 - 1 + slot;
            float* dst = &s_occ[(slot * 16 + c1) * OCC_STRIDE + x0];
            if (row < 0 || row > 63) {
                dst[0] = 0.f; dst[1] = 0.f; dst[2] = 0.f; dst[3] = 0.f;
                continue;
            }
            float xv[3][6];
#pragma unroll
            for (int dy = 0; dy < 3; dy++) {
                int yy = row - 1 + dy;
                bool rv = (yy >= 0 && yy <= 63);
                const float* rp = &s_cv[yy * 66];
#pragma unroll
                for (int k = 0; k < 6; k++) {
                    int col = x0 - 1 + k;
                    xv[dy][k] = (rv && col >= 0 && col <= 63) ? rp[col] : 0.f;
                }
            }
#pragma unroll
            for (int j = 0; j < 4; j++) {
                float a = b1r;
#pragma unroll
                for (int dy = 0; dy < 3; dy++)
#pragma unroll
                    for (int dx = 0; dx < 3; dx++)
                        a = fmaf(w1r[dy * 3 + dx], xv[dy][j + dx], a);
                dst[j] = fmaxf(a, 0.f);
            }
        }
        __syncthreads();

        // ---- conv2 : rows r0+rr2 and r0+rr2+4 ----
        {
            float a0 = b2v, a1 = b2v;
            float mL = (x2 > 0) ? 1.f : 0.f;
            float mR = (x2 < 63) ? 1.f : 0.f;
            int xm = (x2 > 0) ? x2 - 1 : 0;
            int xp = (x2 < 63) ? x2 + 1 : 63;
#pragma unroll
            for (int c = 0; c < 16; c++) {
                float w[9];
#pragma unroll
                for (int k = 0; k < 9; k++) w[k] = s_w2[c * 9 + k];
#pragma unroll
                for (int dy = 0; dy < 3; dy++) {
                    const float* p0 = &s_occ[((rr2 + dy) * 16 + c) * OCC_STRIDE];
                    const float* p1 = &s_occ[((rr2 + 4 + dy) * 16 + c) * OCC_STRIDE];
                    a0 = fmaf(w[dy * 3 + 0], p0[xm] * mL, a0);
                    a0 = fmaf(w[dy * 3 + 1], p0[x2], a0);
                    a0 = fmaf(w[dy * 3 + 2], p0[xp] * mR, a0);
                    a1 = fmaf(w[dy * 3 + 0], p1[xm] * mL, a1);
                    a1 = fmaf(w[dy * 3 + 1], p1[x2], a1);
                    a1 = fmaf(w[dy * 3 + 2], p1[xp] * mR, a1);
                }
            }
            s_pmap[(r0 + rr2) * 64 + x2] = a0;
            s_pmap[(r0 + rr2 + 4) * 64 + x2] = a1;
        }

        // ---- conv3 via tf32 mma: M=128 (16/warp), N=32, K=144 ----
        {
            float d[4][4];
#pragma unroll
            for (int nt = 0; nt < 4; nt++)
#pragma unroll
                for (int u = 0; u < 4; u++) d[nt][u] = 0.f;

#pragma unroll
            for (int st = 0; st < 18; st++) {
                int k0 = st * 8 + qd;
                int k1 = k0 + 4;
                int ic0 = (k0 * 456) >> 12; int rk0 = k0 - 9 * ic0;
                int dy0 = (rk0 * 11) >> 5;  int dx0 = rk0 - 3 * dy0;
                int ic1 = (k1 * 456) >> 12; int rk1 = k1 - 9 * ic1;
                int dy1 = (rk1 * 11) >> 5;  int dx1 = rk1 - 3 * dy1;
                int ko0 = (dy0 * 16 + ic0) * OCC_STRIDE + dx0;
                int ko1 = (dy1 * 16 + ic1) * OCC_STRIDE + dx1;
                float a0 = tf32r(s_occ[base0 + ko0]);
                float a1 = tf32r(s_occ[base0 + 16 + ko0]);
                float a2 = tf32r(s_occ[base0 + ko1]);
                float a3 = tf32r(s_occ[base0 + 16 + ko1]);
                const float* bp = &s_w3t[k0 * 33 + g];
#pragma unroll
                for (int nt = 0; nt < 4; nt++) {
                    float bb0 = bp[nt * 8];
                    float bb1 = bp[4 * 33 + nt * 8];
                    mma_tf32(d[nt][0], d[nt][1], d[nt][2], d[nt][3], a0, a1, a2, a3, bb0, bb1);
                }
            }
#pragma unroll
            for (int nt = 0; nt < 4; nt++) {
                macc[nt][0] += fmaxf(d[nt][0] + b3n[nt][0], 0.f) + fmaxf(d[nt][2] + b3n[nt][0], 0.f);
                macc[nt][1] += fmaxf(d[nt][1] + b3n[nt][1], 0.f) + fmaxf(d[nt][3] + b3n[nt][1], 0.f);
            }
        }
        __syncthreads();
    }

    // conv3 reduction: sum over row groups (lane>>2), then atomics from lanes 0-3
#pragma unroll
    for (int nt = 0; nt < 4; nt++) {
#pragma unroll
        for (int j = 0; j < 2; j++) {
            float v = macc[nt][j];
#pragma unroll
            for (int o = 4; o <= 16; o <<= 1) v += __shfl_xor_sync(0xffffffffu, v, o);
            if (g == 0) atomicAdd(&s_o3[nt * 8 + qd * 2 + j], v);
        }
    }

    // softmax over pmap*20, expected coords
    float lmax = -1e30f;
    for (int i = t; i < 4096; i += 256) lmax = fmaxf(lmax, s_pmap[i]);
#pragma unroll
    for (int o = 16; o; o >>= 1) lmax = fmaxf(lmax, __shfl_xor_sync(0xffffffffu, lmax, o));
    if ((t & 31) == 0) s_red[t >> 5] = lmax;
    __syncthreads();
    if (t == 0) {
        float m = s_red[0];
        for (int i = 1; i < 8; i++) m = fmaxf(m, s_red[i]);
        s_red[31] = m;
    }
    __syncthreads();
    float m = s_red[31];
    float se = 0.f, sy = 0.f, sx = 0.f;
    for (int i = t; i < 4096; i += 256) {
        float e = __expf((s_pmap[i] - m) * 20.f);
        se += e;
        sy += e * (float)(i >> 6);
        sx += e * (float)(i & 63);
    }
    __syncthreads();
#pragma unroll
    for (int o = 16; o; o >>= 1) {
        se += __shfl_xor_sync(0xffffffffu, se, o);
        sy += __shfl_xor_sync(0xffffffffu, sy, o);
        sx += __shfl_xor_sync(0xffffffffu, sx, o);
    }
    if ((t & 31) == 0) { int w = t >> 5; s_red[w] = se; s_red[8 + w] = sy; s_red[16 + w] = sx; }
    __syncthreads();
    if (t == 0) {
        float Se = 0, Sy = 0, Sx = 0;
        for (int i = 0; i < 8; i++) { Se += s_red[i]; Sy += s_red[8 + i]; Sx += s_red[16 + i]; }
        g_pos[q * 2 + 0] = (Sx / Se) * 8.f;
        g_pos[q * 2 + 1] = (Sy / Se) * 8.f;
    }
    __syncthreads();

    // head FCs
    if (t < 16) {
        float a = s_b4[t];
        for (int ic = 0; ic < 32; ic++) a = fmaf(s_o3[ic] * (1.f / 1024.f), s_w4[ic * 16 + t], a);
        s_h4[t] = fmaxf(a, 0.f);
    }
    __syncthreads();
    if (t == 0) {
        float o = s_ob[0], ex2 = s_ob[1];
        for (int k = 0; k < 16; k++) {
            o   = fmaf(s_h4[k], s_ow[k * 2 + 0], o);
            ex2 = fmaf(s_h4[k], s_ow[k * 2 + 1], ex2);
        }
        g_occv[q] = o;
        g_expd[q] = ex2;
    }
}

// ---------------- correlation + mlp_in assembly (per iteration) ----------------
__global__ __launch_bounds__(256) void k_corr(const float* __restrict__ hg,
                                              const float* __restrict__ fg) {
    __shared__ float s_q[384];
    __shared__ float s_D[64];
    int q = blockIdx.x, t = threadIdx.x;
    float px = g_pos[q * 2 + 0], py = g_pos[q * 2 + 1];
    for (int i = t; i < 384; i += 256) s_q[i] = g_feats[q * 384 + i];
    float* mi = g_mlpin + q * MI_STRIDE;
    if (t == 0) { mi[0] = 0.f; mi[1] = 0.f; mi[2] = g_occv[q]; mi[3] = g_expd[q]; }
    for (int i = t; i < 384; i += 256) mi[4 + i] = g_feats[q * 384 + i];
    __syncthreads();

    const float* Gs[3] = { hg, fg, g_fgavg };
    const int Hs[3] = { 128, 64, 32 };
    const int Cs[3] = { 128, 256, 256 };
    const int QO[3] = { 0, 128, 128 };

    int wrp = t >> 5, lane = t & 31;
    for (int l = 0; l < 3; l++) {
        const float* G = Gs[l];
        int H = Hs[l], C = Cs[l], qo = QO[l];
        float sc = (float)H / 512.f;
        float gy = py * sc, gx = px * sc;
        float y0f = floorf(gy), x0f = floorf(gx);
        float wy = gy - y0f, wx = gx - x0f;
        int y0 = (int)y0f, x0 = (int)x0f;

        for (int p = wrp; p < 64; p += 8) {
            int ry = min(max(y0 + (p >> 3) - 3, 0), H - 1);
            int rx = min(max(x0 + (p & 7) - 3, 0), H - 1);
            const float* gp = G + (ry * H + rx) * C;
            float s = 0.f;
            for (int c = lane; c < C; c += 32) s = fmaf(gp[c], s_q[qo + c], s);
#pragma unroll
            for (int o = 16; o; o >>= 1) s += __shfl_xor_sync(0xffffffffu, s, o);
            if (lane == 0) s_D[p] = s;
        }
        __syncthreads();
        if (t < 49) {
            int r = t / 7, c2 = t - r * 7;
            float d00 = s_D[r * 8 + c2],       d01 = s_D[r * 8 + c2 + 1];
            float d10 = s_D[(r + 1) * 8 + c2], d11 = s_D[(r + 1) * 8 + c2 + 1];
            float corr = (1.f - wy) * (1.f - wx) * d00 + (1.f - wy) * wx * d01
                       + wy * (1.f - wx) * d10 + wy * wx * d11;
            mi[388 + l * 49 + t] = corr;
        }
        __syncthreads();
    }
}

// ---------------- GEMM1: [1024,535]@[535,512] + bias, gelu  (tf32 mma) ----------------
__global__ __launch_bounds__(256) void k_gemm1(const float* __restrict__ B,
                                               const float* __restrict__ bias) {
    __shared__ float As[64 * 17];
    __shared__ float Bs[16 * 72];
    int n0 = blockIdx.x * 64, m0 = blockIdx.y * 64, t = threadIdx.x;
    int w = t >> 5, lane = t & 31, qd = lane & 3, g = lane >> 2;
    int wm = (w >> 2) * 32, wn = (w & 3) * 16;
    float acc[2][2][4];
#pragma unroll
    for (int mt = 0; mt < 2; mt++)
#pragma unroll
        for (int nt = 0; nt < 2; nt++)
#pragma unroll
            for (int u = 0; u < 4; u++) acc[mt][nt][u] = 0.f;

    for (int k0 = 0; k0 < 544; k0 += 16) {
#pragma unroll
        for (int i = t; i < 1024; i += 256) {
            int mm = i >> 4, kk = i & 15, k = k0 + kk;
            As[mm * 17 + kk] = (k < 535) ? tf32r(g_mlpin[(m0 + mm) * MI_STRIDE + k]) : 0.f;
        }
#pragma unroll
        for (int i = t; i < 1024; i += 256) {
            int kk = i >> 6, nn = i & 63, k = k0 + kk;
            Bs[kk * 72 + nn] = (k < 535) ? tf32r(B[k * 512 + n0 + nn]) : 0.f;
        }
        __syncthreads();
#pragma unroll
        for (int s = 0; s < 2; s++) {
            float a[2][4], b[2][2];
#pragma unroll
            for (int mt = 0; mt < 2; mt++) {
                int row = wm + mt * 16 + g;
                a[mt][0] = As[row * 17 + s * 8 + qd];
                a[mt][1] = As[(row + 8) * 17 + s * 8 + qd];
                a[mt][2] = As[row * 17 + s * 8 + qd + 4];
                a[mt][3] = As[(row + 8) * 17 + s * 8 + qd + 4];
            }
#pragma unroll
            for (int nt = 0; nt < 2; nt++) {
                int bn = wn + nt * 8 + g;
                b[nt][0] = Bs[(s * 8 + qd) * 72 + bn];
                b[nt][1] = Bs[(s * 8 + qd + 4) * 72 + bn];
            }
#pragma unroll
            for (int mt = 0; mt < 2; mt++)
#pragma unroll
                for (int nt = 0; nt < 2; nt++)
                    mma_tf32(acc[mt][nt][0], acc[mt][nt][1], acc[mt][nt][2], acc[mt][nt][3],
                             a[mt][0], a[mt][1], a[mt][2], a[mt][3], b[nt][0], b[nt][1]);
        }
        __syncthreads();
    }
#pragma unroll
    for (int mt = 0; mt < 2; mt++)
#pragma unroll
        for (int nt = 0; nt < 2; nt++) {
            int mg = m0 + wm + mt * 16 + g;
            int ng = n0 + wn + nt * 8 + qd * 2;
            float bz0 = bias[ng], bz1 = bias[ng + 1];
            float2 v0 = make_float2(gelu_tanh(acc[mt][nt][0] + bz0), gelu_tanh(acc[mt][nt][1] + bz1));
            float2 v1 = make_float2(gelu_tanh(acc[mt][nt][2] + bz0), gelu_tanh(acc[mt][nt][3] + bz1));
            *(float2*)&g_hid[mg * 512 + ng] = v0;
            *(float2*)&g_hid[(mg + 8) * 512 + ng] = v1;
        }
}

// ---------------- GEMM2: [1024,512]@[512,388] + bias, state update (tf32 mma) ----------------
__global__ __launch_bounds__(256) void k_gemm2(const float* __restrict__ B,
                                               const float* __restrict__ bias) {
    __shared__ float As[64 * 17];
    __shared__ float Bs[16 * 72];
    int n0 = blockIdx.x * 64, m0 = blockIdx.y * 64, t = threadIdx.x;
    int w = t >> 5, lane = t & 31, qd = lane & 3, g = lane >> 2;
    int wm = (w >> 2) * 32, wn = (w & 3) * 16;
    float acc[2][2][4];
#pragma unroll
    for (int mt = 0; mt < 2; mt++)
#pragma unroll
        for (int nt = 0; nt < 2; nt++)
#pragma unroll
            for (int u = 0; u < 4; u++) acc[mt][nt][u] = 0.f;

    for (int k0 = 0; k0 < 512; k0 += 16) {
#pragma unroll
        for (int i = t; i < 1024; i += 256) {
            int mm = i >> 4, kk = i & 15;
            As[mm * 17 + kk] = tf32r(g_hid[(m0 + mm) * 512 + k0 + kk]);
        }
#pragma unroll
        for (int i = t; i < 1024; i += 256) {
            int kk = i >> 6, nn = i & 63, n = n0 + nn;
            Bs[kk * 72 + nn] = (n < 388) ? tf32r(B[(k0 + kk) * 388 + n]) : 0.f;
        }
        __syncthreads();
#pragma unroll
        for (int s = 0; s < 2; s++) {
            float a[2][4], b[2][2];
#pragma unroll
            for (int mt = 0; mt < 2; mt++) {
                int row = wm + mt * 16 + g;
                a[mt][0] = As[row * 17 + s * 8 + qd];
                a[mt][1] = As[(row + 8) * 17 + s * 8 + qd];
                a[mt][2] = As[row * 17 + s * 8 + qd + 4];
                a[mt][3] = As[(row + 8) * 17 + s * 8 + qd + 4];
            }
#pragma unroll
            for (int nt = 0; nt < 2; nt++) {
                int bn = wn + nt * 8 + g;
                b[nt][0] = Bs[(s * 8 + qd) * 72 + bn];
                b[nt][1] = Bs[(s * 8 + qd + 4) * 72 + bn];
            }
#pragma unroll
            for (int mt = 0; mt < 2; mt++)
#pragma unroll
                for (int nt = 0; nt < 2; nt++)
                    mma_tf32(acc[mt][nt][0], acc[mt][nt][1], acc[mt][nt][2], acc[mt][nt][3],
                             a[mt][0], a[mt][1], a[mt][2], a[mt][3], b[nt][0], b[nt][1]);
        }
        __syncthreads();
    }
#pragma unroll
    for (int mt = 0; mt < 2; mt++)
#pragma unroll
        for (int nt = 0; nt < 2; nt++) {
#pragma unroll
            for (int rr = 0; rr < 2; rr++) {
                int mg = m0 + wm + mt * 16 + g + rr * 8;
#pragma unroll
                for (int jj = 0; jj < 2; jj++) {
                    int ng = n0 + wn + nt * 8 + qd * 2 + jj;
                    if (ng < 388) {
                        float v = acc[mt][nt][rr * 2 + jj] + bias[ng];
                        if (ng < 2)       g_pos[mg * 2 + ng] += v;
                        else if (ng == 2) g_occv[mg] += v;
                        else if (ng == 3) g_expd[mg] += v;
                        else              g_feats[mg * 384 + ng - 4] += v;
                    }
                }
            }
        }
}

// ---------------- pack output ----------------
__global__ void k_out(float* __restrict__ out) {
    int i = blockIdx.x * blockDim.x + threadIdx.x;
    if (i < NQ) {
        out[i * 4 + 0] = g_pos[i * 2 + 0];
        out[i * 4 + 1] = g_pos[i * 2 + 1];
        out[i * 4 + 2] = g_occv[i];
        out[i * 4 + 3] = g_expd[i];
    }
}

// ---------------- launch ----------------
extern "C" void kernel_launch(void* const* d_in, const int* in_sizes, int n_in,
                              void* d_out, int out_size) {
    const float* fg   = (const float*)d_in[0];
    const float* hg   = (const float*)d_in[1];
    const float* qf   = (const float*)d_in[2];
    const float* hq   = (const float*)d_in[3];
    const float* w1   = (const float*)d_in[4];
    const float* b1   = (const float*)d_in[5];
    const float* w2   = (const float*)d_in[6];
    const float* b2   = (const float*)d_in[7];
    const float* w3   = (const float*)d_in[8];
    const float* b3   = (const float*)d_in[9];
    const float* w4   = (const float*)d_in[10];
    const float* b4   = (const float*)d_in[11];
    const float* occw = (const float*)d_in[12];
    const float* occb = (const float*)d_in[13];
    const float* miw  = (const float*)d_in[14];
    const float* mib  = (const float*)d_in[15];
    const float* mow  = (const float*)d_in[16];
    const float* mob  = (const float*)d_in[17];
    float* out = (float*)d_out;

    // s_cv 4224 + s_occ 10560 + s_pmap 4096 + s_w3t 4752 + s_w2 144 + s_w4 512 + misc 162
    const int smem_head = (4224 + 10560 + 4096 + 4752 + 144 + 512 + 162) * 4;
    cudaFuncSetAttribute(k_head, cudaFuncAttributeMaxDynamicSharedMemorySize, smem_head);

    k_cv<<<dim3(64, 16), 256>>>(qf, fg, g_cv);
    k_fgavg<<<1024, 256>>>(fg, g_fgavg);
    k_head<<<NQ, 256, smem_head>>>(g_cv, hq, qf, w1, b1, w2, b2, w3, b3, w4, b4, occw, occb);

    for (int it = 0; it < 4; it++) {
        k_corr<<<NQ, 256>>>(hg, fg);
        k_gemm1<<<dim3(8, 16), 256>>>(miw, mib);
        k_gemm2<<<dim3(7, 16), 256>>>(mow, mob);
    }
    k_out<<<4, 256>>>(out);
}

// round 4
// speedup vs baseline: 2.1055x; 1.2018x over previous
#include <cuda_runtime.h>
#include <cuda_bf16.h>
#include <math.h>

#define NQ 1024
#define MI_STRIDE 544   // padded stride for mlp_in (535 real cols)

// ---------------- scratch (device globals; no allocation) ----------------
__device__ float g_cv[NQ * 4096];        // 16 MB
__device__ float g_pos[NQ * 2];
__device__ float g_occv[NQ];
__device__ float g_expd[NQ];
__device__ float g_feats[NQ * 384];
__device__ float g_fgavg[32 * 32 * 256]; // 1 MB
__device__ float g_mlpin[NQ * MI_STRIDE];
__device__ float g_hid[NQ * 512];

__device__ __forceinline__ float gelu_tanh(float x) {
    float x3 = x * x * x;
    return 0.5f * x * (1.f + tanhf(0.7978845608028654f * (x + 0.044715f * x3)));
}

__device__ __forceinline__ float tf32r(float x) {
    unsigned u;
    asm("cvt.rna.tf32.f32 %0, %1;" : "=r"(u) : "f"(x));
    return __uint_as_float(u);
}

__device__ __forceinline__ void mma_tf32(float& d0, float& d1, float& d2, float& d3,
                                         float a0, float a1, float a2, float a3,
                                         float b0, float b1) {
    asm("mma.sync.aligned.m16n8k8.row.col.f32.tf32.tf32.f32 "
        "{%0,%1,%2,%3},{%4,%5,%6,%7},{%8,%9},{%0,%1,%2,%3};"
        : "+f"(d0), "+f"(d1), "+f"(d2), "+f"(d3)
        : "r"(__float_as_uint(a0)), "r"(__float_as_uint(a1)),
          "r"(__float_as_uint(a2)), "r"(__float_as_uint(a3)),
          "r"(__float_as_uint(b0)), "r"(__float_as_uint(b1)));
}

__device__ __forceinline__ void mma_bf16(float& d0, float& d1, float& d2, float& d3,
                                         unsigned a0, unsigned a1, unsigned a2, unsigned a3,
                                         unsigned b0, unsigned b1) {
    asm("mma.sync.aligned.m16n8k16.row.col.f32.bf16.bf16.f32 "
        "{%0,%1,%2,%3},{%4,%5,%6,%7},{%8,%9},{%0,%1,%2,%3};"
        : "+f"(d0), "+f"(d1), "+f"(d2), "+f"(d3)
        : "r"(a0), "r"(a1), "r"(a2), "r"(a3), "r"(b0), "r"(b1));
}

// ---------------- cv = qf[1024,256] @ fg[4096,256]^T  (fp32, 128x128 tiles) ----------------
__global__ __launch_bounds__(256) void k_cv(const float* __restrict__ A,
                                            const float* __restrict__ B,
                                            float* __restrict__ C) {
    __shared__ float As[16][132];
    __shared__ float Bs[16][132];
    int n0 = blockIdx.x * 128, m0 = blockIdx.y * 128, t = threadIdx.x;
    int ty = t >> 4, tx = t & 15;
    float acc[8][8];
#pragma unroll
    for (int i = 0; i < 8; i++)
#pragma unroll
        for (int j = 0; j < 8; j++) acc[i][j] = 0.f;

    for (int k0 = 0; k0 < 256; k0 += 16) {
#pragma unroll
        for (int i = t; i < 512; i += 256) {
            int mm = i >> 2, k4 = (i & 3) * 4;
            float4 v = *(const float4*)&A[(m0 + mm) * 256 + k0 + k4];
            As[k4][mm] = v.x; As[k4 + 1][mm] = v.y; As[k4 + 2][mm] = v.z; As[k4 + 3][mm] = v.w;
            float4 u = *(const float4*)&B[(n0 + mm) * 256 + k0 + k4];
            Bs[k4][mm] = u.x; Bs[k4 + 1][mm] = u.y; Bs[k4 + 2][mm] = u.z; Bs[k4 + 3][mm] = u.w;
        }
        __syncthreads();
#pragma unroll
        for (int kk = 0; kk < 16; kk++) {
            float a[8], b[8];
            float4 a0 = *(const float4*)&As[kk][ty * 8];
            float4 a1 = *(const float4*)&As[kk][ty * 8 + 4];
            float4 b0 = *(const float4*)&Bs[kk][tx * 8];
            float4 b1 = *(const float4*)&Bs[kk][tx * 8 + 4];
            a[0] = a0.x; a[1] = a0.y; a[2] = a0.z; a[3] = a0.w;
            a[4] = a1.x; a[5] = a1.y; a[6] = a1.z; a[7] = a1.w;
            b[0] = b0.x; b[1] = b0.y; b[2] = b0.z; b[3] = b0.w;
            b[4] = b1.x; b[5] = b1.y; b[6] = b1.z; b[7] = b1.w;
#pragma unroll
            for (int i = 0; i < 8; i++)
#pragma unroll
                for (int j = 0; j < 8; j++) acc[i][j] = fmaf(a[i], b[j], acc[i][j]);
        }
        __syncthreads();
    }
#pragma unroll
    for (int i = 0; i < 8; i++) {
        float* cp = &C[(m0 + ty * 8 + i) * 4096 + n0 + tx * 8];
        *(float4*)cp = make_float4(acc[i][0], acc[i][1], acc[i][2], acc[i][3]);
        *(float4*)(cp + 4) = make_float4(acc[i][4], acc[i][5], acc[i][6], acc[i][7]);
    }
}

// ---------------- fg_avg (2x2 mean pool) ----------------
__global__ void k_fgavg(const float* __restrict__ fg, float* __restrict__ out) {
    int b = blockIdx.x;
    int y = b >> 5, x = b & 31, t = threadIdx.x;
    const float* p = fg + ((2 * y) * 64 + 2 * x) * 256;
    float v = p[t] + p[256 + t] + p[64 * 256 + t] + p[64 * 256 + 256 + t];
    out[(y * 32 + x) * 256 + t] = 0.25f * v;
}

// ---------------- per-query head ----------------
#define OCC_STRIDE 66
__global__ __launch_bounds__(256) void k_head(
    const float* __restrict__ cv_g, const float* __restrict__ hq, const float* __restrict__ qf,
    const float* __restrict__ w1, const float* __restrict__ b1,
    const float* __restrict__ w2, const float* __restrict__ b2,
    const float* __restrict__ w3, const float* __restrict__ b3,
    const float* __restrict__ w4, const float* __restrict__ b4,
    const float* __restrict__ occw, const float* __restrict__ occb) {
    extern __shared__ float sm[];
    float* s_cv   = sm;                       // 64*66 = 4224
    float* s_occ  = s_cv + 64 * 66;           // 10*16*66 = 10560
    float* s_pmap = s_occ + 10560;            // 4096
    float* s_w3t  = s_pmap + 4096;            // 144*33 = 4752
    float* s_w2   = s_w3t + 4752;             // 144
    float* s_w4   = s_w2 + 144;               // 512
    float* s_b3   = s_w4 + 512;               // 32
    float* s_b4   = s_b3 + 32;                // 16
    float* s_ow   = s_b4 + 16;                // 32
    float* s_ob   = s_ow + 32;                // 2
    float* s_red  = s_ob + 2;                 // 32
    float* s_o3   = s_red + 32;               // 32
    float* s_h4   = s_o3 + 32;                // 16

    int q = blockIdx.x, t = threadIdx.x;
    const float* cvq = cv_g + q * 4096;
    for (int i = t; i < 4096; i += 256) s_cv[(i >> 6) * 66 + (i & 63)] = cvq[i];
    for (int i = t; i < 144; i += 256) s_w2[i] = w2[i];
    for (int i = t; i < 4608; i += 256) { int oc = i / 144, k = i - oc * 144; s_w3t[k * 33 + oc] = tf32r(w3[i]); }
    for (int i = t; i < 512; i += 256) s_w4[i] = w4[i];
    if (t < 32) s_b3[t] = b3[t];
    if (t < 16) s_b4[t] = b4[t];
    if (t < 32) s_ow[t] = occw[t];
    if (t < 2)  s_ob[t] = occb[t];
    if (t < 32) s_o3[t] = 0.f;
    if (t < 160) { s_occ[t * 66 + 64] = 0.f; s_occ[t * 66 + 65] = 0.f; }
    for (int i = t; i < 128; i += 256) g_feats[q * 384 + i] = hq[q * 128 + i];
    for (int i = t; i < 256; i += 256) g_feats[q * 384 + 128 + i] = qf[q * 256 + i];
    float b2v = b2[0];

    int c1 = t & 15, x0 = (t >> 4) * 4;
    float w1r[9], b1r = b1[c1];
#pragma unroll
    for (int k = 0; k < 9; k++) w1r[k] = w1[c1 * 9 + k];

    int rr2 = t >> 6, x2 = t & 63;

    int wrp = t >> 5, lane = t & 31, qd = lane & 3, g = lane >> 2;
    int jrow3 = wrp >> 1;
    int col0 = (wrp & 1) * 16 + g;
    int base0 = (2 * jrow3 + 1) * (16 * OCC_STRIDE) + 2 * col0;
    float macc[4][2];
#pragma unroll
    for (int nt = 0; nt < 4; nt++) { macc[nt][0] = 0.f; macc[nt][1] = 0.f; }

    __syncthreads();

    float b3n[4][2];
#pragma unroll
    for (int nt = 0; nt < 4; nt++) {
        b3n[nt][0] = s_b3[nt * 8 + qd * 2 + 0];
        b3n[nt][1] = s_b3[nt * 8 + qd * 2 + 1];
    }

    for (int r0 = 0; r0 < 64; r0 += 8) {
#pragma unroll
        for (int slot = 0; slot < 10; slot++) {
            int row = r0 - 1 + slot;
            float* dst = &s_occ[(slot * 16 + c1) * OCC_STRIDE + x0];
            if (row < 0 || row > 63) {
                dst[0] = 0.f; dst[1] = 0.f; dst[2] = 0.f; dst[3] = 0.f;
                continue;
            }
            float xv[3][6];
#pragma unroll
            for (int dy = 0; dy < 3; dy++) {
                int yy = row - 1 + dy;
                bool rv = (yy >= 0 && yy <= 63);
                const float* rp = &s_cv[yy * 66];
#pragma unroll
                for (int k = 0; k < 6; k++) {
                    int col = x0 - 1 + k;
                    xv[dy][k] = (rv && col >= 0 && col <= 63) ? rp[col] : 0.f;
                }
            }
#pragma unroll
            for (int j = 0; j < 4; j++) {
                float a = b1r;
#pragma unroll
                for (int dy = 0; dy < 3; dy++)
#pragma unroll
                    for (int dx = 0; dx < 3; dx++)
                        a = fmaf(w1r[dy * 3 + dx], xv[dy][j + dx], a);
                dst[j] = fmaxf(a, 0.f);
            }
        }
        __syncthreads();

        {
            float a0 = b2v, a1 = b2v;
            float mL = (x2 > 0) ? 1.f : 0.f;
            float mR = (x2 < 63) ? 1.f : 0.f;
            int xm = (x2 > 0) ? x2 - 1 : 0;
            int xp = (x2 < 63) ? x2 + 1 : 63;
#pragma unroll
            for (int c = 0; c < 16; c++) {
                float w[9];
#pragma unroll
                for (int k = 0; k < 9; k++) w[k] = s_w2[c * 9 + k];
#pragma unroll
                for (int dy = 0; dy < 3; dy++) {
                    const float* p0 = &s_occ[((rr2 + dy) * 16 + c) * OCC_STRIDE];
                    const float* p1 = &s_occ[((rr2 + 4 + dy) * 16 + c) * OCC_STRIDE];
                    a0 = fmaf(w[dy * 3 + 0], p0[xm] * mL, a0);
                    a0 = fmaf(w[dy * 3 + 1], p0[x2], a0);
                    a0 = fmaf(w[dy * 3 + 2], p0[xp] * mR, a0);
                    a1 = fmaf(w[dy * 3 + 0], p1[xm] * mL, a1);
                    a1 = fmaf(w[dy * 3 + 1], p1[x2], a1);
                    a1 = fmaf(w[dy * 3 + 2], p1[xp] * mR, a1);
                }
            }
            s_pmap[(r0 + rr2) * 64 + x2] = a0;
            s_pmap[(r0 + rr2 + 4) * 64 + x2] = a1;
        }

        {
            float d[4][4];
#pragma unroll
            for (int nt = 0; nt < 4; nt++)
#pragma unroll
                for (int u = 0; u < 4; u++) d[nt][u] = 0.f;

#pragma unroll
            for (int st = 0; st < 18; st++) {
                int k0 = st * 8 + qd;
                int k1 = k0 + 4;
                int ic0 = (k0 * 456) >> 12; int rk0 = k0 - 9 * ic0;
                int dy0 = (rk0 * 11) >> 5;  int dx0 = rk0 - 3 * dy0;
                int ic1 = (k1 * 456) >> 12; int rk1 = k1 - 9 * ic1;
                int dy1 = (rk1 * 11) >> 5;  int dx1 = rk1 - 3 * dy1;
                int ko0 = (dy0 * 16 + ic0) * OCC_STRIDE + dx0;
                int ko1 = (dy1 * 16 + ic1) * OCC_STRIDE + dx1;
                float a0 = tf32r(s_occ[base0 + ko0]);
                float a1 = tf32r(s_occ[base0 + 16 + ko0]);
                float a2 = tf32r(s_occ[base0 + ko1]);
                float a3 = tf32r(s_occ[base0 + 16 + ko1]);
                const float* bp = &s_w3t[k0 * 33 + g];
#pragma unroll
                for (int nt = 0; nt < 4; nt++) {
                    float bb0 = bp[nt * 8];
                    float bb1 = bp[4 * 33 + nt * 8];
                    mma_tf32(d[nt][0], d[nt][1], d[nt][2], d[nt][3], a0, a1, a2, a3, bb0, bb1);
                }
            }
#pragma unroll
            for (int nt = 0; nt < 4; nt++) {
                macc[nt][0] += fmaxf(d[nt][0] + b3n[nt][0], 0.f) + fmaxf(d[nt][2] + b3n[nt][0], 0.f);
                macc[nt][1] += fmaxf(d[nt][1] + b3n[nt][1], 0.f) + fmaxf(d[nt][3] + b3n[nt][1], 0.f);
            }
        }
        __syncthreads();
    }

#pragma unroll
    for (int nt = 0; nt < 4; nt++) {
#pragma unroll
        for (int j = 0; j < 2; j++) {
            float v = macc[nt][j];
#pragma unroll
            for (int o = 4; o <= 16; o <<= 1) v += __shfl_xor_sync(0xffffffffu, v, o);
            if (g == 0) atomicAdd(&s_o3[nt * 8 + qd * 2 + j], v);
        }
    }

    float lmax = -1e30f;
    for (int i = t; i < 4096; i += 256) lmax = fmaxf(lmax, s_pmap[i]);
#pragma unroll
    for (int o = 16; o; o >>= 1) lmax = fmaxf(lmax, __shfl_xor_sync(0xffffffffu, lmax, o));
    if ((t & 31) == 0) s_red[t >> 5] = lmax;
    __syncthreads();
    if (t == 0) {
        float m = s_red[0];
        for (int i = 1; i < 8; i++) m = fmaxf(m, s_red[i]);
        s_red[31] = m;
    }
    __syncthreads();
    float m = s_red[31];
    float se = 0.f, sy = 0.f, sx = 0.f;
    for (int i = t; i < 4096; i += 256) {
        float e = __expf((s_pmap[i] - m) * 20.f);
        se += e;
        sy += e * (float)(i >> 6);
        sx += e * (float)(i & 63);
    }
    __syncthreads();
#pragma unroll
    for (int o = 16; o; o >>= 1) {
        se += __shfl_xor_sync(0xffffffffu, se, o);
        sy += __shfl_xor_sync(0xffffffffu, sy, o);
        sx += __shfl_xor_sync(0xffffffffu, sx, o);
    }
    if ((t & 31) == 0) { int w = t >> 5; s_red[w] = se; s_red[8 + w] = sy; s_red[16 + w] = sx; }
    __syncthreads();
    if (t == 0) {
        float Se = 0, Sy = 0, Sx = 0;
        for (int i = 0; i < 8; i++) { Se += s_red[i]; Sy += s_red[8 + i]; Sx += s_red[16 + i]; }
        g_pos[q * 2 + 0] = (Sx / Se) * 8.f;
        g_pos[q * 2 + 1] = (Sy / Se) * 8.f;
    }
    __syncthreads();

    if (t < 16) {
        float a = s_b4[t];
        for (int ic = 0; ic < 32; ic++) a = fmaf(s_o3[ic] * (1.f / 1024.f), s_w4[ic * 16 + t], a);
        s_h4[t] = fmaxf(a, 0.f);
    }
    __syncthreads();
    if (t == 0) {
        float o = s_ob[0], ex2 = s_ob[1];
        for (int k = 0; k < 16; k++) {
            o   = fmaf(s_h4[k], s_ow[k * 2 + 0], o);
            ex2 = fmaf(s_h4[k], s_ow[k * 2 + 1], ex2);
        }
        g_occv[q] = o;
        g_expd[q] = ex2;
    }
}

// ---------------- correlation + mlp_in assembly (per iteration) ----------------
__global__ __launch_bounds__(256) void k_corr(const float* __restrict__ hg,
                                              const float* __restrict__ fg) {
    __shared__ float s_q[384];
    __shared__ float s_D[64];
    int q = blockIdx.x, t = threadIdx.x;
    float px = g_pos[q * 2 + 0], py = g_pos[q * 2 + 1];
    for (int i = t; i < 384; i += 256) s_q[i] = g_feats[q * 384 + i];
    float* mi = g_mlpin + q * MI_STRIDE;
    if (t == 0) { mi[0] = 0.f; mi[1] = 0.f; mi[2] = g_occv[q]; mi[3] = g_expd[q]; }
    for (int i = t; i < 384; i += 256) mi[4 + i] = g_feats[q * 384 + i];
    __syncthreads();

    const float* Gs[3] = { hg, fg, g_fgavg };
    const int Hs[3] = { 128, 64, 32 };
    const int Cs[3] = { 128, 256, 256 };
    const int QO[3] = { 0, 128, 128 };

    int wrp = t >> 5, lane = t & 31;
#pragma unroll
    for (int l = 0; l < 3; l++) {
        const float* G = Gs[l];
        const int H = Hs[l], C = Cs[l], qo = QO[l];
        float sc = (float)H / 512.f;
        float gy = py * sc, gx = px * sc;
        float y0f = floorf(gy), x0f = floorf(gx);
        float wy = gy - y0f, wx = gx - x0f;
        int y0 = (int)y0f, x0 = (int)x0f;
        const float* sq = s_q + qo;

#pragma unroll
        for (int pp = 0; pp < 8; pp++) {
            int p = wrp + pp * 8;
            int ry = min(max(y0 + (p >> 3) - 3, 0), H - 1);
            int rx = min(max(x0 + (p & 7) - 3, 0), H - 1);
            const float* gp = G + (ry * H + rx) * C;
            float s0 = gp[lane] * sq[lane];
            float s1 = gp[lane + 32] * sq[lane + 32];
            float s2 = gp[lane + 64] * sq[lane + 64];
            float s3 = gp[lane + 96] * sq[lane + 96];
            if (C == 256) {
                s0 = fmaf(gp[lane + 128], sq[lane + 128], s0);
                s1 = fmaf(gp[lane + 160], sq[lane + 160], s1);
                s2 = fmaf(gp[lane + 192], sq[lane + 192], s2);
                s3 = fmaf(gp[lane + 224], sq[lane + 224], s3);
            }
            float s = (s0 + s1) + (s2 + s3);
#pragma unroll
            for (int o = 16; o; o >>= 1) s += __shfl_xor_sync(0xffffffffu, s, o);
            if (lane == 0) s_D[p] = s;
        }
        __syncthreads();
        if (t < 49) {
            int r = t / 7, c2 = t - r * 7;
            float d00 = s_D[r * 8 + c2],       d01 = s_D[r * 8 + c2 + 1];
            float d10 = s_D[(r + 1) * 8 + c2], d11 = s_D[(r + 1) * 8 + c2 + 1];
            float corr = (1.f - wy) * (1.f - wx) * d00 + (1.f - wy) * wx * d01
                       + wy * (1.f - wx) * d10 + wy * wx * d11;
            mi[388 + l * 49 + t] = corr;
        }
        __syncthreads();
    }
}

// ---------------- GEMM1: [1024,535]@[535,512] + bias, gelu  (bf16 mma) ----------------
__global__ __launch_bounds__(256) void k_gemm1(const float* __restrict__ B,
                                               const float* __restrict__ bias) {
    __shared__ __nv_bfloat16 As[64 * 36];
    __shared__ __nv_bfloat16 Bs[64 * 36];
    int n0 = blockIdx.x * 64, m0 = blockIdx.y * 64, t = threadIdx.x;
    int w = t >> 5, lane = t & 31, qd = lane & 3, g = lane >> 2;
    int wm = (w >> 2) * 32, wn = (w & 3) * 16;
    float acc[2][2][4];
#pragma unroll
    for (int mt = 0; mt < 2; mt++)
#pragma unroll
        for (int nt = 0; nt < 2; nt++)
#pragma unroll
            for (int u = 0; u < 4; u++) acc[mt][nt][u] = 0.f;

    for (int k0 = 0; k0 < 544; k0 += 32) {
#pragma unroll
        for (int i = t; i < 2048; i += 256) {
            int mm = i >> 5, kk = i & 31, k = k0 + kk;
            float v = (k < 535) ? g_mlpin[(m0 + mm) * MI_STRIDE + k] : 0.f;
            As[mm * 36 + kk] = __float2bfloat16(v);
        }
#pragma unroll
        for (int i = t; i < 2048; i += 256) {
            int kk = i >> 6, nn = i & 63, k = k0 + kk;
            float v = (k < 535) ? B[k * 512 + n0 + nn] : 0.f;
            Bs[nn * 36 + kk] = __float2bfloat16(v);
        }
        __syncthreads();
#pragma unroll
        for (int s = 0; s < 2; s++) {
            unsigned a[2][4], b[2][2];
#pragma unroll
            for (int mt = 0; mt < 2; mt++) {
                int row = wm + mt * 16 + g;
                a[mt][0] = *(const unsigned*)&As[row * 36 + s * 16 + 2 * qd];
                a[mt][1] = *(const unsigned*)&As[(row + 8) * 36 + s * 16 + 2 * qd];
                a[mt][2] = *(const unsigned*)&As[row * 36 + s * 16 + 2 * qd + 8];
                a[mt][3] = *(const unsigned*)&As[(row + 8) * 36 + s * 16 + 2 * qd + 8];
            }
#pragma unroll
            for (int nt = 0; nt < 2; nt++) {
                int bn = wn + nt * 8 + g;
                b[nt][0] = *(const unsigned*)&Bs[bn * 36 + s * 16 + 2 * qd];
                b[nt][1] = *(const unsigned*)&Bs[bn * 36 + s * 16 + 2 * qd + 8];
            }
#pragma unroll
            for (int mt = 0; mt < 2; mt++)
#pragma unroll
                for (int nt = 0; nt < 2; nt++)
                    mma_bf16(acc[mt][nt][0], acc[mt][nt][1], acc[mt][nt][2], acc[mt][nt][3],
                             a[mt][0], a[mt][1], a[mt][2], a[mt][3], b[nt][0], b[nt][1]);
        }
        __syncthreads();
    }
#pragma unroll
    for (int mt = 0; mt < 2; mt++)
#pragma unroll
        for (int nt = 0; nt < 2; nt++) {
            int mg = m0 + wm + mt * 16 + g;
            int ng = n0 + wn + nt * 8 + qd * 2;
            float bz0 = bias[ng], bz1 = bias[ng + 1];
            float2 v0 = make_float2(gelu_tanh(acc[mt][nt][0] + bz0), gelu_tanh(acc[mt][nt][1] + bz1));
            float2 v1 = make_float2(gelu_tanh(acc[mt][nt][2] + bz0), gelu_tanh(acc[mt][nt][3] + bz1));
            *(float2*)&g_hid[mg * 512 + ng] = v0;
            *(float2*)&g_hid[(mg + 8) * 512 + ng] = v1;
        }
}

// ---------------- GEMM2: [1024,512]@[512,388] + bias, state update (bf16 mma) ----------------
__global__ __launch_bounds__(256) void k_gemm2(const float* __restrict__ B,
                                               const float* __restrict__ bias) {
    __shared__ __nv_bfloat16 As[64 * 36];
    __shared__ __nv_bfloat16 Bs[64 * 36];
    int n0 = blockIdx.x * 64, m0 = blockIdx.y * 64, t = threadIdx.x;
    int w = t >> 5, lane = t & 31, qd = lane & 3, g = lane >> 2;
    int wm = (w >> 2) * 32, wn = (w & 3) * 16;
    float acc[2][2][4];
#pragma unroll
    for (int mt = 0; mt < 2; mt++)
#pragma unroll
        for (int nt = 0; nt < 2; nt++)
#pragma unroll
            for (int u = 0; u < 4; u++) acc[mt][nt][u] = 0.f;

    for (int k0 = 0; k0 < 512; k0 += 32) {
#pragma unroll
        for (int i = t; i < 2048; i += 256) {
            int mm = i >> 5, kk = i & 31;
            As[mm * 36 + kk] = __float2bfloat16(g_hid[(m0 + mm) * 512 + k0 + kk]);
        }
#pragma unroll
        for (int i = t; i < 2048; i += 256) {
            int kk = i >> 6, nn = i & 63, n = n0 + nn;
            float v = (n < 388) ? B[(k0 + kk) * 388 + n] : 0.f;
            Bs[nn * 36 + kk] = __float2bfloat16(v);
        }
        __syncthreads();
#pragma unroll
        for (int s = 0; s < 2; s++) {
            unsigned a[2][4], b[2][2];
#pragma unroll
            for (int mt = 0; mt < 2; mt++) {
                int row = wm + mt * 16 + g;
                a[mt][0] = *(const unsigned*)&As[row * 36 + s * 16 + 2 * qd];
                a[mt][1] = *(const unsigned*)&As[(row + 8) * 36 + s * 16 + 2 * qd];
                a[mt][2] = *(const unsigned*)&As[row * 36 + s * 16 + 2 * qd + 8];
                a[mt][3] = *(const unsigned*)&As[(row + 8) * 36 + s * 16 + 2 * qd + 8];
            }
#pragma unroll
            for (int nt = 0; nt < 2; nt++) {
                int bn = wn + nt * 8 + g;
                b[nt][0] = *(const unsigned*)&Bs[bn * 36 + s * 16 + 2 * qd];
                b[nt][1] = *(const unsigned*)&Bs[bn * 36 + s * 16 + 2 * qd + 8];
            }
#pragma unroll
            for (int mt = 0; mt < 2; mt++)
#pragma unroll
                for (int nt = 0; nt < 2; nt++)
                    mma_bf16(acc[mt][nt][0], acc[mt][nt][1], acc[mt][nt][2], acc[mt][nt][3],
                             a[mt][0], a[mt][1], a[mt][2], a[mt][3], b[nt][0], b[nt][1]);
        }
        __syncthreads();
    }
#pragma unroll
    for (int mt = 0; mt < 2; mt++)
#pragma unroll
        for (int nt = 0; nt < 2; nt++) {
#pragma unroll
            for (int rr = 0; rr < 2; rr++) {
                int mg = m0 + wm + mt * 16 + g + rr * 8;
#pragma unroll
                for (int jj = 0; jj < 2; jj++) {
                    int ng = n0 + wn + nt * 8 + qd * 2 + jj;
                    if (ng < 388) {
                        float v = acc[mt][nt][rr * 2 + jj] + bias[ng];
                        if (ng < 2)       g_pos[mg * 2 + ng] += v;
                        else if (ng == 2) g_occv[mg] += v;
                        else if (ng == 3) g_expd[mg] += v;
                        else              g_feats[mg * 384 + ng - 4] += v;
                    }
                }
            }
        }
}

// ---------------- pack output ----------------
__global__ void k_out(float* __restrict__ out) {
    int i = blockIdx.x * blockDim.x + threadIdx.x;
    if (i < NQ) {
        out[i * 4 + 0] = g_pos[i * 2 + 0];
        out[i * 4 + 1] = g_pos[i * 2 + 1];
        out[i * 4 + 2] = g_occv[i];
        out[i * 4 + 3] = g_expd[i];
    }
}

// ---------------- launch ----------------
extern "C" void kernel_launch(void* const* d_in, const int* in_sizes, int n_in,
                              void* d_out, int out_size) {
    const float* fg   = (const float*)d_in[0];
    const float* hg   = (const float*)d_in[1];
    const float* qf   = (const float*)d_in[2];
    const float* hq   = (const float*)d_in[3];
    const float* w1   = (const float*)d_in[4];
    const float* b1   = (const float*)d_in[5];
    const float* w2   = (const float*)d_in[6];
    const float* b2   = (const float*)d_in[7];
    const float* w3   = (const float*)d_in[8];
    const float* b3   = (const float*)d_in[9];
    const float* w4   = (const float*)d_in[10];
    const float* b4   = (const float*)d_in[11];
    const float* occw = (const float*)d_in[12];
    const float* occb = (const float*)d_in[13];
    const float* miw  = (const float*)d_in[14];
    const float* mib  = (const float*)d_in[15];
    const float* mow  = (const float*)d_in[16];
    const float* mob  = (const float*)d_in[17];
    float* out = (float*)d_out;

    const int smem_head = (4224 + 10560 + 4096 + 4752 + 144 + 512 + 162) * 4;
    cudaFuncSetAttribute(k_head, cudaFuncAttributeMaxDynamicSharedMemorySize, smem_head);

    k_cv<<<dim3(32, 8), 256>>>(qf, fg, g_cv);
    k_fgavg<<<1024, 256>>>(fg, g_fgavg);
    k_head<<<NQ, 256, smem_head>>>(g_cv, hq, qf, w1, b1, w2, b2, w3, b3, w4, b4, occw, occb);

    for (int it = 0; it < 4; it++) {
        k_corr<<<NQ, 256>>>(hg, fg);
        k_gemm1<<<dim3(8, 16), 256>>>(miw, mib);
        k_gemm2<<<dim3(7, 16), 256>>>(mow, mob);
    }
    k_out<<<4, 256>>>(out);
}

// round 5
// speedup vs baseline: 2.2403x; 1.0641x over previous
#include <cuda_runtime.h>
#include <cuda_bf16.h>
#include <math.h>

#define NQ 1024
#define MI_STRIDE 544   // padded stride for mlp_in (535 real cols)

// ---------------- scratch (device globals; no allocation) ----------------
__device__ float g_cv[NQ * 4096];        // 16 MB
__device__ float g_pos[NQ * 2];
__device__ float g_occv[NQ];
__device__ float g_expd[NQ];
__device__ float g_feats[NQ * 384];
__device__ float g_fgavg[32 * 32 * 256]; // 1 MB
__device__ float g_mlpin[NQ * MI_STRIDE];
__device__ float g_hid[NQ * 512];

__device__ __forceinline__ float gelu_tanh(float x) {
    float x3 = x * x * x;
    return 0.5f * x * (1.f + tanhf(0.7978845608028654f * (x + 0.044715f * x3)));
}

__device__ __forceinline__ float tf32r(float x) {
    unsigned u;
    asm("cvt.rna.tf32.f32 %0, %1;" : "=r"(u) : "f"(x));
    return __uint_as_float(u);
}

__device__ __forceinline__ void mma_tf32(float& d0, float& d1, float& d2, float& d3,
                                         float a0, float a1, float a2, float a3,
                                         float b0, float b1) {
    asm("mma.sync.aligned.m16n8k8.row.col.f32.tf32.tf32.f32 "
        "{%0,%1,%2,%3},{%4,%5,%6,%7},{%8,%9},{%0,%1,%2,%3};"
        : "+f"(d0), "+f"(d1), "+f"(d2), "+f"(d3)
        : "r"(__float_as_uint(a0)), "r"(__float_as_uint(a1)),
          "r"(__float_as_uint(a2)), "r"(__float_as_uint(a3)),
          "r"(__float_as_uint(b0)), "r"(__float_as_uint(b1)));
}

__device__ __forceinline__ void mma_bf16(float& d0, float& d1, float& d2, float& d3,
                                         unsigned a0, unsigned a1, unsigned a2, unsigned a3,
                                         unsigned b0, unsigned b1) {
    asm("mma.sync.aligned.m16n8k16.row.col.f32.bf16.bf16.f32 "
        "{%0,%1,%2,%3},{%4,%5,%6,%7},{%8,%9},{%0,%1,%2,%3};"
        : "+f"(d0), "+f"(d1), "+f"(d2), "+f"(d3)
        : "r"(a0), "r"(a1), "r"(a2), "r"(a3), "r"(b0), "r"(b1));
}

// ---------------- cv = qf[1024,256] @ fg[4096,256]^T  (fp32, 128x128 tiles) ----------------
__global__ __launch_bounds__(256) void k_cv(const float* __restrict__ A,
                                            const float* __restrict__ B,
                                            float* __restrict__ C) {
    __shared__ float As[16][132];
    __shared__ float Bs[16][132];
    int n0 = blockIdx.x * 128, m0 = blockIdx.y * 128, t = threadIdx.x;
    int ty = t >> 4, tx = t & 15;
    float acc[8][8];
#pragma unroll
    for (int i = 0; i < 8; i++)
#pragma unroll
        for (int j = 0; j < 8; j++) acc[i][j] = 0.f;

    for (int k0 = 0; k0 < 256; k0 += 16) {
#pragma unroll
        for (int i = t; i < 512; i += 256) {
            int mm = i >> 2, k4 = (i & 3) * 4;
            float4 v = *(const float4*)&A[(m0 + mm) * 256 + k0 + k4];
            As[k4][mm] = v.x; As[k4 + 1][mm] = v.y; As[k4 + 2][mm] = v.z; As[k4 + 3][mm] = v.w;
            float4 u = *(const float4*)&B[(n0 + mm) * 256 + k0 + k4];
            Bs[k4][mm] = u.x; Bs[k4 + 1][mm] = u.y; Bs[k4 + 2][mm] = u.z; Bs[k4 + 3][mm] = u.w;
        }
        __syncthreads();
#pragma unroll
        for (int kk = 0; kk < 16; kk++) {
            float a[8], b[8];
            float4 a0 = *(const float4*)&As[kk][ty * 8];
            float4 a1 = *(const float4*)&As[kk][ty * 8 + 4];
            float4 b0 = *(const float4*)&Bs[kk][tx * 8];
            float4 b1 = *(const float4*)&Bs[kk][tx * 8 + 4];
            a[0] = a0.x; a[1] = a0.y; a[2] = a0.z; a[3] = a0.w;
            a[4] = a1.x; a[5] = a1.y; a[6] = a1.z; a[7] = a1.w;
            b[0] = b0.x; b[1] = b0.y; b[2] = b0.z; b[3] = b0.w;
            b[4] = b1.x; b[5] = b1.y; b[6] = b1.z; b[7] = b1.w;
#pragma unroll
            for (int i = 0; i < 8; i++)
#pragma unroll
                for (int j = 0; j < 8; j++) acc[i][j] = fmaf(a[i], b[j], acc[i][j]);
        }
        __syncthreads();
    }
#pragma unroll
    for (int i = 0; i < 8; i++) {
        float* cp = &C[(m0 + ty * 8 + i) * 4096 + n0 + tx * 8];
        *(float4*)cp = make_float4(acc[i][0], acc[i][1], acc[i][2], acc[i][3]);
        *(float4*)(cp + 4) = make_float4(acc[i][4], acc[i][5], acc[i][6], acc[i][7]);
    }
}

// ---------------- fg_avg (2x2 mean pool) ----------------
__global__ void k_fgavg(const float* __restrict__ fg, float* __restrict__ out) {
    int b = blockIdx.x;
    int y = b >> 5, x = b & 31, t = threadIdx.x;
    const float* p = fg + ((2 * y) * 64 + 2 * x) * 256;
    float v = p[t] + p[256 + t] + p[64 * 256 + t] + p[64 * 256 + 256 + t];
    out[(y * 32 + x) * 256 + t] = 0.25f * v;
}

// ---------------- per-query head ----------------
// padded layouts: s_cv 66x66 (zero border), s_occ stride 68, data at col offset 1
#define CV_S 66
#define OC_S 68
__global__ __launch_bounds__(256) void k_head(
    const float* __restrict__ cv_g, const float* __restrict__ hq, const float* __restrict__ qf,
    const float* __restrict__ w1, const float* __restrict__ b1,
    const float* __restrict__ w2, const float* __restrict__ b2,
    const float* __restrict__ w3, const float* __restrict__ b3,
    const float* __restrict__ w4, const float* __restrict__ b4,
    const float* __restrict__ occw, const float* __restrict__ occb) {
    extern __shared__ float sm[];
    float* s_cv   = sm;                       // 66*66 = 4356
    float* s_occ  = s_cv + 4356;              // 10*16*68 = 10880
    float* s_w3t  = s_occ + 10880;            // 144*36 = 5184 (permuted [k][g*4+nt])
    float* s_ko   = s_w3t + 5184;             // 144 (int offsets)
    float* s_w2   = s_ko + 144;               // 16*12 = 192
    float* s_w4   = s_w2 + 192;               // 512
    float* s_b3   = s_w4 + 512;               // 32
    float* s_b4   = s_b3 + 32;                // 16
    float* s_ow   = s_b4 + 16;                // 32
    float* s_ob   = s_ow + 32;                // 2
    float* s_red  = s_ob + 2;                 // 32
    float* s_o3   = s_red + 32;               // 32
    float* s_h4   = s_o3 + 32;                // 16
    int* s_koi = (int*)s_ko;

    int q = blockIdx.x, t = threadIdx.x;
    const float* cvq = cv_g + q * 4096;
    // cv with zero border
    for (int i = t; i < 4096; i += 256) s_cv[(1 + (i >> 6)) * CV_S + 1 + (i & 63)] = cvq[i];
    if (t < 66) { s_cv[t] = 0.f; s_cv[65 * CV_S + t] = 0.f; }
    if (t < 64) { s_cv[(t + 1) * CV_S] = 0.f; s_cv[(t + 1) * CV_S + 65] = 0.f; }
    // occ pad columns 0, 65..67
    for (int i = t; i < 160; i += 256) {
        float* rb = &s_occ[i * OC_S];
        rb[0] = 0.f; rb[65] = 0.f; rb[66] = 0.f; rb[67] = 0.f;
    }
    // weights
    for (int i = t; i < 144; i += 256) { int c = i / 9, k = i - c * 9; s_w2[c * 12 + k] = w2[i]; }
    for (int i = t; i < 4608; i += 256) {
        int oc = i / 144, k = i - oc * 144;
        s_w3t[k * 36 + (oc & 7) * 4 + (oc >> 3)] = tf32r(w3[i]);
    }
    for (int i = t; i < 144; i += 256) {
        int ic = i / 9, rk = i - ic * 9;
        int dy = rk / 3, dx = rk - dy * 3;
        s_koi[i] = (dy * 16 + ic) * OC_S + dx;
    }
    for (int i = t; i < 512; i += 256) s_w4[i] = w4[i];
    if (t < 32) s_b3[t] = b3[t];
    if (t < 16) s_b4[t] = b4[t];
    if (t < 32) s_ow[t] = occw[t];
    if (t < 2)  s_ob[t] = occb[t];
    if (t < 32) s_o3[t] = 0.f;
    for (int i = t; i < 128; i += 256) g_feats[q * 384 + i] = hq[q * 128 + i];
    for (int i = t; i < 256; i += 256) g_feats[q * 384 + 128 + i] = qf[q * 256 + i];
    float b2v = b2[0];

    // conv1 mapping: c1 (16) x xg (8) x sl2 (2); 8 cols, 5 slots per thread
    int c1 = t & 15, xg = (t >> 4) & 7, sl2 = t >> 7;
    int x0 = xg * 8;
    float w1r[9], b1r = b1[c1];
#pragma unroll
    for (int k = 0; k < 9; k++) w1r[k] = w1[c1 * 9 + k];

    // conv2 mapping
    int rr2 = t >> 6, x2 = t & 63;
    float pm[16];

    // conv3 mma mapping
    int wrp = t >> 5, lane = t & 31, qd = lane & 3, g = lane >> 2;
    int jrow3 = wrp >> 1;
    int col0 = (wrp & 1) * 16 + g;
    int base0 = (2 * jrow3 + 1) * (16 * OC_S) + 2 * col0 + 1;
    float macc[4][2];
#pragma unroll
    for (int nt = 0; nt < 4; nt++) { macc[nt][0] = 0.f; macc[nt][1] = 0.f; }

    __syncthreads();

    float b3n[4][2];
#pragma unroll
    for (int nt = 0; nt < 4; nt++) {
        b3n[nt][0] = s_b3[nt * 8 + qd * 2 + 0];
        b3n[nt][1] = s_b3[nt * 8 + qd * 2 + 1];
    }

    for (int r0 = 0; r0 < 64; r0 += 8) {
        // ---- conv1 + relu : fill occ band rows r0-1..r0+8 (padded, unconditional loads) ----
#pragma unroll
        for (int s = 0; s < 5; s++) {
            int slot = sl2 + 2 * s;
            int row = r0 - 1 + slot;
            float* dst = &s_occ[(slot * 16 + c1) * OC_S + 1 + x0];
            if (row < 0 || row > 63) {
#pragma unroll
                for (int j = 0; j < 8; j++) dst[j] = 0.f;
                continue;
            }
            float xv[3][10];
#pragma unroll
            for (int dy = 0; dy < 3; dy++) {
                const float* rp = &s_cv[(row + dy) * CV_S + x0];  // padded: row-1+dy+1, col x0-1+1
#pragma unroll
                for (int k = 0; k < 10; k++) xv[dy][k] = rp[k];
            }
#pragma unroll
            for (int j = 0; j < 8; j++) {
                float a = b1r;
#pragma unroll
                for (int dy = 0; dy < 3; dy++)
#pragma unroll
                    for (int dx = 0; dx < 3; dx++)
                        a = fmaf(w1r[dy * 3 + dx], xv[dy][j + dx], a);
                dst[j] = fmaxf(a, 0.f);
            }
        }
        __syncthreads();

        // ---- conv2 : rows r0+rr2 and r0+rr2+4 (unconditional via pad) ----
        {
            float a0 = b2v, a1 = b2v;
#pragma unroll
            for (int c = 0; c < 16; c++) {
                float4 wA = *(const float4*)&s_w2[c * 12];
                float4 wB = *(const float4*)&s_w2[c * 12 + 4];
                float w8 = s_w2[c * 12 + 8];
                float w[9] = {wA.x, wA.y, wA.z, wA.w, wB.x, wB.y, wB.z, wB.w, w8};
#pragma unroll
                for (int dy = 0; dy < 3; dy++) {
                    const float* p0 = &s_occ[((rr2 + dy) * 16 + c) * OC_S + x2];
                    const float* p1 = &s_occ[((rr2 + 4 + dy) * 16 + c) * OC_S + x2];
                    a0 = fmaf(w[dy * 3 + 0], p0[0], a0);
                    a0 = fmaf(w[dy * 3 + 1], p0[1], a0);
                    a0 = fmaf(w[dy * 3 + 2], p0[2], a0);
                    a1 = fmaf(w[dy * 3 + 0], p1[0], a1);
                    a1 = fmaf(w[dy * 3 + 1], p1[1], a1);
                    a1 = fmaf(w[dy * 3 + 2], p1[2], a1);
                }
            }
            pm[(r0 >> 3) * 2 + 0] = a0;
            pm[(r0 >> 3) * 2 + 1] = a1;
        }

        // ---- conv3 via tf32 mma: M=128, N=32, K=144 ----
        {
            float d[4][4];
#pragma unroll
            for (int nt = 0; nt < 4; nt++)
#pragma unroll
                for (int u = 0; u < 4; u++) d[nt][u] = 0.f;

#pragma unroll
            for (int st = 0; st < 18; st++) {
                int k0 = st * 8 + qd;
                int ko0 = s_koi[k0];
                int ko1 = s_koi[k0 + 4];
                float a0 = tf32r(s_occ[base0 + ko0]);
                float a1 = tf32r(s_occ[base0 + 16 + ko0]);
                float a2 = tf32r(s_occ[base0 + ko1]);
                float a3 = tf32r(s_occ[base0 + 16 + ko1]);
                float4 bv0 = *(const float4*)&s_w3t[k0 * 36 + g * 4];
                float4 bv1 = *(const float4*)&s_w3t[(k0 + 4) * 36 + g * 4];
                mma_tf32(d[0][0], d[0][1], d[0][2], d[0][3], a0, a1, a2, a3, bv0.x, bv1.x);
                mma_tf32(d[1][0], d[1][1], d[1][2], d[1][3], a0, a1, a2, a3, bv0.y, bv1.y);
                mma_tf32(d[2][0], d[2][1], d[2][2], d[2][3], a0, a1, a2, a3, bv0.z, bv1.z);
                mma_tf32(d[3][0], d[3][1], d[3][2], d[3][3], a0, a1, a2, a3, bv0.w, bv1.w);
            }
#pragma unroll
            for (int nt = 0; nt < 4; nt++) {
                macc[nt][0] += fmaxf(d[nt][0] + b3n[nt][0], 0.f) + fmaxf(d[nt][2] + b3n[nt][0], 0.f);
                macc[nt][1] += fmaxf(d[nt][1] + b3n[nt][1], 0.f) + fmaxf(d[nt][3] + b3n[nt][1], 0.f);
            }
        }
        __syncthreads();
    }

    // conv3 reduction into s_o3
#pragma unroll
    for (int nt = 0; nt < 4; nt++) {
#pragma unroll
        for (int j = 0; j < 2; j++) {
            float v = macc[nt][j];
#pragma unroll
            for (int o = 4; o <= 16; o <<= 1) v += __shfl_xor_sync(0xffffffffu, v, o);
            if (g == 0) atomicAdd(&s_o3[nt * 8 + qd * 2 + j], v);
        }
    }

    // softmax over pm (registers): rows 8b+rr2, 8b+rr2+4, col x2
    float lmax = pm[0];
#pragma unroll
    for (int u = 1; u < 16; u++) lmax = fmaxf(lmax, pm[u]);
#pragma unroll
    for (int o = 16; o; o >>= 1) lmax = fmaxf(lmax, __shfl_xor_sync(0xffffffffu, lmax, o));
    if ((t & 31) == 0) s_red[t >> 5] = lmax;
    __syncthreads();
    if (t == 0) {
        float m = s_red[0];
        for (int i = 1; i < 8; i++) m = fmaxf(m, s_red[i]);
        s_red[31] = m;
    }
    __syncthreads();
    float m = s_red[31];
    float se = 0.f, sy = 0.f;
#pragma unroll
    for (int u = 0; u < 16; u++) {
        float e = __expf((pm[u] - m) * 20.f);
        se += e;
        float row = (float)(8 * (u >> 1) + rr2 + 4 * (u & 1));
        sy = fmaf(e, row, sy);
    }
    float sx = se * (float)x2;
    __syncthreads();
#pragma unroll
    for (int o = 16; o; o >>= 1) {
        se += __shfl_xor_sync(0xffffffffu, se, o);
        sy += __shfl_xor_sync(0xffffffffu, sy, o);
        sx += __shfl_xor_sync(0xffffffffu, sx, o);
    }
    if ((t & 31) == 0) { int w = t >> 5; s_red[w] = se; s_red[8 + w] = sy; s_red[16 + w] = sx; }
    __syncthreads();
    if (t == 0) {
        float Se = 0, Sy = 0, Sx = 0;
        for (int i = 0; i < 8; i++) { Se += s_red[i]; Sy += s_red[8 + i]; Sx += s_red[16 + i]; }
        g_pos[q * 2 + 0] = (Sx / Se) * 8.f;
        g_pos[q * 2 + 1] = (Sy / Se) * 8.f;
    }
    __syncthreads();

    // head FCs
    if (t < 16) {
        float a = s_b4[t];
        for (int ic = 0; ic < 32; ic++) a = fmaf(s_o3[ic] * (1.f / 1024.f), s_w4[ic * 16 + t], a);
        s_h4[t] = fmaxf(a, 0.f);
    }
    __syncthreads();
    if (t == 0) {
        float o = s_ob[0], ex2 = s_ob[1];
        for (int k = 0; k < 16; k++) {
            o   = fmaf(s_h4[k], s_ow[k * 2 + 0], o);
            ex2 = fmaf(s_h4[k], s_ow[k * 2 + 1], ex2);
        }
        g_occv[q] = o;
        g_expd[q] = ex2;
    }
}

// ---------------- correlation + mlp_in assembly (per iteration) ----------------
__global__ __launch_bounds__(256) void k_corr(const float* __restrict__ hg,
                                              const float* __restrict__ fg) {
    __shared__ float s_q[384];
    __shared__ float s_D[64];
    int q = blockIdx.x, t = threadIdx.x;
    float px = g_pos[q * 2 + 0], py = g_pos[q * 2 + 1];
    for (int i = t; i < 384; i += 256) s_q[i] = g_feats[q * 384 + i];
    float* mi = g_mlpin + q * MI_STRIDE;
    if (t == 0) { mi[0] = 0.f; mi[1] = 0.f; mi[2] = g_occv[q]; mi[3] = g_expd[q]; }
    for (int i = t; i < 384; i += 256) mi[4 + i] = g_feats[q * 384 + i];
    __syncthreads();

    const float* Gs[3] = { hg, fg, g_fgavg };
    const int Hs[3] = { 128, 64, 32 };
    const int Cs[3] = { 128, 256, 256 };
    const int QO[3] = { 0, 128, 128 };

    int wrp = t >> 5, lane = t & 31;
#pragma unroll
    for (int l = 0; l < 3; l++) {
        const float* G = Gs[l];
        const int H = Hs[l], C = Cs[l], qo = QO[l];
        float sc = (float)H / 512.f;
        float gy = py * sc, gx = px * sc;
        float y0f = floorf(gy), x0f = floorf(gx);
        float wy = gy - y0f, wx = gx - x0f;
        int y0 = (int)y0f, x0 = (int)x0f;
        const float* sq = s_q + qo;

#pragma unroll
        for (int pp = 0; pp < 8; pp++) {
            int p = wrp + pp * 8;
            int ry = min(max(y0 + (p >> 3) - 3, 0), H - 1);
            int rx = min(max(x0 + (p & 7) - 3, 0), H - 1);
            const float* gp = G + (ry * H + rx) * C;
            float s0 = gp[lane] * sq[lane];
            float s1 = gp[lane + 32] * sq[lane + 32];
            float s2 = gp[lane + 64] * sq[lane + 64];
            float s3 = gp[lane + 96] * sq[lane + 96];
            if (C == 256) {
                s0 = fmaf(gp[lane + 128], sq[lane + 128], s0);
                s1 = fmaf(gp[lane + 160], sq[lane + 160], s1);
                s2 = fmaf(gp[lane + 192], sq[lane + 192], s2);
                s3 = fmaf(gp[lane + 224], sq[lane + 224], s3);
            }
            float s = (s0 + s1) + (s2 + s3);
#pragma unroll
            for (int o = 16; o; o >>= 1) s += __shfl_xor_sync(0xffffffffu, s, o);
            if (lane == 0) s_D[p] = s;
        }
        __syncthreads();
        if (t < 49) {
            int r = t / 7, c2 = t - r * 7;
            float d00 = s_D[r * 8 + c2],       d01 = s_D[r * 8 + c2 + 1];
            float d10 = s_D[(r + 1) * 8 + c2], d11 = s_D[(r + 1) * 8 + c2 + 1];
            float corr = (1.f - wy) * (1.f - wx) * d00 + (1.f - wy) * wx * d01
                       + wy * (1.f - wx) * d10 + wy * wx * d11;
            mi[388 + l * 49 + t] = corr;
        }
        __syncthreads();
    }
}

// ---------------- GEMM1: [1024,535]@[535,512] + bias, gelu  (bf16 mma) ----------------
__global__ __launch_bounds__(256) void k_gemm1(const float* __restrict__ B,
                                               const float* __restrict__ bias) {
    __shared__ __nv_bfloat16 As[64 * 36];
    __shared__ __nv_bfloat16 Bs[64 * 36];
    int n0 = blockIdx.x * 64, m0 = blockIdx.y * 64, t = threadIdx.x;
    int w = t >> 5, lane = t & 31, qd = lane & 3, g = lane >> 2;
    int wm = (w >> 2) * 32, wn = (w & 3) * 16;
    float acc[2][2][4];
#pragma unroll
    for (int mt = 0; mt < 2; mt++)
#pragma unroll
        for (int nt = 0; nt < 2; nt++)
#pragma unroll
            for (int u = 0; u < 4; u++) acc[mt][nt][u] = 0.f;

    for (int k0 = 0; k0 < 544; k0 += 32) {
#pragma unroll
        for (int i = t; i < 2048; i += 256) {
            int mm = i >> 5, kk = i & 31, k = k0 + kk;
            float v = (k < 535) ? g_mlpin[(m0 + mm) * MI_STRIDE + k] : 0.f;
            As[mm * 36 + kk] = __float2bfloat16(v);
        }
#pragma unroll
        for (int i = t; i < 2048; i += 256) {
            int kk = i >> 6, nn = i & 63, k = k0 + kk;
            float v = (k < 535) ? B[k * 512 + n0 + nn] : 0.f;
            Bs[nn * 36 + kk] = __float2bfloat16(v);
        }
        __syncthreads();
#pragma unroll
        for (int s = 0; s < 2; s++) {
            unsigned a[2][4], b[2][2];
#pragma unroll
            for (int mt = 0; mt < 2; mt++) {
                int row = wm + mt * 16 + g;
                a[mt][0] = *(const unsigned*)&As[row * 36 + s * 16 + 2 * qd];
                a[mt][1] = *(const unsigned*)&As[(row + 8) * 36 + s * 16 + 2 * qd];
                a[mt][2] = *(const unsigned*)&As[row * 36 + s * 16 + 2 * qd + 8];
                a[mt][3] = *(const unsigned*)&As[(row + 8) * 36 + s * 16 + 2 * qd + 8];
            }
#pragma unroll
            for (int nt = 0; nt < 2; nt++) {
                int bn = wn + nt * 8 + g;
                b[nt][0] = *(const unsigned*)&Bs[bn * 36 + s * 16 + 2 * qd];
                b[nt][1] = *(const unsigned*)&Bs[bn * 36 + s * 16 + 2 * qd + 8];
            }
#pragma unroll
            for (int mt = 0; mt < 2; mt++)
#pragma unroll
                for (int nt = 0; nt < 2; nt++)
                    mma_bf16(acc[mt][nt][0], acc[mt][nt][1], acc[mt][nt][2], acc[mt][nt][3],
                             a[mt][0], a[mt][1], a[mt][2], a[mt][3], b[nt][0], b[nt][1]);
        }
        __syncthreads();
    }
#pragma unroll
    for (int mt = 0; mt < 2; mt++)
#pragma unroll
        for (int nt = 0; nt < 2; nt++) {
            int mg = m0 + wm + mt * 16 + g;
            int ng = n0 + wn + nt * 8 + qd * 2;
            float bz0 = bias[ng], bz1 = bias[ng + 1];
            float2 v0 = make_float2(gelu_tanh(acc[mt][nt][0] + bz0), gelu_tanh(acc[mt][nt][1] + bz1));
            float2 v1 = make_float2(gelu_tanh(acc[mt][nt][2] + bz0), gelu_tanh(acc[mt][nt][3] + bz1));
            *(float2*)&g_hid[mg * 512 + ng] = v0;
            *(float2*)&g_hid[(mg + 8) * 512 + ng] = v1;
        }
}

// ---------------- GEMM2: [1024,512]@[512,388] + bias, state update (bf16 mma) ----------------
__global__ __launch_bounds__(256) void k_gemm2(const float* __restrict__ B,
                                               const float* __restrict__ bias) {
    __shared__ __nv_bfloat16 As[64 * 36];
    __shared__ __nv_bfloat16 Bs[64 * 36];
    int n0 = blockIdx.x * 64, m0 = blockIdx.y * 64, t = threadIdx.x;
    int w = t >> 5, lane = t & 31, qd = lane & 3, g = lane >> 2;
    int wm = (w >> 2) * 32, wn = (w & 3) * 16;
    float acc[2][2][4];
#pragma unroll
    for (int mt = 0; mt < 2; mt++)
#pragma unroll
        for (int nt = 0; nt < 2; nt++)
#pragma unroll
            for (int u = 0; u < 4; u++) acc[mt][nt][u] = 0.f;

    for (int k0 = 0; k0 < 512; k0 += 32) {
#pragma unroll
        for (int i = t; i < 2048; i += 256) {
            int mm = i >> 5, kk = i & 31;
            As[mm * 36 + kk] = __float2bfloat16(g_hid[(m0 + mm) * 512 + k0 + kk]);
        }
#pragma unroll
        for (int i = t; i < 2048; i += 256) {
            int kk = i >> 6, nn = i & 63, n = n0 + nn;
            float v = (n < 388) ? B[(k0 + kk) * 388 + n] : 0.f;
            Bs[nn * 36 + kk] = __float2bfloat16(v);
        }
        __syncthreads();
#pragma unroll
        for (int s = 0; s < 2; s++) {
            unsigned a[2][4], b[2][2];
#pragma unroll
            for (int mt = 0; mt < 2; mt++) {
                int row = wm + mt * 16 + g;
                a[mt][0] = *(const unsigned*)&As[row * 36 + s * 16 + 2 * qd];
                a[mt][1] = *(const unsigned*)&As[(row + 8) * 36 + s * 16 + 2 * qd];
                a[mt][2] = *(const unsigned*)&As[row * 36 + s * 16 + 2 * qd + 8];
                a[mt][3] = *(const unsigned*)&As[(row + 8) * 36 + s * 16 + 2 * qd + 8];
            }
#pragma unroll
            for (int nt = 0; nt < 2; nt++) {
                int bn = wn + nt * 8 + g;
                b[nt][0] = *(const unsigned*)&Bs[bn * 36 + s * 16 + 2 * qd];
                b[nt][1] = *(const unsigned*)&Bs[bn * 36 + s * 16 + 2 * qd + 8];
            }
#pragma unroll
            for (int mt = 0; mt < 2; mt++)
#pragma unroll
                for (int nt = 0; nt < 2; nt++)
                    mma_bf16(acc[mt][nt][0], acc[mt][nt][1], acc[mt][nt][2], acc[mt][nt][3],
                             a[mt][0], a[mt][1], a[mt][2], a[mt][3], b[nt][0], b[nt][1]);
        }
        __syncthreads();
    }
#pragma unroll
    for (int mt = 0; mt < 2; mt++)
#pragma unroll
        for (int nt = 0; nt < 2; nt++) {
#pragma unroll
            for (int rr = 0; rr < 2; rr++) {
                int mg = m0 + wm + mt * 16 + g + rr * 8;
#pragma unroll
                for (int jj = 0; jj < 2; jj++) {
                    int ng = n0 + wn + nt * 8 + qd * 2 + jj;
                    if (ng < 388) {
                        float v = acc[mt][nt][rr * 2 + jj] + bias[ng];
                        if (ng < 2)       g_pos[mg * 2 + ng] += v;
                        else if (ng == 2) g_occv[mg] += v;
                        else if (ng == 3) g_expd[mg] += v;
                        else              g_feats[mg * 384 + ng - 4] += v;
                    }
                }
            }
        }
}

// ---------------- pack output ----------------
__global__ void k_out(float* __restrict__ out) {
    int i = blockIdx.x * blockDim.x + threadIdx.x;
    if (i < NQ) {
        out[i * 4 + 0] = g_pos[i * 2 + 0];
        out[i * 4 + 1] = g_pos[i * 2 + 1];
        out[i * 4 + 2] = g_occv[i];
        out[i * 4 + 3] = g_expd[i];
    }
}

// ---------------- launch ----------------
extern "C" void kernel_launch(void* const* d_in, const int* in_sizes, int n_in,
                              void* d_out, int out_size) {
    const float* fg   = (const float*)d_in[0];
    const float* hg   = (const float*)d_in[1];
    const float* qf   = (const float*)d_in[2];
    const float* hq   = (const float*)d_in[3];
    const float* w1   = (const float*)d_in[4];
    const float* b1   = (const float*)d_in[5];
    const float* w2   = (const float*)d_in[6];
    const float* b2   = (const float*)d_in[7];
    const float* w3   = (const float*)d_in[8];
    const float* b3   = (const float*)d_in[9];
    const float* w4   = (const float*)d_in[10];
    const float* b4   = (const float*)d_in[11];
    const float* occw = (const float*)d_in[12];
    const float* occb = (const float*)d_in[13];
    const float* miw  = (const float*)d_in[14];
    const float* mib  = (const float*)d_in[15];
    const float* mow  = (const float*)d_in[16];
    const float* mob  = (const float*)d_in[17];
    float* out = (float*)d_out;

    // 4356 + 10880 + 5184 + 144 + 192 + 512 + 32 + 16 + 32 + 2 + 32 + 32 + 16 = 21430 floats
    const int smem_head = 21430 * 4;
    cudaFuncSetAttribute(k_head, cudaFuncAttributeMaxDynamicSharedMemorySize, smem_head);

    k_cv<<<dim3(32, 8), 256>>>(qf, fg, g_cv);
    k_fgavg<<<1024, 256>>>(fg, g_fgavg);
    k_head<<<NQ, 256, smem_head>>>(g_cv, hq, qf, w1, b1, w2, b2, w3, b3, w4, b4, occw, occb);

    for (int it = 0; it < 4; it++) {
        k_corr<<<NQ, 256>>>(hg, fg);
        k_gemm1<<<dim3(8, 16), 256>>>(miw, mib);
        k_gemm2<<<dim3(7, 16), 256>>>(mow, mob);
    }
    k_out<<<4, 256>>>(out);
}

// round 6
// speedup vs baseline: 2.5870x; 1.1547x over previous
#include <cuda_runtime.h>
#include <cuda_bf16.h>
#include <math.h>

#define NQ 1024
#define MI_STRIDE 544   // padded stride for mlp_in (535 real cols)

// ---------------- scratch (device globals; no allocation) ----------------
__device__ float g_cv[NQ * 4096];        // 16 MB
__device__ float g_pos[NQ * 2];
__device__ float g_occv[NQ];
__device__ float g_expd[NQ];
__device__ float g_feats[NQ * 384];
__device__ float g_fgavg[32 * 32 * 256]; // 1 MB
__device__ float g_mlpin[NQ * MI_STRIDE];
__device__ float g_hid[NQ * 512];

__device__ __forceinline__ float gelu_tanh(float x) {
    float x3 = x * x * x;
    return 0.5f * x * (1.f + tanhf(0.7978845608028654f * (x + 0.044715f * x3)));
}

__device__ __forceinline__ float tf32r(float x) {
    unsigned u;
    asm("cvt.rna.tf32.f32 %0, %1;" : "=r"(u) : "f"(x));
    return __uint_as_float(u);
}

__device__ __forceinline__ unsigned packbf(float lo, float hi) {
    __nv_bfloat162 v = __floats2bfloat162_rn(lo, hi);
    return *(unsigned*)&v;
}

__device__ __forceinline__ void mma_tf32(float& d0, float& d1, float& d2, float& d3,
                                         float a0, float a1, float a2, float a3,
                                         float b0, float b1) {
    asm("mma.sync.aligned.m16n8k8.row.col.f32.tf32.tf32.f32 "
        "{%0,%1,%2,%3},{%4,%5,%6,%7},{%8,%9},{%0,%1,%2,%3};"
        : "+f"(d0), "+f"(d1), "+f"(d2), "+f"(d3)
        : "r"(__float_as_uint(a0)), "r"(__float_as_uint(a1)),
          "r"(__float_as_uint(a2)), "r"(__float_as_uint(a3)),
          "r"(__float_as_uint(b0)), "r"(__float_as_uint(b1)));
}

__device__ __forceinline__ void mma_bf16(float& d0, float& d1, float& d2, float& d3,
                                         unsigned a0, unsigned a1, unsigned a2, unsigned a3,
                                         unsigned b0, unsigned b1) {
    asm("mma.sync.aligned.m16n8k16.row.col.f32.bf16.bf16.f32 "
        "{%0,%1,%2,%3},{%4,%5,%6,%7},{%8,%9},{%0,%1,%2,%3};"
        : "+f"(d0), "+f"(d1), "+f"(d2), "+f"(d3)
        : "r"(a0), "r"(a1), "r"(a2), "r"(a3), "r"(b0), "r"(b1));
}

// ---------------- cv = qf[1024,256] @ fg[4096,256]^T  (tf32 mma) ----------------
__global__ __launch_bounds__(256) void k_cv(const float* __restrict__ A,
                                            const float* __restrict__ B,
                                            float* __restrict__ C) {
    __shared__ float As[64 * 17];
    __shared__ float Bs[16 * 73];
    int n0 = blockIdx.x * 64, m0 = blockIdx.y * 64, t = threadIdx.x;
    int w = t >> 5, lane = t & 31, qd = lane & 3, g = lane >> 2;
    int wm = (w >> 2) * 32, wn = (w & 3) * 16;
    int mm = t >> 2, k4 = (t & 3) * 4;
    float acc[2][2][4];
#pragma unroll
    for (int mt = 0; mt < 2; mt++)
#pragma unroll
        for (int nt = 0; nt < 2; nt++)
#pragma unroll
            for (int u = 0; u < 4; u++) acc[mt][nt][u] = 0.f;

    for (int k0 = 0; k0 < 256; k0 += 16) {
        float4 va = *(const float4*)&A[(m0 + mm) * 256 + k0 + k4];
        As[mm * 17 + k4 + 0] = tf32r(va.x);
        As[mm * 17 + k4 + 1] = tf32r(va.y);
        As[mm * 17 + k4 + 2] = tf32r(va.z);
        As[mm * 17 + k4 + 3] = tf32r(va.w);
        float4 vb = *(const float4*)&B[(n0 + mm) * 256 + k0 + k4];
        Bs[(k4 + 0) * 73 + mm] = tf32r(vb.x);
        Bs[(k4 + 1) * 73 + mm] = tf32r(vb.y);
        Bs[(k4 + 2) * 73 + mm] = tf32r(vb.z);
        Bs[(k4 + 3) * 73 + mm] = tf32r(vb.w);
        __syncthreads();
#pragma unroll
        for (int s = 0; s < 2; s++) {
            float a[2][4], b[2][2];
#pragma unroll
            for (int mt = 0; mt < 2; mt++) {
                int row = wm + mt * 16 + g;
                a[mt][0] = As[row * 17 + s * 8 + qd];
                a[mt][1] = As[(row + 8) * 17 + s * 8 + qd];
                a[mt][2] = As[row * 17 + s * 8 + qd + 4];
                a[mt][3] = As[(row + 8) * 17 + s * 8 + qd + 4];
            }
#pragma unroll
            for (int nt = 0; nt < 2; nt++) {
                int bn = wn + nt * 8 + g;
                b[nt][0] = Bs[(s * 8 + qd) * 73 + bn];
                b[nt][1] = Bs[(s * 8 + qd + 4) * 73 + bn];
            }
#pragma unroll
            for (int mt = 0; mt < 2; mt++)
#pragma unroll
                for (int nt = 0; nt < 2; nt++)
                    mma_tf32(acc[mt][nt][0], acc[mt][nt][1], acc[mt][nt][2], acc[mt][nt][3],
                             a[mt][0], a[mt][1], a[mt][2], a[mt][3], b[nt][0], b[nt][1]);
        }
        __syncthreads();
    }
#pragma unroll
    for (int mt = 0; mt < 2; mt++)
#pragma unroll
        for (int nt = 0; nt < 2; nt++) {
            int mg = m0 + wm + mt * 16 + g;
            int ng = n0 + wn + nt * 8 + qd * 2;
            *(float2*)&C[mg * 4096 + ng] = make_float2(acc[mt][nt][0], acc[mt][nt][1]);
            *(float2*)&C[(mg + 8) * 4096 + ng] = make_float2(acc[mt][nt][2], acc[mt][nt][3]);
        }
}

// ---------------- fg_avg (2x2 mean pool) ----------------
__global__ void k_fgavg(const float* __restrict__ fg, float* __restrict__ out) {
    int b = blockIdx.x;
    int y = b >> 5, x = b & 31, t = threadIdx.x;
    const float* p = fg + ((2 * y) * 64 + 2 * x) * 256;
    float v = p[t] + p[256 + t] + p[64 * 256 + t] + p[64 * 256 + 256 + t];
    out[(y * 32 + x) * 256 + t] = 0.25f * v;
}

// ---------------- per-query head ----------------
// padded layouts: s_cv 66x66 (zero border), s_occ stride 66, data at col offset 1
#define CV_S 66
#define OC_S 66
__global__ __launch_bounds__(256, 3) void k_head(
    const float* __restrict__ cv_g, const float* __restrict__ hq, const float* __restrict__ qf,
    const float* __restrict__ w1, const float* __restrict__ b1,
    const float* __restrict__ w2, const float* __restrict__ b2,
    const float* __restrict__ w3, const float* __restrict__ b3,
    const float* __restrict__ w4, const float* __restrict__ b4,
    const float* __restrict__ occw, const float* __restrict__ occb) {
    extern __shared__ float sm[];
    float* s_cv   = sm;                       // 66*66 = 4356
    float* s_occ  = s_cv + 4356;              // 10*16*66 = 10560
    unsigned* s_w3b = (unsigned*)(s_occ + 10560); // 72*33 = 2376 (bf16x2 pairs [k/2][oc])
    float* s_ko   = (float*)(s_w3b + 2376);   // 144 (int offsets)
    float* s_w2   = s_ko + 144;               // 16*12 = 192
    float* s_w4   = s_w2 + 192;               // 512
    float* s_b3   = s_w4 + 512;               // 32
    float* s_b4   = s_b3 + 32;                // 16
    float* s_ow   = s_b4 + 16;                // 32
    float* s_ob   = s_ow + 32;                // 2
    float* s_red  = s_ob + 2;                 // 32
    float* s_o3   = s_red + 32;               // 32
    float* s_h4   = s_o3 + 32;                // 16
    int* s_koi = (int*)s_ko;

    int q = blockIdx.x, t = threadIdx.x;
    const float* cvq = cv_g + q * 4096;
    // cv with zero border
    for (int i = t; i < 4096; i += 256) s_cv[(1 + (i >> 6)) * CV_S + 1 + (i & 63)] = cvq[i];
    if (t < 66) { s_cv[t] = 0.f; s_cv[65 * CV_S + t] = 0.f; }
    if (t < 64) { s_cv[(t + 1) * CV_S] = 0.f; s_cv[(t + 1) * CV_S + 65] = 0.f; }
    // occ pad columns 0, 65
    for (int i = t; i < 160; i += 256) {
        float* rb = &s_occ[i * OC_S];
        rb[0] = 0.f; rb[65] = 0.f;
    }
    // weights
    for (int i = t; i < 144; i += 256) { int c = i / 9, k = i - c * 9; s_w2[c * 12 + k] = w2[i]; }
    for (int i = t; i < 72 * 32; i += 256) {
        int krow = i >> 5, oc = i & 31;
        int k = krow * 2;
        s_w3b[krow * 33 + oc] = packbf(w3[oc * 144 + k], w3[oc * 144 + k + 1]);
    }
    for (int i = t; i < 144; i += 256) {
        int ic = i / 9, rk = i - ic * 9;
        int dy = rk / 3, dx = rk - dy * 3;
        s_koi[i] = (dy * 16 + ic) * OC_S + dx;
    }
    for (int i = t; i < 512; i += 256) s_w4[i] = w4[i];
    if (t < 32) s_b3[t] = b3[t];
    if (t < 16) s_b4[t] = b4[t];
    if (t < 32) s_ow[t] = occw[t];
    if (t < 2)  s_ob[t] = occb[t];
    if (t < 32) s_o3[t] = 0.f;
    for (int i = t; i < 128; i += 256) g_feats[q * 384 + i] = hq[q * 128 + i];
    for (int i = t; i < 256; i += 256) g_feats[q * 384 + 128 + i] = qf[q * 256 + i];
    float b2v = b2[0];

    // conv1 mapping: c1 (16) x xg (8) x sl2 (2); 8 cols, 5 slots per thread
    int c1 = t & 15, xg = (t >> 4) & 7, sl2 = t >> 7;
    int x0 = xg * 8;
    float w1r[9], b1r = b1[c1];
#pragma unroll
    for (int k = 0; k < 9; k++) w1r[k] = w1[c1 * 9 + k];

    // conv2 mapping
    int rr2 = t >> 6, x2 = t & 63;
    float pm[16];

    // conv3 mma mapping
    int wrp = t >> 5, lane = t & 31, qd = lane & 3, g = lane >> 2;
    int jrow3 = wrp >> 1;
    int col0 = (wrp & 1) * 16 + g;
    int base0 = (2 * jrow3 + 1) * (16 * OC_S) + 2 * col0 + 1;
    float macc[4][2];
#pragma unroll
    for (int nt = 0; nt < 4; nt++) { macc[nt][0] = 0.f; macc[nt][1] = 0.f; }

    __syncthreads();

    float b3n[4][2];
#pragma unroll
    for (int nt = 0; nt < 4; nt++) {
        b3n[nt][0] = s_b3[nt * 8 + qd * 2 + 0];
        b3n[nt][1] = s_b3[nt * 8 + qd * 2 + 1];
    }

    for (int r0 = 0; r0 < 64; r0 += 8) {
        // ---- conv1 + relu : fill occ band rows r0-1..r0+8 (padded, unconditional loads) ----
#pragma unroll
        for (int s = 0; s < 5; s++) {
            int slot = sl2 + 2 * s;
            int row = r0 - 1 + slot;
            float* dst = &s_occ[(slot * 16 + c1) * OC_S + 1 + x0];
            if (row < 0 || row > 63) {
#pragma unroll
                for (int j = 0; j < 8; j++) dst[j] = 0.f;
                continue;
            }
            float xv[3][10];
#pragma unroll
            for (int dy = 0; dy < 3; dy++) {
                const float* rp = &s_cv[(row + dy) * CV_S + x0];
#pragma unroll
                for (int k = 0; k < 10; k++) xv[dy][k] = rp[k];
            }
#pragma unroll
            for (int j = 0; j < 8; j++) {
                float a = b1r;
#pragma unroll
                for (int dy = 0; dy < 3; dy++)
#pragma unroll
                    for (int dx = 0; dx < 3; dx++)
                        a = fmaf(w1r[dy * 3 + dx], xv[dy][j + dx], a);
                dst[j] = fmaxf(a, 0.f);
            }
        }
        __syncthreads();

        // ---- conv2 : rows r0+rr2 and r0+rr2+4 (unconditional via pad) ----
        {
            float a0 = b2v, a1 = b2v;
#pragma unroll
            for (int c = 0; c < 16; c++) {
                float4 wA = *(const float4*)&s_w2[c * 12];
                float4 wB = *(const float4*)&s_w2[c * 12 + 4];
                float w8 = s_w2[c * 12 + 8];
                float w[9] = {wA.x, wA.y, wA.z, wA.w, wB.x, wB.y, wB.z, wB.w, w8};
#pragma unroll
                for (int dy = 0; dy < 3; dy++) {
                    const float* p0 = &s_occ[((rr2 + dy) * 16 + c) * OC_S + x2];
                    const float* p1 = &s_occ[((rr2 + 4 + dy) * 16 + c) * OC_S + x2];
                    a0 = fmaf(w[dy * 3 + 0], p0[0], a0);
                    a0 = fmaf(w[dy * 3 + 1], p0[1], a0);
                    a0 = fmaf(w[dy * 3 + 2], p0[2], a0);
                    a1 = fmaf(w[dy * 3 + 0], p1[0], a1);
                    a1 = fmaf(w[dy * 3 + 1], p1[1], a1);
                    a1 = fmaf(w[dy * 3 + 2], p1[2], a1);
                }
            }
            pm[(r0 >> 3) * 2 + 0] = a0;
            pm[(r0 >> 3) * 2 + 1] = a1;
        }

        // ---- conv3 via bf16 mma (k16): M=128, N=32, K=144 (9 steps) ----
        {
            float d[4][4];
#pragma unroll
            for (int nt = 0; nt < 4; nt++)
#pragma unroll
                for (int u = 0; u < 4; u++) d[nt][u] = 0.f;

#pragma unroll
            for (int st = 0; st < 9; st++) {
                int kE = st * 16 + 2 * qd;
                int kO = kE + 8;
                int e0 = s_koi[kE], e1 = s_koi[kE + 1];
                int o0 = s_koi[kO], o1 = s_koi[kO + 1];
                unsigned a0 = packbf(s_occ[base0 + e0],      s_occ[base0 + e1]);
                unsigned a1 = packbf(s_occ[base0 + 16 + e0], s_occ[base0 + 16 + e1]);
                unsigned a2 = packbf(s_occ[base0 + o0],      s_occ[base0 + o1]);
                unsigned a3 = packbf(s_occ[base0 + 16 + o0], s_occ[base0 + 16 + o1]);
                int kr = st * 8 + qd;
                const unsigned* bp0 = &s_w3b[kr * 33];
                const unsigned* bp1 = &s_w3b[(kr + 4) * 33];
#pragma unroll
                for (int nt = 0; nt < 4; nt++) {
                    unsigned b0 = bp0[nt * 8 + g];
                    unsigned b1 = bp1[nt * 8 + g];
                    mma_bf16(d[nt][0], d[nt][1], d[nt][2], d[nt][3], a0, a1, a2, a3, b0, b1);
                }
            }
#pragma unroll
            for (int nt = 0; nt < 4; nt++) {
                macc[nt][0] += fmaxf(d[nt][0] + b3n[nt][0], 0.f) + fmaxf(d[nt][2] + b3n[nt][0], 0.f);
                macc[nt][1] += fmaxf(d[nt][1] + b3n[nt][1], 0.f) + fmaxf(d[nt][3] + b3n[nt][1], 0.f);
            }
        }
        __syncthreads();
    }

    // conv3 reduction into s_o3
#pragma unroll
    for (int nt = 0; nt < 4; nt++) {
#pragma unroll
        for (int j = 0; j < 2; j++) {
            float v = macc[nt][j];
#pragma unroll
            for (int o = 4; o <= 16; o <<= 1) v += __shfl_xor_sync(0xffffffffu, v, o);
            if (g == 0) atomicAdd(&s_o3[nt * 8 + qd * 2 + j], v);
        }
    }

    // softmax over pm (registers)
    float lmax = pm[0];
#pragma unroll
    for (int u = 1; u < 16; u++) lmax = fmaxf(lmax, pm[u]);
#pragma unroll
    for (int o = 16; o; o >>= 1) lmax = fmaxf(lmax, __shfl_xor_sync(0xffffffffu, lmax, o));
    if ((t & 31) == 0) s_red[t >> 5] = lmax;
    __syncthreads();
    if (t == 0) {
        float m = s_red[0];
        for (int i = 1; i < 8; i++) m = fmaxf(m, s_red[i]);
        s_red[31] = m;
    }
    __syncthreads();
    float m = s_red[31];
    float se = 0.f, sy = 0.f;
#pragma unroll
    for (int u = 0; u < 16; u++) {
        float e = __expf((pm[u] - m) * 20.f);
        se += e;
        float row = (float)(8 * (u >> 1) + rr2 + 4 * (u & 1));
        sy = fmaf(e, row, sy);
    }
    float sx = se * (float)x2;
    __syncthreads();
#pragma unroll
    for (int o = 16; o; o >>= 1) {
        se += __shfl_xor_sync(0xffffffffu, se, o);
        sy += __shfl_xor_sync(0xffffffffu, sy, o);
        sx += __shfl_xor_sync(0xffffffffu, sx, o);
    }
    if ((t & 31) == 0) { int w = t >> 5; s_red[w] = se; s_red[8 + w] = sy; s_red[16 + w] = sx; }
    __syncthreads();
    if (t == 0) {
        float Se = 0, Sy = 0, Sx = 0;
        for (int i = 0; i < 8; i++) { Se += s_red[i]; Sy += s_red[8 + i]; Sx += s_red[16 + i]; }
        g_pos[q * 2 + 0] = (Sx / Se) * 8.f;
        g_pos[q * 2 + 1] = (Sy / Se) * 8.f;
    }
    __syncthreads();

    // head FCs
    if (t < 16) {
        float a = s_b4[t];
        for (int ic = 0; ic < 32; ic++) a = fmaf(s_o3[ic] * (1.f / 1024.f), s_w4[ic * 16 + t], a);
        s_h4[t] = fmaxf(a, 0.f);
    }
    __syncthreads();
    if (t == 0) {
        float o = s_ob[0], ex2 = s_ob[1];
        for (int k = 0; k < 16; k++) {
            o   = fmaf(s_h4[k], s_ow[k * 2 + 0], o);
            ex2 = fmaf(s_h4[k], s_ow[k * 2 + 1], ex2);
        }
        g_occv[q] = o;
        g_expd[q] = ex2;
    }
}

// ---------------- correlation + mlp_in assembly (per iteration) ----------------
__global__ __launch_bounds__(256) void k_corr(const float* __restrict__ hg,
                                              const float* __restrict__ fg) {
    __shared__ float s_q[384];
    __shared__ float s_D[64];
    int q = blockIdx.x, t = threadIdx.x;
    float px = g_pos[q * 2 + 0], py = g_pos[q * 2 + 1];
    for (int i = t; i < 384; i += 256) s_q[i] = g_feats[q * 384 + i];
    float* mi = g_mlpin + q * MI_STRIDE;
    if (t == 0) { mi[0] = 0.f; mi[1] = 0.f; mi[2] = g_occv[q]; mi[3] = g_expd[q]; }
    for (int i = t; i < 384; i += 256) mi[4 + i] = g_feats[q * 384 + i];
    __syncthreads();

    const float* Gs[3] = { hg, fg, g_fgavg };
    const int Hs[3] = { 128, 64, 32 };
    const int Cs[3] = { 128, 256, 256 };
    const int QO[3] = { 0, 128, 128 };

    int wrp = t >> 5, lane = t & 31;
#pragma unroll
    for (int l = 0; l < 3; l++) {
        const float* G = Gs[l];
        const int H = Hs[l], C = Cs[l], qo = QO[l];
        float sc = (float)H / 512.f;
        float gy = py * sc, gx = px * sc;
        float y0f = floorf(gy), x0f = floorf(gx);
        float wy = gy - y0f, wx = gx - x0f;
        int y0 = (int)y0f, x0 = (int)x0f;
        const float* sq = s_q + qo;

#pragma unroll
        for (int pp = 0; pp < 8; pp++) {
            int p = wrp + pp * 8;
            int ry = min(max(y0 + (p >> 3) - 3, 0), H - 1);
            int rx = min(max(x0 + (p & 7) - 3, 0), H - 1);
            const float* gp = G + (ry * H + rx) * C;
            float s0 = gp[lane] * sq[lane];
            float s1 = gp[lane + 32] * sq[lane + 32];
            float s2 = gp[lane + 64] * sq[lane + 64];
            float s3 = gp[lane + 96] * sq[lane + 96];
            if (C == 256) {
                s0 = fmaf(gp[lane + 128], sq[lane + 128], s0);
                s1 = fmaf(gp[lane + 160], sq[lane + 160], s1);
                s2 = fmaf(gp[lane + 192], sq[lane + 192], s2);
                s3 = fmaf(gp[lane + 224], sq[lane + 224], s3);
            }
            float s = (s0 + s1) + (s2 + s3);
#pragma unroll
            for (int o = 16; o; o >>= 1) s += __shfl_xor_sync(0xffffffffu, s, o);
            if (lane == 0) s_D[p] = s;
        }
        __syncthreads();
        if (t < 49) {
            int r = t / 7, c2 = t - r * 7;
            float d00 = s_D[r * 8 + c2],       d01 = s_D[r * 8 + c2 + 1];
            float d10 = s_D[(r + 1) * 8 + c2], d11 = s_D[(r + 1) * 8 + c2 + 1];
            float corr = (1.f - wy) * (1.f - wx) * d00 + (1.f - wy) * wx * d01
                       + wy * (1.f - wx) * d10 + wy * wx * d11;
            mi[388 + l * 49 + t] = corr;
        }
        __syncthreads();
    }
}

// ---------------- GEMM1: [1024,535]@[535,512] + bias, gelu  (bf16 mma) ----------------
__global__ __launch_bounds__(256) void k_gemm1(const float* __restrict__ B,
                                               const float* __restrict__ bias) {
    __shared__ __nv_bfloat16 As[64 * 36];
    __shared__ __nv_bfloat16 Bs[64 * 36];
    int n0 = blockIdx.x * 64, m0 = blockIdx.y * 64, t = threadIdx.x;
    int w = t >> 5, lane = t & 31, qd = lane & 3, g = lane >> 2;
    int wm = (w >> 2) * 32, wn = (w & 3) * 16;
    float acc[2][2][4];
#pragma unroll
    for (int mt = 0; mt < 2; mt++)
#pragma unroll
        for (int nt = 0; nt < 2; nt++)
#pragma unroll
            for (int u = 0; u < 4; u++) acc[mt][nt][u] = 0.f;

    for (int k0 = 0; k0 < 544; k0 += 32) {
#pragma unroll
        for (int i = t; i < 2048; i += 256) {
            int mm = i >> 5, kk = i & 31, k = k0 + kk;
            float v = (k < 535) ? g_mlpin[(m0 + mm) * MI_STRIDE + k] : 0.f;
            As[mm * 36 + kk] = __float2bfloat16(v);
        }
#pragma unroll
        for (int i = t; i < 2048; i += 256) {
            int kk = i >> 6, nn = i & 63, k = k0 + kk;
            float v = (k < 535) ? B[k * 512 + n0 + nn] : 0.f;
            Bs[nn * 36 + kk] = __float2bfloat16(v);
        }
        __syncthreads();
#pragma unroll
        for (int s = 0; s < 2; s++) {
            unsigned a[2][4], b[2][2];
#pragma unroll
            for (int mt = 0; mt < 2; mt++) {
                int row = wm + mt * 16 + g;
                a[mt][0] = *(const unsigned*)&As[row * 36 + s * 16 + 2 * qd];
                a[mt][1] = *(const unsigned*)&As[(row + 8) * 36 + s * 16 + 2 * qd];
                a[mt][2] = *(const unsigned*)&As[row * 36 + s * 16 + 2 * qd + 8];
                a[mt][3] = *(const unsigned*)&As[(row + 8) * 36 + s * 16 + 2 * qd + 8];
            }
#pragma unroll
            for (int nt = 0; nt < 2; nt++) {
                int bn = wn + nt * 8 + g;
                b[nt][0] = *(const unsigned*)&Bs[bn * 36 + s * 16 + 2 * qd];
                b[nt][1] = *(const unsigned*)&Bs[bn * 36 + s * 16 + 2 * qd + 8];
            }
#pragma unroll
            for (int mt = 0; mt < 2; mt++)
#pragma unroll
                for (int nt = 0; nt < 2; nt++)
                    mma_bf16(acc[mt][nt][0], acc[mt][nt][1], acc[mt][nt][2], acc[mt][nt][3],
                             a[mt][0], a[mt][1], a[mt][2], a[mt][3], b[nt][0], b[nt][1]);
        }
        __syncthreads();
    }
#pragma unroll
    for (int mt = 0; mt < 2; mt++)
#pragma unroll
        for (int nt = 0; nt < 2; nt++) {
            int mg = m0 + wm + mt * 16 + g;
            int ng = n0 + wn + nt * 8 + qd * 2;
            float bz0 = bias[ng], bz1 = bias[ng + 1];
            float2 v0 = make_float2(gelu_tanh(acc[mt][nt][0] + bz0), gelu_tanh(acc[mt][nt][1] + bz1));
            float2 v1 = make_float2(gelu_tanh(acc[mt][nt][2] + bz0), gelu_tanh(acc[mt][nt][3] + bz1));
            *(float2*)&g_hid[mg * 512 + ng] = v0;
            *(float2*)&g_hid[(mg + 8) * 512 + ng] = v1;
        }
}

// ---------------- GEMM2: [1024,512]@[512,388] + bias, state update (bf16 mma) ----------------
__global__ __launch_bounds__(256) void k_gemm2(const float* __restrict__ B,
                                               const float* __restrict__ bias) {
    __shared__ __nv_bfloat16 As[64 * 36];
    __shared__ __nv_bfloat16 Bs[64 * 36];
    int n0 = blockIdx.x * 64, m0 = blockIdx.y * 64, t = threadIdx.x;
    int w = t >> 5, lane = t & 31, qd = lane & 3, g = lane >> 2;
    int wm = (w >> 2) * 32, wn = (w & 3) * 16;
    float acc[2][2][4];
#pragma unroll
    for (int mt = 0; mt < 2; mt++)
#pragma unroll
        for (int nt = 0; nt < 2; nt++)
#pragma unroll
            for (int u = 0; u < 4; u++) acc[mt][nt][u] = 0.f;

    for (int k0 = 0; k0 < 512; k0 += 32) {
#pragma unroll
        for (int i = t; i < 2048; i += 256) {
            int mm = i >> 5, kk = i & 31;
            As[mm * 36 + kk] = __float2bfloat16(g_hid[(m0 + mm) * 512 + k0 + kk]);
        }
#pragma unroll
        for (int i = t; i < 2048; i += 256) {
            int kk = i >> 6, nn = i & 63, n = n0 + nn;
            float v = (n < 388) ? B[(k0 + kk) * 388 + n] : 0.f;
            Bs[nn * 36 + kk] = __float2bfloat16(v);
        }
        __syncthreads();
#pragma unroll
        for (int s = 0; s < 2; s++) {
            unsigned a[2][4], b[2][2];
#pragma unroll
            for (int mt = 0; mt < 2; mt++) {
                int row = wm + mt * 16 + g;
                a[mt][0] = *(const unsigned*)&As[row * 36 + s * 16 + 2 * qd];
                a[mt][1] = *(const unsigned*)&As[(row + 8) * 36 + s * 16 + 2 * qd];
                a[mt][2] = *(const unsigned*)&As[row * 36 + s * 16 + 2 * qd + 8];
                a[mt][3] = *(const unsigned*)&As[(row + 8) * 36 + s * 16 + 2 * qd + 8];
            }
#pragma unroll
            for (int nt = 0; nt < 2; nt++) {
                int bn = wn + nt * 8 + g;
                b[nt][0] = *(const unsigned*)&Bs[bn * 36 + s * 16 + 2 * qd];
                b[nt][1] = *(const unsigned*)&Bs[bn * 36 + s * 16 + 2 * qd + 8];
            }
#pragma unroll
            for (int mt = 0; mt < 2; mt++)
#pragma unroll
                for (int nt = 0; nt < 2; nt++)
                    mma_bf16(acc[mt][nt][0], acc[mt][nt][1], acc[mt][nt][2], acc[mt][nt][3],
                             a[mt][0], a[mt][1], a[mt][2], a[mt][3], b[nt][0], b[nt][1]);
        }
        __syncthreads();
    }
#pragma unroll
    for (int mt = 0; mt < 2; mt++)
#pragma unroll
        for (int nt = 0; nt < 2; nt++) {
#pragma unroll
            for (int rr = 0; rr < 2; rr++) {
                int mg = m0 + wm + mt * 16 + g + rr * 8;
#pragma unroll
                for (int jj = 0; jj < 2; jj++) {
                    int ng = n0 + wn + nt * 8 + qd * 2 + jj;
                    if (ng < 388) {
                        float v = acc[mt][nt][rr * 2 + jj] + bias[ng];
                        if (ng < 2)       g_pos[mg * 2 + ng] += v;
                        else if (ng == 2) g_occv[mg] += v;
                        else if (ng == 3) g_expd[mg] += v;
                        else              g_feats[mg * 384 + ng - 4] += v;
                    }
                }
            }
        }
}

// ---------------- pack output ----------------
__global__ void k_out(float* __restrict__ out) {
    int i = blockIdx.x * blockDim.x + threadIdx.x;
    if (i < NQ) {
        out[i * 4 + 0] = g_pos[i * 2 + 0];
        out[i * 4 + 1] = g_pos[i * 2 + 1];
        out[i * 4 + 2] = g_occv[i];
        out[i * 4 + 3] = g_expd[i];
    }
}

// ---------------- launch ----------------
extern "C" void kernel_launch(void* const* d_in, const int* in_sizes, int n_in,
                              void* d_out, int out_size) {
    const float* fg   = (const float*)d_in[0];
    const float* hg   = (const float*)d_in[1];
    const float* qf   = (const float*)d_in[2];
    const float* hq   = (const float*)d_in[3];
    const float* w1   = (const float*)d_in[4];
    const float* b1   = (const float*)d_in[5];
    const float* w2   = (const float*)d_in[6];
    const float* b2   = (const float*)d_in[7];
    const float* w3   = (const float*)d_in[8];
    const float* b3   = (const float*)d_in[9];
    const float* w4   = (const float*)d_in[10];
    const float* b4   = (const float*)d_in[11];
    const float* occw = (const float*)d_in[12];
    const float* occb = (const float*)d_in[13];
    const float* miw  = (const float*)d_in[14];
    const float* mib  = (const float*)d_in[15];
    const float* mow  = (const float*)d_in[16];
    const float* mob  = (const float*)d_in[17];
    float* out = (float*)d_out;

    // 4356 + 10560 + 2376 + 144 + 192 + 512 + 32+16+32+2+32+32+16 = 18302 floats = 73208 B
    const int smem_head = 18302 * 4;
    cudaFuncSetAttribute(k_head, cudaFuncAttributeMaxDynamicSharedMemorySize, smem_head);

    k_cv<<<dim3(64, 16), 256>>>(qf, fg, g_cv);
    k_fgavg<<<1024, 256>>>(fg, g_fgavg);
    k_head<<<NQ, 256, smem_head>>>(g_cv, hq, qf, w1, b1, w2, b2, w3, b3, w4, b4, occw, occb);

    for (int it = 0; it < 4; it++) {
        k_corr<<<NQ, 256>>>(hg, fg);
        k_gemm1<<<dim3(8, 16), 256>>>(miw, mib);
        k_gemm2<<<dim3(7, 16), 256>>>(mow, mob);
    }
    k_out<<<4, 256>>>(out);
}

// round 7
// speedup vs baseline: 2.6789x; 1.0355x over previous
#include <cuda_runtime.h>
#include <cuda_bf16.h>
#include <math.h>

#define NQ 1024
#define MI_STRIDE 544   // padded stride for mlp_in (535 real cols)

// ---------------- scratch (device globals; no allocation) ----------------
__device__ float g_cv[NQ * 4096];        // 16 MB
__device__ float g_pos[NQ * 2];
__device__ float g_occv[NQ];
__device__ float g_expd[NQ];
__device__ float g_feats[NQ * 384];
__device__ float g_fgavg[32 * 32 * 256]; // 1 MB
__device__ float g_mlpin[NQ * MI_STRIDE];
__device__ float g_hid[NQ * 512];

__device__ __forceinline__ float gelu_tanh(float x) {
    float x3 = x * x * x;
    return 0.5f * x * (1.f + tanhf(0.7978845608028654f * (x + 0.044715f * x3)));
}

__device__ __forceinline__ float tf32r(float x) {
    unsigned u;
    asm("cvt.rna.tf32.f32 %0, %1;" : "=r"(u) : "f"(x));
    return __uint_as_float(u);
}

__device__ __forceinline__ unsigned packbf(float lo, float hi) {
    __nv_bfloat162 v = __floats2bfloat162_rn(lo, hi);
    return *(unsigned*)&v;
}

__device__ __forceinline__ void mma_tf32(float& d0, float& d1, float& d2, float& d3,
                                         float a0, float a1, float a2, float a3,
                                         float b0, float b1) {
    asm("mma.sync.aligned.m16n8k8.row.col.f32.tf32.tf32.f32 "
        "{%0,%1,%2,%3},{%4,%5,%6,%7},{%8,%9},{%0,%1,%2,%3};"
        : "+f"(d0), "+f"(d1), "+f"(d2), "+f"(d3)
        : "r"(__float_as_uint(a0)), "r"(__float_as_uint(a1)),
          "r"(__float_as_uint(a2)), "r"(__float_as_uint(a3)),
          "r"(__float_as_uint(b0)), "r"(__float_as_uint(b1)));
}

__device__ __forceinline__ void mma_bf16(float& d0, float& d1, float& d2, float& d3,
                                         unsigned a0, unsigned a1, unsigned a2, unsigned a3,
                                         unsigned b0, unsigned b1) {
    asm("mma.sync.aligned.m16n8k16.row.col.f32.bf16.bf16.f32 "
        "{%0,%1,%2,%3},{%4,%5,%6,%7},{%8,%9},{%0,%1,%2,%3};"
        : "+f"(d0), "+f"(d1), "+f"(d2), "+f"(d3)
        : "r"(a0), "r"(a1), "r"(a2), "r"(a3), "r"(b0), "r"(b1));
}

// ---------------- cv = qf[1024,256] @ fg[4096,256]^T  (tf32 mma) ----------------
__global__ __launch_bounds__(256) void k_cv(const float* __restrict__ A,
                                            const float* __restrict__ B,
                                            float* __restrict__ C) {
    __shared__ float As[64 * 17];
    __shared__ float Bs[16 * 73];
    int n0 = blockIdx.x * 64, m0 = blockIdx.y * 64, t = threadIdx.x;
    int w = t >> 5, lane = t & 31, qd = lane & 3, g = lane >> 2;
    int wm = (w >> 2) * 32, wn = (w & 3) * 16;
    int mm = t >> 2, k4 = (t & 3) * 4;
    float acc[2][2][4];
#pragma unroll
    for (int mt = 0; mt < 2; mt++)
#pragma unroll
        for (int nt = 0; nt < 2; nt++)
#pragma unroll
            for (int u = 0; u < 4; u++) acc[mt][nt][u] = 0.f;

    for (int k0 = 0; k0 < 256; k0 += 16) {
        float4 va = *(const float4*)&A[(m0 + mm) * 256 + k0 + k4];
        As[mm * 17 + k4 + 0] = tf32r(va.x);
        As[mm * 17 + k4 + 1] = tf32r(va.y);
        As[mm * 17 + k4 + 2] = tf32r(va.z);
        As[mm * 17 + k4 + 3] = tf32r(va.w);
        float4 vb = *(const float4*)&B[(n0 + mm) * 256 + k0 + k4];
        Bs[(k4 + 0) * 73 + mm] = tf32r(vb.x);
        Bs[(k4 + 1) * 73 + mm] = tf32r(vb.y);
        Bs[(k4 + 2) * 73 + mm] = tf32r(vb.z);
        Bs[(k4 + 3) * 73 + mm] = tf32r(vb.w);
        __syncthreads();
#pragma unroll
        for (int s = 0; s < 2; s++) {
            float a[2][4], b[2][2];
#pragma unroll
            for (int mt = 0; mt < 2; mt++) {
                int row = wm + mt * 16 + g;
                a[mt][0] = As[row * 17 + s * 8 + qd];
                a[mt][1] = As[(row + 8) * 17 + s * 8 + qd];
                a[mt][2] = As[row * 17 + s * 8 + qd + 4];
                a[mt][3] = As[(row + 8) * 17 + s * 8 + qd + 4];
            }
#pragma unroll
            for (int nt = 0; nt < 2; nt++) {
                int bn = wn + nt * 8 + g;
                b[nt][0] = Bs[(s * 8 + qd) * 73 + bn];
                b[nt][1] = Bs[(s * 8 + qd + 4) * 73 + bn];
            }
#pragma unroll
            for (int mt = 0; mt < 2; mt++)
#pragma unroll
                for (int nt = 0; nt < 2; nt++)
                    mma_tf32(acc[mt][nt][0], acc[mt][nt][1], acc[mt][nt][2], acc[mt][nt][3],
                             a[mt][0], a[mt][1], a[mt][2], a[mt][3], b[nt][0], b[nt][1]);
        }
        __syncthreads();
    }
#pragma unroll
    for (int mt = 0; mt < 2; mt++)
#pragma unroll
        for (int nt = 0; nt < 2; nt++) {
            int mg = m0 + wm + mt * 16 + g;
            int ng = n0 + wn + nt * 8 + qd * 2;
            *(float2*)&C[mg * 4096 + ng] = make_float2(acc[mt][nt][0], acc[mt][nt][1]);
            *(float2*)&C[(mg + 8) * 4096 + ng] = make_float2(acc[mt][nt][2], acc[mt][nt][3]);
        }
}

// ---------------- fg_avg (2x2 mean pool) ----------------
__global__ void k_fgavg(const float* __restrict__ fg, float* __restrict__ out) {
    int b = blockIdx.x;
    int y = b >> 5, x = b & 31, t = threadIdx.x;
    const float* p = fg + ((2 * y) * 64 + 2 * x) * 256;
    float v = p[t] + p[256 + t] + p[64 * 256 + t] + p[64 * 256 + 256 + t];
    out[(y * 32 + x) * 256 + t] = 0.25f * v;
}

// ---------------- per-query head ----------------
// s_cv 66 rows x stride 68, data at (row+1, col+1); s_occ stride 68, data col offset 1
#define CV_S 68
#define OC_S 68
__global__ __launch_bounds__(256, 3) void k_head(
    const float* __restrict__ cv_g, const float* __restrict__ hq, const float* __restrict__ qf,
    const float* __restrict__ w1, const float* __restrict__ b1,
    const float* __restrict__ w2, const float* __restrict__ b2,
    const float* __restrict__ w3, const float* __restrict__ b3,
    const float* __restrict__ w4, const float* __restrict__ b4,
    const float* __restrict__ occw, const float* __restrict__ occb) {
    extern __shared__ float sm[];
    float* s_cv   = sm;                       // 66*68 = 4488
    float* s_occ  = s_cv + 4488;              // 160*68 = 10880
    unsigned* s_w3b = (unsigned*)(s_occ + 10880); // 2376 (bf16x2 pairs [k/2][oc])
    float* s_ko   = (float*)(s_w3b + 2376);   // 144 (int offsets)
    float* s_w2   = s_ko + 144;               // 16*12 = 192
    float* s_w4   = s_w2 + 192;               // 512
    float* s_b3   = s_w4 + 512;               // 32
    float* s_b4   = s_b3 + 32;                // 16
    float* s_ow   = s_b4 + 16;                // 32
    float* s_ob   = s_ow + 32;                // 2
    float* s_red  = s_ob + 2;                 // 32
    float* s_o3   = s_red + 32;               // 32
    float* s_h4   = s_o3 + 32;                // 16
    int* s_koi = (int*)s_ko;

    int q = blockIdx.x, t = threadIdx.x;
    const float* cvq = cv_g + q * 4096;
    // cv with zero border: rows 0,65 zero; cols 0,65 zero; data rows 1..64 cols 1..64
    for (int i = t; i < 4096; i += 256) s_cv[(1 + (i >> 6)) * CV_S + 1 + (i & 63)] = cvq[i];
    if (t < 68) { s_cv[t] = 0.f; s_cv[65 * CV_S + t] = 0.f; }
    if (t < 64) {
        s_cv[(t + 1) * CV_S] = 0.f;
        s_cv[(t + 1) * CV_S + 65] = 0.f;
        s_cv[(t + 1) * CV_S + 66] = 0.f;
    }
    // occ pad columns 0, 65
    for (int i = t; i < 160; i += 256) {
        float* rb = &s_occ[i * OC_S];
        rb[0] = 0.f; rb[65] = 0.f;
    }
    // weights
    for (int i = t; i < 144; i += 256) { int c = i / 9, k = i - c * 9; s_w2[c * 12 + k] = w2[i]; }
    for (int i = t; i < 72 * 32; i += 256) {
        int krow = i >> 5, oc = i & 31;
        int k = krow * 2;
        s_w3b[krow * 33 + oc] = packbf(w3[oc * 144 + k], w3[oc * 144 + k + 1]);
    }
    for (int i = t; i < 144; i += 256) {
        int ic = i / 9, rk = i - ic * 9;
        int dy = rk / 3, dx = rk - dy * 3;
        s_koi[i] = (dy * 16 + ic) * OC_S + dx;
    }
    for (int i = t; i < 512; i += 256) s_w4[i] = w4[i];
    if (t < 32) s_b3[t] = b3[t];
    if (t < 16) s_b4[t] = b4[t];
    if (t < 32) s_ow[t] = occw[t];
    if (t < 2)  s_ob[t] = occb[t];
    if (t < 32) s_o3[t] = 0.f;
    for (int i = t; i < 128; i += 256) g_feats[q * 384 + i] = hq[q * 128 + i];
    for (int i = t; i < 256; i += 256) g_feats[q * 384 + 128 + i] = qf[q * 256 + i];
    float b2v = b2[0];

    // conv1 mapping: c1 (16) x xg (8) x sl2 (2); 8 cols, 5 slots per thread
    int c1 = t & 15, xg = (t >> 4) & 7, sl2 = t >> 7;
    int x0 = xg * 8;
    float w1r[9], b1r = b1[c1];
#pragma unroll
    for (int k = 0; k < 9; k++) w1r[k] = w1[c1 * 9 + k];

    // conv2 mapping: active threads t<128: rr = t>>4 (0..7), cg = t&15, cols 4cg..4cg+3
    int rr2 = (t >> 4) & 7, cg2 = t & 15;
    bool c2act = (t < 128);
    float pm[32];   // [band][4 cols]

    // conv3 mma mapping
    int wrp = t >> 5, lane = t & 31, qd = lane & 3, g = lane >> 2;
    int jrow3 = wrp >> 1;
    int col0 = (wrp & 1) * 16 + g;
    int base0 = (2 * jrow3 + 1) * (16 * OC_S) + 2 * col0 + 1;
    float macc[4][2];
#pragma unroll
    for (int nt = 0; nt < 4; nt++) { macc[nt][0] = 0.f; macc[nt][1] = 0.f; }

    __syncthreads();

    float b3n[4][2];
#pragma unroll
    for (int nt = 0; nt < 4; nt++) {
        b3n[nt][0] = s_b3[nt * 8 + qd * 2 + 0];
        b3n[nt][1] = s_b3[nt * 8 + qd * 2 + 1];
    }

    for (int r0 = 0; r0 < 64; r0 += 8) {
        int band = r0 >> 3;
        // ---- conv1 + relu : vectorized loads (f4,f4,f2 per row) ----
#pragma unroll
        for (int s = 0; s < 5; s++) {
            int slot = sl2 + 2 * s;
            int row = r0 - 1 + slot;
            float* dst = &s_occ[(slot * 16 + c1) * OC_S + 1 + x0];
            if (row < 0 || row > 63) {
#pragma unroll
                for (int j = 0; j < 8; j++) dst[j] = 0.f;
                continue;
            }
            float xv[3][10];
#pragma unroll
            for (int dy = 0; dy < 3; dy++) {
                // absolute needed cols x0 .. x0+9 in padded row (row+dy)
                const float* rp = &s_cv[(row + dy) * CV_S + x0];
                float4 vA = *(const float4*)rp;
                float4 vB = *(const float4*)(rp + 4);
                float2 vC = *(const float2*)(rp + 8);
                xv[dy][0] = vA.x; xv[dy][1] = vA.y; xv[dy][2] = vA.z; xv[dy][3] = vA.w;
                xv[dy][4] = vB.x; xv[dy][5] = vB.y; xv[dy][6] = vB.z; xv[dy][7] = vB.w;
                xv[dy][8] = vC.x; xv[dy][9] = vC.y;
            }
#pragma unroll
            for (int j = 0; j < 8; j++) {
                float a = b1r;
#pragma unroll
                for (int dy = 0; dy < 3; dy++)
#pragma unroll
                    for (int dx = 0; dx < 3; dx++)
                        a = fmaf(w1r[dy * 3 + dx], xv[dy][j + dx], a);
                dst[j] = fmaxf(a, 0.f);
            }
        }
        __syncthreads();

        // ---- conv2 : 128 threads, one row (r0+rr2), 4 cols each, vector loads ----
        if (c2act) {
            float a[4] = {b2v, b2v, b2v, b2v};
#pragma unroll
            for (int c = 0; c < 16; c++) {
                float4 wA = *(const float4*)&s_w2[c * 12];
                float4 wB = *(const float4*)&s_w2[c * 12 + 4];
                float w8 = s_w2[c * 12 + 8];
                float wv[9] = {wA.x, wA.y, wA.z, wA.w, wB.x, wB.y, wB.z, wB.w, w8};
#pragma unroll
                for (int dy = 0; dy < 3; dy++) {
                    // absolute cols 4cg .. 4cg+5  (x = 4cg-1 .. 4cg+4)
                    const float* rp = &s_occ[((rr2 + dy) * 16 + c) * OC_S + 4 * cg2];
                    float4 vA = *(const float4*)rp;
                    float2 vB = *(const float2*)(rp + 4);
                    float v[6] = {vA.x, vA.y, vA.z, vA.w, vB.x, vB.y};
#pragma unroll
                    for (int j = 0; j < 4; j++)
                        a[j] = fmaf(wv[dy * 3 + 0], v[j],
                               fmaf(wv[dy * 3 + 1], v[j + 1],
                               fmaf(wv[dy * 3 + 2], v[j + 2], a[j])));
                }
            }
#pragma unroll
            for (int j = 0; j < 4; j++) pm[band * 4 + j] = a[j];
        }

        // ---- conv3 via bf16 mma (k16): M=128, N=32, K=144 (9 steps) ----
        {
            float d[4][4];
#pragma unroll
            for (int nt = 0; nt < 4; nt++)
#pragma unroll
                for (int u = 0; u < 4; u++) d[nt][u] = 0.f;

#pragma unroll
            for (int st = 0; st < 9; st++) {
                int kE = st * 16 + 2 * qd;
                int kO = kE + 8;
                int e0 = s_koi[kE], e1 = s_koi[kE + 1];
                int o0 = s_koi[kO], o1 = s_koi[kO + 1];
                unsigned a0 = packbf(s_occ[base0 + e0],      s_occ[base0 + e1]);
                unsigned a1 = packbf(s_occ[base0 + 16 + e0], s_occ[base0 + 16 + e1]);
                unsigned a2 = packbf(s_occ[base0 + o0],      s_occ[base0 + o1]);
                unsigned a3 = packbf(s_occ[base0 + 16 + o0], s_occ[base0 + 16 + o1]);
                int kr = st * 8 + qd;
                const unsigned* bp0 = &s_w3b[kr * 33];
                const unsigned* bp1 = &s_w3b[(kr + 4) * 33];
#pragma unroll
                for (int nt = 0; nt < 4; nt++) {
                    unsigned b0 = bp0[nt * 8 + g];
                    unsigned b1 = bp1[nt * 8 + g];
                    mma_bf16(d[nt][0], d[nt][1], d[nt][2], d[nt][3], a0, a1, a2, a3, b0, b1);
                }
            }
#pragma unroll
            for (int nt = 0; nt < 4; nt++) {
                macc[nt][0] += fmaxf(d[nt][0] + b3n[nt][0], 0.f) + fmaxf(d[nt][2] + b3n[nt][0], 0.f);
                macc[nt][1] += fmaxf(d[nt][1] + b3n[nt][1], 0.f) + fmaxf(d[nt][3] + b3n[nt][1], 0.f);
            }
        }
        __syncthreads();
    }

    // conv3 reduction into s_o3
#pragma unroll
    for (int nt = 0; nt < 4; nt++) {
#pragma unroll
        for (int j = 0; j < 2; j++) {
            float v = macc[nt][j];
#pragma unroll
            for (int o = 4; o <= 16; o <<= 1) v += __shfl_xor_sync(0xffffffffu, v, o);
            if (g == 0) atomicAdd(&s_o3[nt * 8 + qd * 2 + j], v);
        }
    }

    // softmax over pm (registers): thread t<128 holds rows 8b+rr2, cols 4cg2+j
    float lmax = -1e30f;
    if (c2act) {
#pragma unroll
        for (int u = 0; u < 32; u++) lmax = fmaxf(lmax, pm[u]);
    }
#pragma unroll
    for (int o = 16; o; o >>= 1) lmax = fmaxf(lmax, __shfl_xor_sync(0xffffffffu, lmax, o));
    if ((t & 31) == 0) s_red[t >> 5] = lmax;
    __syncthreads();
    if (t == 0) {
        float m = s_red[0];
        for (int i = 1; i < 8; i++) m = fmaxf(m, s_red[i]);
        s_red[31] = m;
    }
    __syncthreads();
    float m = s_red[31];
    float se = 0.f, sy = 0.f, sx = 0.f;
    if (c2act) {
#pragma unroll
        for (int b = 0; b < 8; b++) {
            float rowf = (float)(8 * b + rr2);
#pragma unroll
            for (int j = 0; j < 4; j++) {
                float e = __expf((pm[b * 4 + j] - m) * 20.f);
                se += e;
                sy = fmaf(e, rowf, sy);
                sx = fmaf(e, (float)(4 * cg2 + j), sx);
            }
        }
    }
    __syncthreads();
#pragma unroll
    for (int o = 16; o; o >>= 1) {
        se += __shfl_xor_sync(0xffffffffu, se, o);
        sy += __shfl_xor_sync(0xffffffffu, sy, o);
        sx += __shfl_xor_sync(0xffffffffu, sx, o);
    }
    if ((t & 31) == 0) { int w = t >> 5; s_red[w] = se; s_red[8 + w] = sy; s_red[16 + w] = sx; }
    __syncthreads();
    if (t == 0) {
        float Se = 0, Sy = 0, Sx = 0;
        for (int i = 0; i < 8; i++) { Se += s_red[i]; Sy += s_red[8 + i]; Sx += s_red[16 + i]; }
        g_pos[q * 2 + 0] = (Sx / Se) * 8.f;
        g_pos[q * 2 + 1] = (Sy / Se) * 8.f;
    }
    __syncthreads();

    // head FCs
    if (t < 16) {
        float a = s_b4[t];
        for (int ic = 0; ic < 32; ic++) a = fmaf(s_o3[ic] * (1.f / 1024.f), s_w4[ic * 16 + t], a);
        s_h4[t] = fmaxf(a, 0.f);
    }
    __syncthreads();
    if (t == 0) {
        float o = s_ob[0], ex2 = s_ob[1];
        for (int k = 0; k < 16; k++) {
            o   = fmaf(s_h4[k], s_ow[k * 2 + 0], o);
            ex2 = fmaf(s_h4[k], s_ow[k * 2 + 1], ex2);
        }
        g_occv[q] = o;
        g_expd[q] = ex2;
    }
}

// ---------------- correlation + mlp_in assembly (per iteration) ----------------
__global__ __launch_bounds__(256) void k_corr(const float* __restrict__ hg,
                                              const float* __restrict__ fg) {
    __shared__ float s_q[384];
    __shared__ float s_D[64];
    int q = blockIdx.x, t = threadIdx.x;
    float px = g_pos[q * 2 + 0], py = g_pos[q * 2 + 1];
    for (int i = t; i < 384; i += 256) s_q[i] = g_feats[q * 384 + i];
    float* mi = g_mlpin + q * MI_STRIDE;
    if (t == 0) { mi[0] = 0.f; mi[1] = 0.f; mi[2] = g_occv[q]; mi[3] = g_expd[q]; }
    for (int i = t; i < 384; i += 256) mi[4 + i] = g_feats[q * 384 + i];
    __syncthreads();

    const float* Gs[3] = { hg, fg, g_fgavg };
    const int Hs[3] = { 128, 64, 32 };
    const int Cs[3] = { 128, 256, 256 };
    const int QO[3] = { 0, 128, 128 };

    int wrp = t >> 5, lane = t & 31;
#pragma unroll
    for (int l = 0; l < 3; l++) {
        const float* G = Gs[l];
        const int H = Hs[l], C = Cs[l], qo = QO[l];
        float sc = (float)H / 512.f;
        float gy = py * sc, gx = px * sc;
        float y0f = floorf(gy), x0f = floorf(gx);
        float wy = gy - y0f, wx = gx - x0f;
        int y0 = (int)y0f, x0 = (int)x0f;
        const float* sq = s_q + qo;

#pragma unroll
        for (int pp = 0; pp < 8; pp++) {
            int p = wrp + pp * 8;
            int ry = min(max(y0 + (p >> 3) - 3, 0), H - 1);
            int rx = min(max(x0 + (p & 7) - 3, 0), H - 1);
            const float* gp = G + (ry * H + rx) * C;
            float s0 = gp[lane] * sq[lane];
            float s1 = gp[lane + 32] * sq[lane + 32];
            float s2 = gp[lane + 64] * sq[lane + 64];
            float s3 = gp[lane + 96] * sq[lane + 96];
            if (C == 256) {
                s0 = fmaf(gp[lane + 128], sq[lane + 128], s0);
                s1 = fmaf(gp[lane + 160], sq[lane + 160], s1);
                s2 = fmaf(gp[lane + 192], sq[lane + 192], s2);
                s3 = fmaf(gp[lane + 224], sq[lane + 224], s3);
            }
            float s = (s0 + s1) + (s2 + s3);
#pragma unroll
            for (int o = 16; o; o >>= 1) s += __shfl_xor_sync(0xffffffffu, s, o);
            if (lane == 0) s_D[p] = s;
        }
        __syncthreads();
        if (t < 49) {
            int r = t / 7, c2 = t - r * 7;
            float d00 = s_D[r * 8 + c2],       d01 = s_D[r * 8 + c2 + 1];
            float d10 = s_D[(r + 1) * 8 + c2], d11 = s_D[(r + 1) * 8 + c2 + 1];
            float corr = (1.f - wy) * (1.f - wx) * d00 + (1.f - wy) * wx * d01
                       + wy * (1.f - wx) * d10 + wy * wx * d11;
            mi[388 + l * 49 + t] = corr;
        }
        __syncthreads();
    }
}

// ---------------- GEMM1: [1024,535]@[535,512] + bias, gelu  (bf16 mma) ----------------
__global__ __launch_bounds__(256) void k_gemm1(const float* __restrict__ B,
                                               const float* __restrict__ bias) {
    __shared__ __nv_bfloat16 As[64 * 36];
    __shared__ __nv_bfloat16 Bs[64 * 36];
    int n0 = blockIdx.x * 64, m0 = blockIdx.y * 64, t = threadIdx.x;
    int w = t >> 5, lane = t & 31, qd = lane & 3, g = lane >> 2;
    int wm = (w >> 2) * 32, wn = (w & 3) * 16;
    float acc[2][2][4];
#pragma unroll
    for (int mt = 0; mt < 2; mt++)
#pragma unroll
        for (int nt = 0; nt < 2; nt++)
#pragma unroll
            for (int u = 0; u < 4; u++) acc[mt][nt][u] = 0.f;

    for (int k0 = 0; k0 < 544; k0 += 32) {
#pragma unroll
        for (int i = t; i < 2048; i += 256) {
            int mm = i >> 5, kk = i & 31, k = k0 + kk;
            float v = (k < 535) ? g_mlpin[(m0 + mm) * MI_STRIDE + k] : 0.f;
            As[mm * 36 + kk] = __float2bfloat16(v);
        }
#pragma unroll
        for (int i = t; i < 2048; i += 256) {
            int kk = i >> 6, nn = i & 63, k = k0 + kk;
            float v = (k < 535) ? B[k * 512 + n0 + nn] : 0.f;
            Bs[nn * 36 + kk] = __float2bfloat16(v);
        }
        __syncthreads();
#pragma unroll
        for (int s = 0; s < 2; s++) {
            unsigned a[2][4], b[2][2];
#pragma unroll
            for (int mt = 0; mt < 2; mt++) {
                int row = wm + mt * 16 + g;
                a[mt][0] = *(const unsigned*)&As[row * 36 + s * 16 + 2 * qd];
                a[mt][1] = *(const unsigned*)&As[(row + 8) * 36 + s * 16 + 2 * qd];
                a[mt][2] = *(const unsigned*)&As[row * 36 + s * 16 + 2 * qd + 8];
                a[mt][3] = *(const unsigned*)&As[(row + 8) * 36 + s * 16 + 2 * qd + 8];
            }
#pragma unroll
            for (int nt = 0; nt < 2; nt++) {
                int bn = wn + nt * 8 + g;
                b[nt][0] = *(const unsigned*)&Bs[bn * 36 + s * 16 + 2 * qd];
                b[nt][1] = *(const unsigned*)&Bs[bn * 36 + s * 16 + 2 * qd + 8];
            }
#pragma unroll
            for (int mt = 0; mt < 2; mt++)
#pragma unroll
                for (int nt = 0; nt < 2; nt++)
                    mma_bf16(acc[mt][nt][0], acc[mt][nt][1], acc[mt][nt][2], acc[mt][nt][3],
                             a[mt][0], a[mt][1], a[mt][2], a[mt][3], b[nt][0], b[nt][1]);
        }
        __syncthreads();
    }
#pragma unroll
    for (int mt = 0; mt < 2; mt++)
#pragma unroll
        for (int nt = 0; nt < 2; nt++) {
            int mg = m0 + wm + mt * 16 + g;
            int ng = n0 + wn + nt * 8 + qd * 2;
            float bz0 = bias[ng], bz1 = bias[ng + 1];
            float2 v0 = make_float2(gelu_tanh(acc[mt][nt][0] + bz0), gelu_tanh(acc[mt][nt][1] + bz1));
            float2 v1 = make_float2(gelu_tanh(acc[mt][nt][2] + bz0), gelu_tanh(acc[mt][nt][3] + bz1));
            *(float2*)&g_hid[mg * 512 + ng] = v0;
            *(float2*)&g_hid[(mg + 8) * 512 + ng] = v1;
        }
}

// ---------------- GEMM2: [1024,512]@[512,388] + bias, state update (bf16 mma) ----------------
__global__ __launch_bounds__(256) void k_gemm2(const float* __restrict__ B,
                                               const float* __restrict__ bias) {
    __shared__ __nv_bfloat16 As[64 * 36];
    __shared__ __nv_bfloat16 Bs[64 * 36];
    int n0 = blockIdx.x * 64, m0 = blockIdx.y * 64, t = threadIdx.x;
    int w = t >> 5, lane = t & 31, qd = lane & 3, g = lane >> 2;
    int wm = (w >> 2) * 32, wn = (w & 3) * 16;
    float acc[2][2][4];
#pragma unroll
    for (int mt = 0; mt < 2; mt++)
#pragma unroll
        for (int nt = 0; nt < 2; nt++)
#pragma unroll
            for (int u = 0; u < 4; u++) acc[mt][nt][u] = 0.f;

    for (int k0 = 0; k0 < 512; k0 += 32) {
#pragma unroll
        for (int i = t; i < 2048; i += 256) {
            int mm = i >> 5, kk = i & 31;
            As[mm * 36 + kk] = __float2bfloat16(g_hid[(m0 + mm) * 512 + k0 + kk]);
        }
#pragma unroll
        for (int i = t; i < 2048; i += 256) {
            int kk = i >> 6, nn = i & 63, n = n0 + nn;
            float v = (n < 388) ? B[(k0 + kk) * 388 + n] : 0.f;
            Bs[nn * 36 + kk] = __float2bfloat16(v);
        }
        __syncthreads();
#pragma unroll
        for (int s = 0; s < 2; s++) {
            unsigned a[2][4], b[2][2];
#pragma unroll
            for (int mt = 0; mt < 2; mt++) {
                int row = wm + mt * 16 + g;
                a[mt][0] = *(const unsigned*)&As[row * 36 + s * 16 + 2 * qd];
                a[mt][1] = *(const unsigned*)&As[(row + 8) * 36 + s * 16 + 2 * qd];
                a[mt][2] = *(const unsigned*)&As[row * 36 + s * 16 + 2 * qd + 8];
                a[mt][3] = *(const unsigned*)&As[(row + 8) * 36 + s * 16 + 2 * qd + 8];
            }
#pragma unroll
            for (int nt = 0; nt < 2; nt++) {
                int bn = wn + nt * 8 + g;
                b[nt][0] = *(const unsigned*)&Bs[bn * 36 + s * 16 + 2 * qd];
                b[nt][1] = *(const unsigned*)&Bs[bn * 36 + s * 16 + 2 * qd + 8];
            }
#pragma unroll
            for (int mt = 0; mt < 2; mt++)
#pragma unroll
                for (int nt = 0; nt < 2; nt++)
                    mma_bf16(acc[mt][nt][0], acc[mt][nt][1], acc[mt][nt][2], acc[mt][nt][3],
                             a[mt][0], a[mt][1], a[mt][2], a[mt][3], b[nt][0], b[nt][1]);
        }
        __syncthreads();
    }
#pragma unroll
    for (int mt = 0; mt < 2; mt++)
#pragma unroll
        for (int nt = 0; nt < 2; nt++) {
#pragma unroll
            for (int rr = 0; rr < 2; rr++) {
                int mg = m0 + wm + mt * 16 + g + rr * 8;
#pragma unroll
                for (int jj = 0; jj < 2; jj++) {
                    int ng = n0 + wn + nt * 8 + qd * 2 + jj;
                    if (ng < 388) {
                        float v = acc[mt][nt][rr * 2 + jj] + bias[ng];
                        if (ng < 2)       g_pos[mg * 2 + ng] += v;
                        else if (ng == 2) g_occv[mg] += v;
                        else if (ng == 3) g_expd[mg] += v;
                        else              g_feats[mg * 384 + ng - 4] += v;
                    }
                }
            }
        }
}

// ---------------- pack output ----------------
__global__ void k_out(float* __restrict__ out) {
    int i = blockIdx.x * blockDim.x + threadIdx.x;
    if (i < NQ) {
        out[i * 4 + 0] = g_pos[i * 2 + 0];
        out[i * 4 + 1] = g_pos[i * 2 + 1];
        out[i * 4 + 2] = g_occv[i];
        out[i * 4 + 3] = g_expd[i];
    }
}

// ---------------- launch ----------------
extern "C" void kernel_launch(void* const* d_in, const int* in_sizes, int n_in,
                              void* d_out, int out_size) {
    const float* fg   = (const float*)d_in[0];
    const float* hg   = (const float*)d_in[1];
    const float* qf   = (const float*)d_in[2];
    const float* hq   = (const float*)d_in[3];
    const float* w1   = (const float*)d_in[4];
    const float* b1   = (const float*)d_in[5];
    const float* w2   = (const float*)d_in[6];
    const float* b2   = (const float*)d_in[7];
    const float* w3   = (const float*)d_in[8];
    const float* b3   = (const float*)d_in[9];
    const float* w4   = (const float*)d_in[10];
    const float* b4   = (const float*)d_in[11];
    const float* occw = (const float*)d_in[12];
    const float* occb = (const float*)d_in[13];
    const float* miw  = (const float*)d_in[14];
    const float* mib  = (const float*)d_in[15];
    const float* mow  = (const float*)d_in[16];
    const float* mob  = (const float*)d_in[17];
    float* out = (float*)d_out;

    // 4488 + 10880 + 2376 + 144 + 192 + 512 + 162 = 18754 floats = 75016 B
    const int smem_head = 18754 * 4;
    cudaFuncSetAttribute(k_head, cudaFuncAttributeMaxDynamicSharedMemorySize, smem_head);

    k_cv<<<dim3(64, 16), 256>>>(qf, fg, g_cv);
    k_fgavg<<<1024, 256>>>(fg, g_fgavg);
    k_head<<<NQ, 256, smem_head>>>(g_cv, hq, qf, w1, b1, w2, b2, w3, b3, w4, b4, occw, occb);

    for (int it = 0; it < 4; it++) {
        k_corr<<<NQ, 256>>>(hg, fg);
        k_gemm1<<<dim3(8, 16), 256>>>(miw, mib);
        k_gemm2<<<dim3(7, 16), 256>>>(mow, mob);
    }
    k_out<<<4, 256>>>(out);
}

// round 8
// speedup vs baseline: 3.3418x; 1.2474x over previous
#include <cuda_runtime.h>
#include <cuda_bf16.h>
#include <math.h>

#define NQ 1024
#define MI_STRIDE 544   // padded stride for mlp_in (535 real cols)

// ---------------- scratch (device globals; no allocation) ----------------
__device__ float g_cv[NQ * 4096];        // 16 MB
__device__ float g_pos[NQ * 2];
__device__ float g_occv[NQ];
__device__ float g_expd[NQ];
__device__ float g_feats[NQ * 384];
__device__ float g_fgavg[32 * 32 * 256]; // 1 MB
__device__ __nv_bfloat16 g_mlpinh[NQ * MI_STRIDE];   // bf16 mixer input
__device__ __nv_bfloat16 g_hidh[NQ * 512];           // bf16 hidden
__device__ __nv_bfloat16 g_miwh[512 * 544];          // miw^T bf16 [n][k], k-padded
__device__ __nv_bfloat16 g_mowh[448 * 512];          // mow^T bf16 [n][k], n-padded

__device__ __forceinline__ float gelu_tanh(float x) {
    float x3 = x * x * x;
    return 0.5f * x * (1.f + tanhf(0.7978845608028654f * (x + 0.044715f * x3)));
}

__device__ __forceinline__ float tf32r(float x) {
    unsigned u;
    asm("cvt.rna.tf32.f32 %0, %1;" : "=r"(u) : "f"(x));
    return __uint_as_float(u);
}

__device__ __forceinline__ unsigned packbf(float lo, float hi) {
    __nv_bfloat162 v = __floats2bfloat162_rn(lo, hi);
    return *(unsigned*)&v;
}

__device__ __forceinline__ void mma_tf32(float& d0, float& d1, float& d2, float& d3,
                                         float a0, float a1, float a2, float a3,
                                         float b0, float b1) {
    asm("mma.sync.aligned.m16n8k8.row.col.f32.tf32.tf32.f32 "
        "{%0,%1,%2,%3},{%4,%5,%6,%7},{%8,%9},{%0,%1,%2,%3};"
        : "+f"(d0), "+f"(d1), "+f"(d2), "+f"(d3)
        : "r"(__float_as_uint(a0)), "r"(__float_as_uint(a1)),
          "r"(__float_as_uint(a2)), "r"(__float_as_uint(a3)),
          "r"(__float_as_uint(b0)), "r"(__float_as_uint(b1)));
}

__device__ __forceinline__ void mma_bf16(float& d0, float& d1, float& d2, float& d3,
                                         unsigned a0, unsigned a1, unsigned a2, unsigned a3,
                                         unsigned b0, unsigned b1) {
    asm("mma.sync.aligned.m16n8k16.row.col.f32.bf16.bf16.f32 "
        "{%0,%1,%2,%3},{%4,%5,%6,%7},{%8,%9},{%0,%1,%2,%3};"
        : "+f"(d0), "+f"(d1), "+f"(d2), "+f"(d3)
        : "r"(a0), "r"(a1), "r"(a2), "r"(a3), "r"(b0), "r"(b1));
}

// ---------------- one-time weight convert+transpose ----------------
__global__ void k_prep(const float* __restrict__ miw, const float* __restrict__ mow) {
    int n = blockIdx.x, t = threadIdx.x;
    if (n < 512) {
        for (int k = t; k < 544; k += 256)
            g_miwh[n * 544 + k] = __float2bfloat16(k < 535 ? miw[k * 512 + n] : 0.f);
    } else {
        int nn = n - 512;   // 0..447
        for (int k = t; k < 512; k += 256)
            g_mowh[nn * 512 + k] = __float2bfloat16(nn < 388 ? mow[k * 388 + nn] : 0.f);
    }
}

// ---------------- cv = qf[1024,256] @ fg[4096,256]^T  (tf32 mma) ----------------
__global__ __launch_bounds__(256) void k_cv(const float* __restrict__ A,
                                            const float* __restrict__ B,
                                            float* __restrict__ C) {
    __shared__ float As[64 * 17];
    __shared__ float Bs[16 * 73];
    int n0 = blockIdx.x * 64, m0 = blockIdx.y * 64, t = threadIdx.x;
    int w = t >> 5, lane = t & 31, qd = lane & 3, g = lane >> 2;
    int wm = (w >> 2) * 32, wn = (w & 3) * 16;
    int mm = t >> 2, k4 = (t & 3) * 4;
    float acc[2][2][4];
#pragma unroll
    for (int mt = 0; mt < 2; mt++)
#pragma unroll
        for (int nt = 0; nt < 2; nt++)
#pragma unroll
            for (int u = 0; u < 4; u++) acc[mt][nt][u] = 0.f;

    for (int k0 = 0; k0 < 256; k0 += 16) {
        float4 va = *(const float4*)&A[(m0 + mm) * 256 + k0 + k4];
        As[mm * 17 + k4 + 0] = tf32r(va.x);
        As[mm * 17 + k4 + 1] = tf32r(va.y);
        As[mm * 17 + k4 + 2] = tf32r(va.z);
        As[mm * 17 + k4 + 3] = tf32r(va.w);
        float4 vb = *(const float4*)&B[(n0 + mm) * 256 + k0 + k4];
        Bs[(k4 + 0) * 73 + mm] = tf32r(vb.x);
        Bs[(k4 + 1) * 73 + mm] = tf32r(vb.y);
        Bs[(k4 + 2) * 73 + mm] = tf32r(vb.z);
        Bs[(k4 + 3) * 73 + mm] = tf32r(vb.w);
        __syncthreads();
#pragma unroll
        for (int s = 0; s < 2; s++) {
            float a[2][4], b[2][2];
#pragma unroll
            for (int mt = 0; mt < 2; mt++) {
                int row = wm + mt * 16 + g;
                a[mt][0] = As[row * 17 + s * 8 + qd];
                a[mt][1] = As[(row + 8) * 17 + s * 8 + qd];
                a[mt][2] = As[row * 17 + s * 8 + qd + 4];
                a[mt][3] = As[(row + 8) * 17 + s * 8 + qd + 4];
            }
#pragma unroll
            for (int nt = 0; nt < 2; nt++) {
                int bn = wn + nt * 8 + g;
                b[nt][0] = Bs[(s * 8 + qd) * 73 + bn];
                b[nt][1] = Bs[(s * 8 + qd + 4) * 73 + bn];
            }
#pragma unroll
            for (int mt = 0; mt < 2; mt++)
#pragma unroll
                for (int nt = 0; nt < 2; nt++)
                    mma_tf32(acc[mt][nt][0], acc[mt][nt][1], acc[mt][nt][2], acc[mt][nt][3],
                             a[mt][0], a[mt][1], a[mt][2], a[mt][3], b[nt][0], b[nt][1]);
        }
        __syncthreads();
    }
#pragma unroll
    for (int mt = 0; mt < 2; mt++)
#pragma unroll
        for (int nt = 0; nt < 2; nt++) {
            int mg = m0 + wm + mt * 16 + g;
            int ng = n0 + wn + nt * 8 + qd * 2;
            *(float2*)&C[mg * 4096 + ng] = make_float2(acc[mt][nt][0], acc[mt][nt][1]);
            *(float2*)&C[(mg + 8) * 4096 + ng] = make_float2(acc[mt][nt][2], acc[mt][nt][3]);
        }
}

// ---------------- fg_avg (2x2 mean pool) ----------------
__global__ void k_fgavg(const float* __restrict__ fg, float* __restrict__ out) {
    int b = blockIdx.x;
    int y = b >> 5, x = b & 31, t = threadIdx.x;
    const float* p = fg + ((2 * y) * 64 + 2 * x) * 256;
    float v = p[t] + p[256 + t] + p[64 * 256 + t] + p[64 * 256 + 256 + t];
    out[(y * 32 + x) * 256 + t] = 0.25f * v;
}

// ---------------- per-query head ----------------
#define CV_S 68
#define OC_S 68
__global__ __launch_bounds__(256, 3) void k_head(
    const float* __restrict__ cv_g, const float* __restrict__ hq, const float* __restrict__ qf,
    const float* __restrict__ w1, const float* __restrict__ b1,
    const float* __restrict__ w2, const float* __restrict__ b2,
    const float* __restrict__ w3, const float* __restrict__ b3,
    const float* __restrict__ w4, const float* __restrict__ b4,
    const float* __restrict__ occw, const float* __restrict__ occb) {
    extern __shared__ float sm[];
    float* s_cv   = sm;                       // 66*68 = 4488
    float* s_occ  = s_cv + 4488;              // 160*68 = 10880
    unsigned* s_w3b = (unsigned*)(s_occ + 10880); // 2376
    float* s_ko   = (float*)(s_w3b + 2376);   // 144
    float* s_w2   = s_ko + 144;               // 192
    float* s_w4   = s_w2 + 192;               // 512
    float* s_b3   = s_w4 + 512;               // 32
    float* s_b4   = s_b3 + 32;                // 16
    float* s_ow   = s_b4 + 16;                // 32
    float* s_ob   = s_ow + 32;                // 2
    float* s_red  = s_ob + 2;                 // 32
    float* s_o3   = s_red + 32;               // 32
    float* s_h4   = s_o3 + 32;                // 16
    int* s_koi = (int*)s_ko;

    int q = blockIdx.x, t = threadIdx.x;
    const float* cvq = cv_g + q * 4096;
    for (int i = t; i < 4096; i += 256) s_cv[(1 + (i >> 6)) * CV_S + 1 + (i & 63)] = cvq[i];
    if (t < 68) { s_cv[t] = 0.f; s_cv[65 * CV_S + t] = 0.f; }
    if (t < 64) {
        s_cv[(t + 1) * CV_S] = 0.f;
        s_cv[(t + 1) * CV_S + 65] = 0.f;
        s_cv[(t + 1) * CV_S + 66] = 0.f;
    }
    for (int i = t; i < 160; i += 256) {
        float* rb = &s_occ[i * OC_S];
        rb[0] = 0.f; rb[65] = 0.f;
    }
    for (int i = t; i < 144; i += 256) { int c = i / 9, k = i - c * 9; s_w2[c * 12 + k] = w2[i]; }
    for (int i = t; i < 72 * 32; i += 256) {
        int krow = i >> 5, oc = i & 31;
        int k = krow * 2;
        s_w3b[krow * 33 + oc] = packbf(w3[oc * 144 + k], w3[oc * 144 + k + 1]);
    }
    for (int i = t; i < 144; i += 256) {
        int ic = i / 9, rk = i - ic * 9;
        int dy = rk / 3, dx = rk - dy * 3;
        s_koi[i] = (dy * 16 + ic) * OC_S + dx;
    }
    for (int i = t; i < 512; i += 256) s_w4[i] = w4[i];
    if (t < 32) s_b3[t] = b3[t];
    if (t < 16) s_b4[t] = b4[t];
    if (t < 32) s_ow[t] = occw[t];
    if (t < 2)  s_ob[t] = occb[t];
    if (t < 32) s_o3[t] = 0.f;
    for (int i = t; i < 128; i += 256) g_feats[q * 384 + i] = hq[q * 128 + i];
    for (int i = t; i < 256; i += 256) g_feats[q * 384 + 128 + i] = qf[q * 256 + i];
    float b2v = b2[0];

    int c1 = t & 15, xg = (t >> 4) & 7, sl2 = t >> 7;
    int x0 = xg * 8;
    float w1r[9], b1r = b1[c1];
#pragma unroll
    for (int k = 0; k < 9; k++) w1r[k] = w1[c1 * 9 + k];

    int rr2 = (t >> 4) & 7, cg2 = t & 15;
    bool c2act = (t < 128);
    float pm[32];

    int wrp = t >> 5, lane = t & 31, qd = lane & 3, g = lane >> 2;
    int jrow3 = wrp >> 1;
    int col0 = (wrp & 1) * 16 + g;
    int base0 = (2 * jrow3 + 1) * (16 * OC_S) + 2 * col0 + 1;
    float macc[4][2];
#pragma unroll
    for (int nt = 0; nt < 4; nt++) { macc[nt][0] = 0.f; macc[nt][1] = 0.f; }

    __syncthreads();

    float b3n[4][2];
#pragma unroll
    for (int nt = 0; nt < 4; nt++) {
        b3n[nt][0] = s_b3[nt * 8 + qd * 2 + 0];
        b3n[nt][1] = s_b3[nt * 8 + qd * 2 + 1];
    }

    for (int r0 = 0; r0 < 64; r0 += 8) {
        int band = r0 >> 3;
#pragma unroll
        for (int s = 0; s < 5; s++) {
            int slot = sl2 + 2 * s;
            int row = r0 - 1 + slot;
            float* dst = &s_occ[(slot * 16 + c1) * OC_S + 1 + x0];
            if (row < 0 || row > 63) {
#pragma unroll
                for (int j = 0; j < 8; j++) dst[j] = 0.f;
                continue;
            }
            float xv[3][10];
#pragma unroll
            for (int dy = 0; dy < 3; dy++) {
                const float* rp = &s_cv[(row + dy) * CV_S + x0];
                float4 vA = *(const float4*)rp;
                float4 vB = *(const float4*)(rp + 4);
                float2 vC = *(const float2*)(rp + 8);
                xv[dy][0] = vA.x; xv[dy][1] = vA.y; xv[dy][2] = vA.z; xv[dy][3] = vA.w;
                xv[dy][4] = vB.x; xv[dy][5] = vB.y; xv[dy][6] = vB.z; xv[dy][7] = vB.w;
                xv[dy][8] = vC.x; xv[dy][9] = vC.y;
            }
#pragma unroll
            for (int j = 0; j < 8; j++) {
                float a = b1r;
#pragma unroll
                for (int dy = 0; dy < 3; dy++)
#pragma unroll
                    for (int dx = 0; dx < 3; dx++)
                        a = fmaf(w1r[dy * 3 + dx], xv[dy][j + dx], a);
                dst[j] = fmaxf(a, 0.f);
            }
        }
        __syncthreads();

        if (c2act) {
            float a[4] = {b2v, b2v, b2v, b2v};
#pragma unroll
            for (int c = 0; c < 16; c++) {
                float4 wA = *(const float4*)&s_w2[c * 12];
                float4 wB = *(const float4*)&s_w2[c * 12 + 4];
                float w8 = s_w2[c * 12 + 8];
                float wv[9] = {wA.x, wA.y, wA.z, wA.w, wB.x, wB.y, wB.z, wB.w, w8};
#pragma unroll
                for (int dy = 0; dy < 3; dy++) {
                    const float* rp = &s_occ[((rr2 + dy) * 16 + c) * OC_S + 4 * cg2];
                    float4 vA = *(const float4*)rp;
                    float2 vB = *(const float2*)(rp + 4);
                    float v[6] = {vA.x, vA.y, vA.z, vA.w, vB.x, vB.y};
#pragma unroll
                    for (int j = 0; j < 4; j++)
                        a[j] = fmaf(wv[dy * 3 + 0], v[j],
                               fmaf(wv[dy * 3 + 1], v[j + 1],
                               fmaf(wv[dy * 3 + 2], v[j + 2], a[j])));
                }
            }
#pragma unroll
            for (int j = 0; j < 4; j++) pm[band * 4 + j] = a[j];
        }

        {
            float d[4][4];
#pragma unroll
            for (int nt = 0; nt < 4; nt++)
#pragma unroll
                for (int u = 0; u < 4; u++) d[nt][u] = 0.f;

#pragma unroll
            for (int st = 0; st < 9; st++) {
                int kE = st * 16 + 2 * qd;
                int kO = kE + 8;
                int e0 = s_koi[kE], e1 = s_koi[kE + 1];
                int o0 = s_koi[kO], o1 = s_koi[kO + 1];
                unsigned a0 = packbf(s_occ[base0 + e0],      s_occ[base0 + e1]);
                unsigned a1 = packbf(s_occ[base0 + 16 + e0], s_occ[base0 + 16 + e1]);
                unsigned a2 = packbf(s_occ[base0 + o0],      s_occ[base0 + o1]);
                unsigned a3 = packbf(s_occ[base0 + 16 + o0], s_occ[base0 + 16 + o1]);
                int kr = st * 8 + qd;
                const unsigned* bp0 = &s_w3b[kr * 33];
                const unsigned* bp1 = &s_w3b[(kr + 4) * 33];
#pragma unroll
                for (int nt = 0; nt < 4; nt++) {
                    unsigned b0 = bp0[nt * 8 + g];
                    unsigned b1 = bp1[nt * 8 + g];
                    mma_bf16(d[nt][0], d[nt][1], d[nt][2], d[nt][3], a0, a1, a2, a3, b0, b1);
                }
            }
#pragma unroll
            for (int nt = 0; nt < 4; nt++) {
                macc[nt][0] += fmaxf(d[nt][0] + b3n[nt][0], 0.f) + fmaxf(d[nt][2] + b3n[nt][0], 0.f);
                macc[nt][1] += fmaxf(d[nt][1] + b3n[nt][1], 0.f) + fmaxf(d[nt][3] + b3n[nt][1], 0.f);
            }
        }
        __syncthreads();
    }

#pragma unroll
    for (int nt = 0; nt < 4; nt++) {
#pragma unroll
        for (int j = 0; j < 2; j++) {
            float v = macc[nt][j];
#pragma unroll
            for (int o = 4; o <= 16; o <<= 1) v += __shfl_xor_sync(0xffffffffu, v, o);
            if (g == 0) atomicAdd(&s_o3[nt * 8 + qd * 2 + j], v);
        }
    }

    float lmax = -1e30f;
    if (c2act) {
#pragma unroll
        for (int u = 0; u < 32; u++) lmax = fmaxf(lmax, pm[u]);
    }
#pragma unroll
    for (int o = 16; o; o >>= 1) lmax = fmaxf(lmax, __shfl_xor_sync(0xffffffffu, lmax, o));
    if ((t & 31) == 0) s_red[t >> 5] = lmax;
    __syncthreads();
    if (t == 0) {
        float m = s_red[0];
        for (int i = 1; i < 8; i++) m = fmaxf(m, s_red[i]);
        s_red[31] = m;
    }
    __syncthreads();
    float m = s_red[31];
    float se = 0.f, sy = 0.f, sx = 0.f;
    if (c2act) {
#pragma unroll
        for (int b = 0; b < 8; b++) {
            float rowf = (float)(8 * b + rr2);
#pragma unroll
            for (int j = 0; j < 4; j++) {
                float e = __expf((pm[b * 4 + j] - m) * 20.f);
                se += e;
                sy = fmaf(e, rowf, sy);
                sx = fmaf(e, (float)(4 * cg2 + j), sx);
            }
        }
    }
    __syncthreads();
#pragma unroll
    for (int o = 16; o; o >>= 1) {
        se += __shfl_xor_sync(0xffffffffu, se, o);
        sy += __shfl_xor_sync(0xffffffffu, sy, o);
        sx += __shfl_xor_sync(0xffffffffu, sx, o);
    }
    if ((t & 31) == 0) { int w = t >> 5; s_red[w] = se; s_red[8 + w] = sy; s_red[16 + w] = sx; }
    __syncthreads();
    if (t == 0) {
        float Se = 0, Sy = 0, Sx = 0;
        for (int i = 0; i < 8; i++) { Se += s_red[i]; Sy += s_red[8 + i]; Sx += s_red[16 + i]; }
        g_pos[q * 2 + 0] = (Sx / Se) * 8.f;
        g_pos[q * 2 + 1] = (Sy / Se) * 8.f;
    }
    __syncthreads();

    if (t < 16) {
        float a = s_b4[t];
        for (int ic = 0; ic < 32; ic++) a = fmaf(s_o3[ic] * (1.f / 1024.f), s_w4[ic * 16 + t], a);
        s_h4[t] = fmaxf(a, 0.f);
    }
    __syncthreads();
    if (t == 0) {
        float o = s_ob[0], ex2 = s_ob[1];
        for (int k = 0; k < 16; k++) {
            o   = fmaf(s_h4[k], s_ow[k * 2 + 0], o);
            ex2 = fmaf(s_h4[k], s_ow[k * 2 + 1], ex2);
        }
        g_occv[q] = o;
        g_expd[q] = ex2;
    }
}

// ---------------- correlation + mlp_in assembly (bf16 out) ----------------
__global__ __launch_bounds__(256) void k_corr(const float* __restrict__ hg,
                                              const float* __restrict__ fg) {
    __shared__ float s_q[384];
    __shared__ float s_D[64];
    int q = blockIdx.x, t = threadIdx.x;
    float px = g_pos[q * 2 + 0], py = g_pos[q * 2 + 1];
    for (int i = t; i < 384; i += 256) s_q[i] = g_feats[q * 384 + i];
    __nv_bfloat16* mih = g_mlpinh + q * MI_STRIDE;
    if (t == 0) {
        mih[0] = __float2bfloat16(0.f);
        mih[1] = __float2bfloat16(0.f);
        mih[2] = __float2bfloat16(g_occv[q]);
        mih[3] = __float2bfloat16(g_expd[q]);
    }
    if (t >= 246 && t < 255) mih[535 + (t - 246)] = __float2bfloat16(0.f);  // k-pad
    for (int i = t; i < 384; i += 256) mih[4 + i] = __float2bfloat16(g_feats[q * 384 + i]);
    __syncthreads();

    const float* Gs[3] = { hg, fg, g_fgavg };
    const int Hs[3] = { 128, 64, 32 };
    const int Cs[3] = { 128, 256, 256 };
    const int QO[3] = { 0, 128, 128 };

    int wrp = t >> 5, lane = t & 31;
#pragma unroll
    for (int l = 0; l < 3; l++) {
        const float* G = Gs[l];
        const int H = Hs[l], C = Cs[l], qo = QO[l];
        float sc = (float)H / 512.f;
        float gy = py * sc, gx = px * sc;
        float y0f = floorf(gy), x0f = floorf(gx);
        float wy = gy - y0f, wx = gx - x0f;
        int y0 = (int)y0f, x0 = (int)x0f;
        const float* sq = s_q + qo;

#pragma unroll
        for (int pp = 0; pp < 8; pp++) {
            int p = wrp + pp * 8;
            int ry = min(max(y0 + (p >> 3) - 3, 0), H - 1);
            int rx = min(max(x0 + (p & 7) - 3, 0), H - 1);
            const float* gp = G + (ry * H + rx) * C;
            float s0 = gp[lane] * sq[lane];
            float s1 = gp[lane + 32] * sq[lane + 32];
            float s2 = gp[lane + 64] * sq[lane + 64];
            float s3 = gp[lane + 96] * sq[lane + 96];
            if (C == 256) {
                s0 = fmaf(gp[lane + 128], sq[lane + 128], s0);
                s1 = fmaf(gp[lane + 160], sq[lane + 160], s1);
                s2 = fmaf(gp[lane + 192], sq[lane + 192], s2);
                s3 = fmaf(gp[lane + 224], sq[lane + 224], s3);
            }
            float s = (s0 + s1) + (s2 + s3);
#pragma unroll
            for (int o = 16; o; o >>= 1) s += __shfl_xor_sync(0xffffffffu, s, o);
            if (lane == 0) s_D[p] = s;
        }
        __syncthreads();
        if (t < 49) {
            int r = t / 7, c2 = t - r * 7;
            float d00 = s_D[r * 8 + c2],       d01 = s_D[r * 8 + c2 + 1];
            float d10 = s_D[(r + 1) * 8 + c2], d11 = s_D[(r + 1) * 8 + c2 + 1];
            float corr = (1.f - wy) * (1.f - wx) * d00 + (1.f - wy) * wx * d01
                       + wy * (1.f - wx) * d10 + wy * wx * d11;
            mih[388 + l * 49 + t] = __float2bfloat16(corr);
        }
        __syncthreads();
    }
}

// ---------------- GEMM1: mlpin[1024,544]@miw^T + bias, gelu -> hid (bf16) ----------------
#define AS_S 40
__global__ __launch_bounds__(256) void k_gemm1(const float* __restrict__ bias) {
    __shared__ __align__(16) __nv_bfloat16 As[2][64 * AS_S];
    __shared__ __align__(16) __nv_bfloat16 Bs[2][64 * AS_S];
    int n0 = blockIdx.x * 64, m0 = blockIdx.y * 64, t = threadIdx.x;
    int w = t >> 5, lane = t & 31, qd = lane & 3, g = lane >> 2;
    int wm = (w >> 2) * 32, wn = (w & 3) * 16;
    int fm = t >> 2, fk = (t & 3) * 8;   // fill: row, k-offset (8 bf16 = 16B)
    float acc[2][2][4];
#pragma unroll
    for (int mt = 0; mt < 2; mt++)
#pragma unroll
        for (int nt = 0; nt < 2; nt++)
#pragma unroll
            for (int u = 0; u < 4; u++) acc[mt][nt][u] = 0.f;

    const int NS = 17;
    // prologue fill stage 0
    *(uint4*)&As[0][fm * AS_S + fk] = *(const uint4*)&g_mlpinh[(m0 + fm) * MI_STRIDE + fk];
    *(uint4*)&Bs[0][fm * AS_S + fk] = *(const uint4*)&g_miwh[(n0 + fm) * 544 + fk];
    __syncthreads();

    for (int st = 0; st < NS; st++) {
        int cur = st & 1;
        if (st + 1 < NS) {
            int nb = (st + 1) & 1, k0 = (st + 1) * 32;
            *(uint4*)&As[nb][fm * AS_S + fk] = *(const uint4*)&g_mlpinh[(m0 + fm) * MI_STRIDE + k0 + fk];
            *(uint4*)&Bs[nb][fm * AS_S + fk] = *(const uint4*)&g_miwh[(n0 + fm) * 544 + k0 + fk];
        }
#pragma unroll
        for (int s = 0; s < 2; s++) {
            unsigned a[2][4], b[2][2];
#pragma unroll
            for (int mt = 0; mt < 2; mt++) {
                int row = wm + mt * 16 + g;
                a[mt][0] = *(const unsigned*)&As[cur][row * AS_S + s * 16 + 2 * qd];
                a[mt][1] = *(const unsigned*)&As[cur][(row + 8) * AS_S + s * 16 + 2 * qd];
                a[mt][2] = *(const unsigned*)&As[cur][row * AS_S + s * 16 + 2 * qd + 8];
                a[mt][3] = *(const unsigned*)&As[cur][(row + 8) * AS_S + s * 16 + 2 * qd + 8];
            }
#pragma unroll
            for (int nt = 0; nt < 2; nt++) {
                int bn = wn + nt * 8 + g;
                b[nt][0] = *(const unsigned*)&Bs[cur][bn * AS_S + s * 16 + 2 * qd];
                b[nt][1] = *(const unsigned*)&Bs[cur][bn * AS_S + s * 16 + 2 * qd + 8];
            }
#pragma unroll
            for (int mt = 0; mt < 2; mt++)
#pragma unroll
                for (int nt = 0; nt < 2; nt++)
                    mma_bf16(acc[mt][nt][0], acc[mt][nt][1], acc[mt][nt][2], acc[mt][nt][3],
                             a[mt][0], a[mt][1], a[mt][2], a[mt][3], b[nt][0], b[nt][1]);
        }
        __syncthreads();
    }
#pragma unroll
    for (int mt = 0; mt < 2; mt++)
#pragma unroll
        for (int nt = 0; nt < 2; nt++) {
            int mg = m0 + wm + mt * 16 + g;
            int ng = n0 + wn + nt * 8 + qd * 2;
            float bz0 = bias[ng], bz1 = bias[ng + 1];
            unsigned h0 = packbf(gelu_tanh(acc[mt][nt][0] + bz0), gelu_tanh(acc[mt][nt][1] + bz1));
            unsigned h1 = packbf(gelu_tanh(acc[mt][nt][2] + bz0), gelu_tanh(acc[mt][nt][3] + bz1));
            *(unsigned*)&g_hidh[mg * 512 + ng] = h0;
            *(unsigned*)&g_hidh[(mg + 8) * 512 + ng] = h1;
        }
}

// ---------------- GEMM2: hid[1024,512]@mow^T + bias, state update ----------------
__global__ __launch_bounds__(256) void k_gemm2(const float* __restrict__ bias) {
    __shared__ __align__(16) __nv_bfloat16 As[2][64 * AS_S];
    __shared__ __align__(16) __nv_bfloat16 Bs[2][64 * AS_S];
    int n0 = blockIdx.x * 64, m0 = blockIdx.y * 64, t = threadIdx.x;
    int w = t >> 5, lane = t & 31, qd = lane & 3, g = lane >> 2;
    int wm = (w >> 2) * 32, wn = (w & 3) * 16;
    int fm = t >> 2, fk = (t & 3) * 8;
    float acc[2][2][4];
#pragma unroll
    for (int mt = 0; mt < 2; mt++)
#pragma unroll
        for (int nt = 0; nt < 2; nt++)
#pragma unroll
            for (int u = 0; u < 4; u++) acc[mt][nt][u] = 0.f;

    const int NS = 16;
    *(uint4*)&As[0][fm * AS_S + fk] = *(const uint4*)&g_hidh[(m0 + fm) * 512 + fk];
    *(uint4*)&Bs[0][fm * AS_S + fk] = *(const uint4*)&g_mowh[(n0 + fm) * 512 + fk];
    __syncthreads();

    for (int st = 0; st < NS; st++) {
        int cur = st & 1;
        if (st + 1 < NS) {
            int nb = (st + 1) & 1, k0 = (st + 1) * 32;
            *(uint4*)&As[nb][fm * AS_S + fk] = *(const uint4*)&g_hidh[(m0 + fm) * 512 + k0 + fk];
            *(uint4*)&Bs[nb][fm * AS_S + fk] = *(const uint4*)&g_mowh[(n0 + fm) * 512 + k0 + fk];
        }
#pragma unroll
        for (int s = 0; s < 2; s++) {
            unsigned a[2][4], b[2][2];
#pragma unroll
            for (int mt = 0; mt < 2; mt++) {
                int row = wm + mt * 16 + g;
                a[mt][0] = *(const unsigned*)&As[cur][row * AS_S + s * 16 + 2 * qd];
                a[mt][1] = *(const unsigned*)&As[cur][(row + 8) * AS_S + s * 16 + 2 * qd];
                a[mt][2] = *(const unsigned*)&As[cur][row * AS_S + s * 16 + 2 * qd + 8];
                a[mt][3] = *(const unsigned*)&As[cur][(row + 8) * AS_S + s * 16 + 2 * qd + 8];
            }
#pragma unroll
            for (int nt = 0; nt < 2; nt++) {
                int bn = wn + nt * 8 + g;
                b[nt][0] = *(const unsigned*)&Bs[cur][bn * AS_S + s * 16 + 2 * qd];
                b[nt][1] = *(const unsigned*)&Bs[cur][bn * AS_S + s * 16 + 2 * qd + 8];
            }
#pragma unroll
            for (int mt = 0; mt < 2; mt++)
#pragma unroll
                for (int nt = 0; nt < 2; nt++)
                    mma_bf16(acc[mt][nt][0], acc[mt][nt][1], acc[mt][nt][2], acc[mt][nt][3],
                             a[mt][0], a[mt][1], a[mt][2], a[mt][3], b[nt][0], b[nt][1]);
        }
        __syncthreads();
    }
#pragma unroll
    for (int mt = 0; mt < 2; mt++)
#pragma unroll
        for (int nt = 0; nt < 2; nt++) {
#pragma unroll
            for (int rr = 0; rr < 2; rr++) {
                int mg = m0 + wm + mt * 16 + g + rr * 8;
#pragma unroll
                for (int jj = 0; jj < 2; jj++) {
                    int ng = n0 + wn + nt * 8 + qd * 2 + jj;
                    if (ng < 388) {
                        float v = acc[mt][nt][rr * 2 + jj] + bias[ng];
                        if (ng < 2)       g_pos[mg * 2 + ng] += v;
                        else if (ng == 2) g_occv[mg] += v;
                        else if (ng == 3) g_expd[mg] += v;
                        else              g_feats[mg * 384 + ng - 4] += v;
                    }
                }
            }
        }
}

// ---------------- pack output ----------------
__global__ void k_out(float* __restrict__ out) {
    int i = blockIdx.x * blockDim.x + threadIdx.x;
    if (i < NQ) {
        out[i * 4 + 0] = g_pos[i * 2 + 0];
        out[i * 4 + 1] = g_pos[i * 2 + 1];
        out[i * 4 + 2] = g_occv[i];
        out[i * 4 + 3] = g_expd[i];
    }
}

// ---------------- launch ----------------
extern "C" void kernel_launch(void* const* d_in, const int* in_sizes, int n_in,
                              void* d_out, int out_size) {
    const float* fg   = (const float*)d_in[0];
    const float* hg   = (const float*)d_in[1];
    const float* qf   = (const float*)d_in[2];
    const float* hq   = (const float*)d_in[3];
    const float* w1   = (const float*)d_in[4];
    const float* b1   = (const float*)d_in[5];
    const float* w2   = (const float*)d_in[6];
    const float* b2   = (const float*)d_in[7];
    const float* w3   = (const float*)d_in[8];
    const float* b3   = (const float*)d_in[9];
    const float* w4   = (const float*)d_in[10];
    const float* b4   = (const float*)d_in[11];
    const float* occw = (const float*)d_in[12];
    const float* occb = (const float*)d_in[13];
    const float* miw  = (const float*)d_in[14];
    const float* mib  = (const float*)d_in[15];
    const float* mow  = (const float*)d_in[16];
    const float* mob  = (const float*)d_in[17];
    float* out = (float*)d_out;

    const int smem_head = 18754 * 4;
    cudaFuncSetAttribute(k_head, cudaFuncAttributeMaxDynamicSharedMemorySize, smem_head);

    k_cv<<<dim3(64, 16), 256>>>(qf, fg, g_cv);
    k_fgavg<<<1024, 256>>>(fg, g_fgavg);
    k_prep<<<960, 256>>>(miw, mow);
    k_head<<<NQ, 256, smem_head>>>(g_cv, hq, qf, w1, b1, w2, b2, w3, b3, w4, b4, occw, occb);

    for (int it = 0; it < 4; it++) {
        k_corr<<<NQ, 256>>>(hg, fg);
        k_gemm1<<<dim3(8, 16), 256>>>(mib);
        k_gemm2<<<dim3(7, 16), 256>>>(mob);
    }
    k_out<<<4, 256>>>(out);
}